// round 11
// baseline (speedup 1.0000x reference)
#include <cuda_runtime.h>
#include <cuda_bf16.h>
#include <math.h>
#include <stdint.h>

// ---------------------------------------------------------------------------
// ResidualRoPETransformer: B=2,U=32,A=512,E=256,NH=8,HD=32, T=32768 tokens
// Round 11: GEMM re-tiled to 64x64 warp tiles (4 warps/CTA) to fix L1-bound
// LDSM:MMA ratio (ncu R10: tensor 39.7%, L1 50.7%).
// ---------------------------------------------------------------------------

#define T_TOK 32768
#define SEQ 512
#define HDIM 32

// ---- scratch (static device globals; no runtime allocation) ----
__device__ __nv_bfloat16 g_Wqkv[768 * 512];   // packed [hi(256)|lo(256)]
__device__ __nv_bfloat16 g_Wo[256 * 512];
__device__ __nv_bfloat16 g_W1[256 * 512];
__device__ __nv_bfloat16 g_W2[256 * 512];
__device__ __nv_bfloat16 g_zln[(size_t)T_TOK * 512];   // packed activations
__device__ __nv_bfloat16 g_att[(size_t)T_TOK * 512];
__device__ __nv_bfloat16 g_h1[(size_t)T_TOK * 512];
__device__ __nv_bfloat16 g_qs[(size_t)512 * 512 * 64];  // [bh][a][qh32|ql32] (scaled)
__device__ __nv_bfloat16 g_ks[(size_t)512 * 512 * 64];  // [bh][a][kh32|kl32]
__device__ __nv_bfloat16 g_vs[(size_t)512 * 512 * 64];  // [bh][a][vh32|vl32]
__device__ float2 g_rtbl[512 * 16];                     // (cos, sin) per (a, i)

// ===========================================================================
// PTX helpers (sm_80-level only: cp.async, ldmatrix, mma.sync)
// ===========================================================================
__device__ __forceinline__ uint32_t smem_u32(const void* p) {
    uint32_t a;
    asm("{ .reg .u64 t; cvta.to.shared.u64 t, %1; cvt.u32.u64 %0, t; }"
        : "=r"(a) : "l"(p));
    return a;
}
#define CP_ASYNC16(dst, src) \
    asm volatile("cp.async.cg.shared.global [%0], [%1], 16;" :: "r"(dst), "l"(src))
#define CP_COMMIT() asm volatile("cp.async.commit_group;" ::: "memory")
#define CP_WAIT(n)  asm volatile("cp.async.wait_group %0;" :: "n"(n) : "memory")

#define LDSM_X4(r0, r1, r2, r3, addr) \
    asm volatile("ldmatrix.sync.aligned.m8n8.x4.shared.b16 {%0,%1,%2,%3},[%4];" \
                 : "=r"(r0), "=r"(r1), "=r"(r2), "=r"(r3) : "r"(addr))
#define LDSM_X4_T(r0, r1, r2, r3, addr) \
    asm volatile("ldmatrix.sync.aligned.m8n8.x4.trans.shared.b16 {%0,%1,%2,%3},[%4];" \
                 : "=r"(r0), "=r"(r1), "=r"(r2), "=r"(r3) : "r"(addr))

#define MMA16816(d, a0, a1, a2, a3, b0, b1) \
    asm volatile("mma.sync.aligned.m16n8k16.row.col.f32.bf16.bf16.f32 " \
                 "{%0,%1,%2,%3},{%4,%5,%6,%7},{%8,%9},{%0,%1,%2,%3};" \
                 : "+f"((d)[0]), "+f"((d)[1]), "+f"((d)[2]), "+f"((d)[3]) \
                 : "r"(a0), "r"(a1), "r"(a2), "r"(a3), "r"(b0), "r"(b1))

__device__ __forceinline__ void split_bf16(float x, __nv_bfloat16& h, __nv_bfloat16& l) {
    h = __float2bfloat16(x);
    l = __float2bfloat16(x - __bfloat162float(h));
}
__device__ __forceinline__ uint32_t packbf(float a, float b) {
    __nv_bfloat162 t = __floats2bfloat162_rn(a, b);
    return *(uint32_t*)&t;
}
__device__ __forceinline__ void pack_split(float v0, float v1, uint32_t& hw, uint32_t& lw) {
    __nv_bfloat16 h0, l0, h1, l1;
    split_bf16(v0, h0, l0); split_bf16(v1, h1, l1);
    hw = packbf(__bfloat162float(h0), __bfloat162float(h1));
    lw = packbf(__bfloat162float(l0), __bfloat162float(l1));
}

// ===========================================================================
__device__ __forceinline__ float blockReduceSum256(float v, float* red) {
    int lane = threadIdx.x & 31, w = threadIdx.x >> 5;
#pragma unroll
    for (int o = 16; o; o >>= 1) v += __shfl_xor_sync(0xffffffffu, v, o);
    __syncthreads();
    if (lane == 0) red[w] = v;
    __syncthreads();
    float s = 0.f;
#pragma unroll
    for (int i = 0; i < 8; i++) s += red[i];
    return s;
}

// ---- rope table ----
__global__ void rope_tbl_kernel(float2* tbl) {
    int idx = blockIdx.x * 256 + threadIdx.x;    // 8192
    int a = idx >> 4, i = idx & 15;
    float freq = exp2f(-(float)i * 0.8304820237218406f);
    float s, c;
    sincosf((float)a * freq, &s, &c);
    tbl[idx] = make_float2(c, s);
}

// ---- all weight norms in one launch (grid 1536) ----
__global__ void wnorm_all(const float* __restrict__ pv, const float* __restrict__ pg,
                          const float* __restrict__ fv, const float* __restrict__ fg,
                          const float* __restrict__ w1v, const float* __restrict__ w1g,
                          const float* __restrict__ w2v, const float* __restrict__ w2g,
                          __nv_bfloat16* __restrict__ Wqkv, __nv_bfloat16* __restrict__ Wo,
                          __nv_bfloat16* __restrict__ W1, __nv_bfloat16* __restrict__ W2) {
    __shared__ float red[8];
    int b = blockIdx.x;
    const float *v, *g; __nv_bfloat16* W; int row;
    if (b < 768)       { v = pv;  g = pg;  W = Wqkv; row = b; }
    else if (b < 1024) { v = fv;  g = fg;  W = Wo;   row = b - 768; }
    else if (b < 1280) { v = w1v; g = w1g; W = W1;   row = b - 1024; }
    else               { v = w2v; g = w2g; W = W2;   row = b - 1280; }
    size_t base = (size_t)row * 256;
    float x = v[base + threadIdx.x];
    float ss = blockReduceSum256(x * x, red);
    float w = x * g[row] * rsqrtf(ss);
    __nv_bfloat16 h, l;
    split_bf16(w, h, l);
    size_t ob = (size_t)row * 512 + threadIdx.x;
    W[ob] = h;
    W[ob + 256] = l;
}

// ---- layernorm -> packed hi/lo bf16 [token][512] ----
__global__ void ln_kernel(const float* __restrict__ x, const float* __restrict__ g,
                          const float* __restrict__ b, __nv_bfloat16* __restrict__ y) {
    __shared__ float red[8];
    size_t base = (size_t)blockIdx.x * 256;
    float v = x[base + threadIdx.x];
    float mean = blockReduceSum256(v, red) * (1.f / 256.f);
    float d = v - mean;
    float var = blockReduceSum256(d * d, red) * (1.f / 256.f);
    float o = d * rsqrtf(var + 1e-5f) * g[threadIdx.x] + b[threadIdx.x];
    __nv_bfloat16 h, l;
    split_bf16(o, h, l);
    size_t ob = (size_t)blockIdx.x * 512 + threadIdx.x;
    y[ob] = h;
    y[ob + 256] = l;
}

// ===========================================================================
// mma.sync bf16 GEMM (split-3 packed K'=768). 4 warps, warp tile 64x64.
// BM=128 BN=128 BK=64, 128 threads, warp grid 2(M)x2(N).
// mode: 1 gelu->packed bf16, 2 bias+residual fp32, 3 qkv: bias+rope -> split Q/K/V
// ===========================================================================
#define ROWP 72
#define STG_BYTES (2 * 128 * ROWP * 2)   // A+B per stage = 36864
#define GEMM_SMEM (2 * STG_BYTES)
#define SCQ 0.17677669529663687f

__global__ __launch_bounds__(128, 2) void gemm_mma(
    const __nv_bfloat16* __restrict__ Ap, const __nv_bfloat16* __restrict__ Wp,
    const float* __restrict__ bias, const float* __restrict__ res,
    float* __restrict__ Cf, __nv_bfloat16* __restrict__ Cp,
    const float2* __restrict__ rtbl,
    __nv_bfloat16* __restrict__ Oq, __nv_bfloat16* __restrict__ Ok,
    __nv_bfloat16* __restrict__ Ov,
    int N, int mode)
{
    extern __shared__ char dsm[];
    int tid = threadIdx.x, wid = tid >> 5, lane = tid & 31;
    int bm = blockIdx.y * 128, bn = blockIdx.x * 128;
    int wm = (wid & 1) * 64, wn = (wid >> 1) * 64;

    uint32_t sbase = smem_u32(dsm);
    int ldr = tid >> 3;          // 0..15
    int ldc = (tid & 7) * 8;

    float acc[4][8][4];
#pragma unroll
    for (int mi = 0; mi < 4; mi++)
#pragma unroll
        for (int ni = 0; ni < 8; ni++)
#pragma unroll
            for (int e = 0; e < 4; e++) acc[mi][ni][e] = 0.f;

    auto issue_loads = [&](int c) {
        int seg = c >> 2;
        int kg = (c & 3) * 64;
        int aoff = (seg == 2) ? 256 + kg : kg;
        int boff = (seg == 1) ? 256 + kg : kg;
        uint32_t st = sbase + (c & 1) * STG_BYTES;
#pragma unroll
        for (int i = 0; i < 8; i++) {
            int r = ldr + i * 16;
            CP_ASYNC16(st + r * 144 + ldc * 2,
                       Ap + (size_t)(bm + r) * 512 + aoff + ldc);
        }
        uint32_t stB = st + 128 * 144;
#pragma unroll
        for (int i = 0; i < 8; i++) {
            int r = ldr + i * 16;
            CP_ASYNC16(stB + r * 144 + ldc * 2,
                       Wp + (size_t)(bn + r) * 512 + boff + ldc);
        }
        CP_COMMIT();
    };

    issue_loads(0);

    int lg8 = ((lane >> 4) << 3) + (lane & 7);
    int koff = ((lane >> 3) & 1) * 8;

    for (int c = 0; c < 12; c++) {
        if (c + 1 < 12) { issue_loads(c + 1); CP_WAIT(1); } else { CP_WAIT(0); }
        __syncthreads();

        uint32_t stA = sbase + (c & 1) * STG_BYTES;
        uint32_t stB = stA + 128 * 144;
#pragma unroll
        for (int kk = 0; kk < 4; kk++) {
            uint32_t a[4][4], b[4][4];
#pragma unroll
            for (int mi = 0; mi < 4; mi++) {
                uint32_t ad = stA + (wm + mi * 16 + (lane & 15)) * 144
                            + (kk * 16 + (lane >> 4) * 8) * 2;
                LDSM_X4(a[mi][0], a[mi][1], a[mi][2], a[mi][3], ad);
            }
#pragma unroll
            for (int ng = 0; ng < 4; ng++) {
                int nrow = wn + ng * 16 + lg8;
                uint32_t bd = stB + nrow * 144 + (kk * 16 + koff) * 2;
                LDSM_X4(b[ng][0], b[ng][1], b[ng][2], b[ng][3], bd);
            }
#pragma unroll
            for (int mi = 0; mi < 4; mi++) {
#pragma unroll
                for (int ng = 0; ng < 4; ng++) {
                    MMA16816(acc[mi][ng * 2 + 0], a[mi][0], a[mi][1], a[mi][2], a[mi][3],
                             b[ng][0], b[ng][1]);
                    MMA16816(acc[mi][ng * 2 + 1], a[mi][0], a[mi][1], a[mi][2], a[mi][3],
                             b[ng][2], b[ng][3]);
                }
            }
        }
        __syncthreads();
    }

    int cg = (lane & 3) * 2;
    int rg = lane >> 2;
#pragma unroll
    for (int ni = 0; ni < 8; ni++) {
        int c0 = bn + wn + ni * 8 + cg;
        float2 b2 = *(const float2*)(bias + c0);
#pragma unroll
        for (int mi = 0; mi < 4; mi++) {
            int r0 = bm + wm + mi * 16 + rg;
#pragma unroll
            for (int h = 0; h < 2; h++) {
                int r = r0 + h * 8;
                float v0 = acc[mi][ni][h * 2 + 0] + b2.x;
                float v1 = acc[mi][ni][h * 2 + 1] + b2.y;
                if (mode == 1) {
                    v0 = 0.5f * v0 * (1.f + erff(v0 * 0.7071067811865476f));
                    v1 = 0.5f * v1 * (1.f + erff(v1 * 0.7071067811865476f));
                    uint32_t hw, lw;
                    pack_split(v0, v1, hw, lw);
                    *(uint32_t*)(Cp + (size_t)r * 512 + c0) = hw;
                    *(uint32_t*)(Cp + (size_t)r * 512 + 256 + c0) = lw;
                } else if (mode == 2) {
                    float2 rr = *(const float2*)(res + (size_t)r * N + c0);
                    *(float2*)(Cf + (size_t)r * N + c0) =
                        make_float2(v0 + rr.x, v1 + rr.y);
                } else {
                    int hh = c0 / 96;
                    int rem = c0 - hh * 96;
                    int type = rem >> 5;        // 0=q 1=k 2=v
                    int i2 = rem & 31;
                    int a = r & 511;
                    int bh = ((r >> 9) << 3) + hh;
                    size_t ob = ((size_t)bh * 512 + a) * 64 + i2;
                    uint32_t hw, lw;
                    if (type == 2) {
                        pack_split(v0, v1, hw, lw);
                        *(uint32_t*)(Ov + ob) = hw;
                        *(uint32_t*)(Ov + ob + 32) = lw;
                    } else {
                        float2 cs = rtbl[a * 16 + (i2 >> 1)];
                        float q0 = v0 * cs.x - v1 * cs.y;
                        float q1 = v1 * cs.x + v0 * cs.y;
                        if (type == 0) { q0 *= SCQ; q1 *= SCQ; }
                        pack_split(q0, q1, hw, lw);
                        __nv_bfloat16* O = (type == 0) ? Oq : Ok;
                        *(uint32_t*)(O + ob) = hw;
                        *(uint32_t*)(O + ob + 32) = lw;
                    }
                }
            }
        }
    }
}

// ---------------------------------------------------------------------------
// Flash-style HMMA attention (unchanged from R9/R10, validated).
// ---------------------------------------------------------------------------
#define ATT2_SMEM (3 * 73728)

__global__ __launch_bounds__(256) void attn_mma(
    const __nv_bfloat16* __restrict__ Qs, const __nv_bfloat16* __restrict__ Ks,
    const __nv_bfloat16* __restrict__ Vs, __nv_bfloat16* __restrict__ Op)
{
    extern __shared__ char sm[];
    uint32_t sQ = smem_u32(sm);
    uint32_t sK = sQ + 73728;
    uint32_t sV = sQ + 147456;
    int bh = blockIdx.x, tid = threadIdx.x, wid = tid >> 5, lane = tid & 31;

    const __nv_bfloat16* qg = Qs + (size_t)bh * 512 * 64;
    const __nv_bfloat16* kg = Ks + (size_t)bh * 512 * 64;
    const __nv_bfloat16* vg = Vs + (size_t)bh * 512 * 64;
    for (int idx = tid; idx < 4096; idx += 256) {
        int r = idx >> 3, c = idx & 7;
        CP_ASYNC16(sQ + r * 144 + c * 16, qg + r * 64 + c * 8);
        CP_ASYNC16(sK + r * 144 + c * 16, kg + r * 64 + c * 8);
        CP_ASYNC16(sV + r * 144 + c * 16, vg + r * 64 + c * 8);
    }
    CP_COMMIT(); CP_WAIT(0);
    __syncthreads();

    int wm = wid * 64;
    float acc[4][4][4];
    float mst[4][2], lst[4][2];
#pragma unroll
    for (int mi = 0; mi < 4; mi++) {
        mst[mi][0] = -1e30f; mst[mi][1] = -1e30f;
        lst[mi][0] = 0.f;    lst[mi][1] = 0.f;
#pragma unroll
        for (int jv = 0; jv < 4; jv++)
#pragma unroll
            for (int e = 0; e < 4; e++) acc[mi][jv][e] = 0.f;
    }

    int lg8 = ((lane >> 4) << 3) + (lane & 7);
    int lk8 = ((lane >> 3) & 1) * 16;
    int vrow = ((lane >> 3) & 1) * 8 + (lane & 7);
    int vcb = (lane >> 4) * 16;

    for (int kt = 0; kt < 16; kt++) {
        int kvb = kt * 32;

        uint32_t bK[4][4][2];
#pragma unroll
        for (int g16 = 0; g16 < 2; g16++)
#pragma unroll
            for (int kq = 0; kq < 4; kq++) {
                uint32_t ad = sK + (kvb + g16 * 16 + lg8) * 144 + kq * 32 + lk8;
                uint32_t r0, r1, r2, r3;
                LDSM_X4(r0, r1, r2, r3, ad);
                bK[g16 * 2][kq][0] = r0;     bK[g16 * 2][kq][1] = r1;
                bK[g16 * 2 + 1][kq][0] = r2; bK[g16 * 2 + 1][kq][1] = r3;
            }
        uint32_t bVh[4][2][2], bVl[4][2][2];
#pragma unroll
        for (int ks = 0; ks < 2; ks++) {
            uint32_t ad = sV + (kvb + ks * 16 + vrow) * 144 + vcb;
            uint32_t r0, r1, r2, r3;
            LDSM_X4_T(r0, r1, r2, r3, ad);
            bVh[0][ks][0] = r0; bVh[0][ks][1] = r1;
            bVh[1][ks][0] = r2; bVh[1][ks][1] = r3;
            LDSM_X4_T(r0, r1, r2, r3, ad + 32);
            bVh[2][ks][0] = r0; bVh[2][ks][1] = r1;
            bVh[3][ks][0] = r2; bVh[3][ks][1] = r3;
            LDSM_X4_T(r0, r1, r2, r3, ad + 64);
            bVl[0][ks][0] = r0; bVl[0][ks][1] = r1;
            bVl[1][ks][0] = r2; bVl[1][ks][1] = r3;
            LDSM_X4_T(r0, r1, r2, r3, ad + 96);
            bVl[2][ks][0] = r0; bVl[2][ks][1] = r1;
            bVl[3][ks][0] = r2; bVl[3][ks][1] = r3;
        }

#pragma unroll
        for (int mi = 0; mi < 4; mi++) {
            uint32_t aQ[4][4];
#pragma unroll
            for (int kq = 0; kq < 4; kq++) {
                uint32_t ad = sQ + (wm + mi * 16 + (lane & 15)) * 144
                            + kq * 32 + (lane >> 4) * 16;
                LDSM_X4(aQ[kq][0], aQ[kq][1], aQ[kq][2], aQ[kq][3], ad);
            }
            float s[4][4];
#pragma unroll
            for (int j = 0; j < 4; j++) {
#pragma unroll
                for (int e = 0; e < 4; e++) s[j][e] = 0.f;
                MMA16816(s[j], aQ[0][0], aQ[0][1], aQ[0][2], aQ[0][3], bK[j][0][0], bK[j][0][1]);
                MMA16816(s[j], aQ[1][0], aQ[1][1], aQ[1][2], aQ[1][3], bK[j][1][0], bK[j][1][1]);
                MMA16816(s[j], aQ[0][0], aQ[0][1], aQ[0][2], aQ[0][3], bK[j][2][0], bK[j][2][1]);
                MMA16816(s[j], aQ[1][0], aQ[1][1], aQ[1][2], aQ[1][3], bK[j][3][0], bK[j][3][1]);
                MMA16816(s[j], aQ[2][0], aQ[2][1], aQ[2][2], aQ[2][3], bK[j][0][0], bK[j][0][1]);
                MMA16816(s[j], aQ[3][0], aQ[3][1], aQ[3][2], aQ[3][3], bK[j][1][0], bK[j][1][1]);
            }
            float mx0 = -1e30f, mx1 = -1e30f;
#pragma unroll
            for (int j = 0; j < 4; j++) {
                mx0 = fmaxf(mx0, fmaxf(s[j][0], s[j][1]));
                mx1 = fmaxf(mx1, fmaxf(s[j][2], s[j][3]));
            }
            mx0 = fmaxf(mx0, __shfl_xor_sync(0xffffffffu, mx0, 1));
            mx0 = fmaxf(mx0, __shfl_xor_sync(0xffffffffu, mx0, 2));
            mx1 = fmaxf(mx1, __shfl_xor_sync(0xffffffffu, mx1, 1));
            mx1 = fmaxf(mx1, __shfl_xor_sync(0xffffffffu, mx1, 2));
            float mn0 = fmaxf(mst[mi][0], mx0);
            float mn1 = fmaxf(mst[mi][1], mx1);
            float al0 = __expf(mst[mi][0] - mn0);
            float al1 = __expf(mst[mi][1] - mn1);
            mst[mi][0] = mn0; mst[mi][1] = mn1;
            float sm0 = 0.f, sm1 = 0.f;
#pragma unroll
            for (int j = 0; j < 4; j++) {
                s[j][0] = __expf(s[j][0] - mn0); sm0 += s[j][0];
                s[j][1] = __expf(s[j][1] - mn0); sm0 += s[j][1];
                s[j][2] = __expf(s[j][2] - mn1); sm1 += s[j][2];
                s[j][3] = __expf(s[j][3] - mn1); sm1 += s[j][3];
            }
            sm0 += __shfl_xor_sync(0xffffffffu, sm0, 1);
            sm0 += __shfl_xor_sync(0xffffffffu, sm0, 2);
            sm1 += __shfl_xor_sync(0xffffffffu, sm1, 1);
            sm1 += __shfl_xor_sync(0xffffffffu, sm1, 2);
            lst[mi][0] = lst[mi][0] * al0 + sm0;
            lst[mi][1] = lst[mi][1] * al1 + sm1;
#pragma unroll
            for (int jv = 0; jv < 4; jv++) {
                acc[mi][jv][0] *= al0; acc[mi][jv][1] *= al0;
                acc[mi][jv][2] *= al1; acc[mi][jv][3] *= al1;
            }
            uint32_t aPh[2][4], aPl[2][4];
#pragma unroll
            for (int ks = 0; ks < 2; ks++) {
                int j0 = 2 * ks, j1 = 2 * ks + 1;
                aPh[ks][0] = packbf(s[j0][0], s[j0][1]);
                aPh[ks][1] = packbf(s[j0][2], s[j0][3]);
                aPh[ks][2] = packbf(s[j1][0], s[j1][1]);
                aPh[ks][3] = packbf(s[j1][2], s[j1][3]);
                __nv_bfloat162 h0 = *(__nv_bfloat162*)&aPh[ks][0];
                __nv_bfloat162 h1 = *(__nv_bfloat162*)&aPh[ks][1];
                __nv_bfloat162 h2 = *(__nv_bfloat162*)&aPh[ks][2];
                __nv_bfloat162 h3 = *(__nv_bfloat162*)&aPh[ks][3];
                aPl[ks][0] = packbf(s[j0][0] - __bfloat162float(h0.x),
                                    s[j0][1] - __bfloat162float(h0.y));
                aPl[ks][1] = packbf(s[j0][2] - __bfloat162float(h1.x),
                                    s[j0][3] - __bfloat162float(h1.y));
                aPl[ks][2] = packbf(s[j1][0] - __bfloat162float(h2.x),
                                    s[j1][1] - __bfloat162float(h2.y));
                aPl[ks][3] = packbf(s[j1][2] - __bfloat162float(h3.x),
                                    s[j1][3] - __bfloat162float(h3.y));
            }
#pragma unroll
            for (int jv = 0; jv < 4; jv++) {
                MMA16816(acc[mi][jv], aPh[0][0], aPh[0][1], aPh[0][2], aPh[0][3],
                         bVh[jv][0][0], bVh[jv][0][1]);
                MMA16816(acc[mi][jv], aPh[1][0], aPh[1][1], aPh[1][2], aPh[1][3],
                         bVh[jv][1][0], bVh[jv][1][1]);
                MMA16816(acc[mi][jv], aPh[0][0], aPh[0][1], aPh[0][2], aPh[0][3],
                         bVl[jv][0][0], bVl[jv][0][1]);
                MMA16816(acc[mi][jv], aPh[1][0], aPh[1][1], aPh[1][2], aPh[1][3],
                         bVl[jv][1][0], bVl[jv][1][1]);
                MMA16816(acc[mi][jv], aPl[0][0], aPl[0][1], aPl[0][2], aPl[0][3],
                         bVh[jv][0][0], bVh[jv][0][1]);
                MMA16816(acc[mi][jv], aPl[1][0], aPl[1][1], aPl[1][2], aPl[1][3],
                         bVh[jv][1][0], bVh[jv][1][1]);
            }
        }
    }

    int tb = (bh >> 3) * 512;
    int cb = (bh & 7) * 32;
#pragma unroll
    for (int mi = 0; mi < 4; mi++) {
        float i0 = 1.f / lst[mi][0];
        float i1 = 1.f / lst[mi][1];
        int r0 = wm + mi * 16 + (lane >> 2);
#pragma unroll
        for (int jv = 0; jv < 4; jv++) {
            int col = cb + jv * 8 + 2 * (lane & 3);
            uint32_t hw, lw;
            pack_split(acc[mi][jv][0] * i0, acc[mi][jv][1] * i0, hw, lw);
            size_t ob = (size_t)(tb + r0) * 512 + col;
            *(uint32_t*)(Op + ob) = hw;
            *(uint32_t*)(Op + ob + 256) = lw;
            pack_split(acc[mi][jv][2] * i1, acc[mi][jv][3] * i1, hw, lw);
            ob = (size_t)(tb + r0 + 8) * 512 + col;
            *(uint32_t*)(Op + ob) = hw;
            *(uint32_t*)(Op + ob + 256) = lw;
        }
    }
}

// ---------------------------------------------------------------------------
extern "C" void kernel_launch(void* const* d_in, const int* in_sizes, int n_in,
                              void* d_out, int out_size) {
    const float* z      = (const float*)d_in[0];
    const float* ln1_g  = (const float*)d_in[1];
    const float* ln1_b  = (const float*)d_in[2];
    const float* proj_v = (const float*)d_in[3];
    const float* proj_g = (const float*)d_in[4];
    const float* proj_b = (const float*)d_in[5];
    const float* ff_v   = (const float*)d_in[6];
    const float* ff_g   = (const float*)d_in[7];
    const float* ff_b   = (const float*)d_in[8];
    const float* ln2_g  = (const float*)d_in[9];
    const float* ln2_b  = (const float*)d_in[10];
    const float* w1_v   = (const float*)d_in[11];
    const float* w1_g   = (const float*)d_in[12];
    const float* w1_b   = (const float*)d_in[13];
    const float* w2_v   = (const float*)d_in[14];
    const float* w2_g   = (const float*)d_in[15];
    const float* w2_b   = (const float*)d_in[16];
    float* out = (float*)d_out;

    void *pWqkv, *pWo, *pW1, *pW2, *pzln, *pqs, *pks, *pvs, *patt, *ph1, *ptbl;
    cudaGetSymbolAddress(&pWqkv, g_Wqkv);
    cudaGetSymbolAddress(&pWo, g_Wo);
    cudaGetSymbolAddress(&pW1, g_W1);
    cudaGetSymbolAddress(&pW2, g_W2);
    cudaGetSymbolAddress(&pzln, g_zln);
    cudaGetSymbolAddress(&pqs, g_qs);
    cudaGetSymbolAddress(&pks, g_ks);
    cudaGetSymbolAddress(&pvs, g_vs);
    cudaGetSymbolAddress(&patt, g_att);
    cudaGetSymbolAddress(&ph1, g_h1);
    cudaGetSymbolAddress(&ptbl, g_rtbl);

    cudaFuncSetAttribute(gemm_mma, cudaFuncAttributeMaxDynamicSharedMemorySize, GEMM_SMEM);
    cudaFuncSetAttribute(attn_mma, cudaFuncAttributeMaxDynamicSharedMemorySize, ATT2_SMEM);

    // 0) rope table
    rope_tbl_kernel<<<32, 256>>>((float2*)ptbl);

    // 1) all weight norms
    wnorm_all<<<1536, 256>>>(proj_v, proj_g, ff_v, ff_g, w1_v, w1_g, w2_v, w2_g,
                             (__nv_bfloat16*)pWqkv, (__nv_bfloat16*)pWo,
                             (__nv_bfloat16*)pW1, (__nv_bfloat16*)pW2);

    // 2) LN1 -> packed bf16
    ln_kernel<<<T_TOK, 256>>>(z, ln1_g, ln1_b, (__nv_bfloat16*)pzln);

    // 3) QKV projection with fused bias+RoPE+split scatter
    gemm_mma<<<dim3(6, 256), 128, GEMM_SMEM>>>(
        (const __nv_bfloat16*)pzln, (const __nv_bfloat16*)pWqkv,
        proj_b, nullptr, nullptr, nullptr,
        (const float2*)ptbl, (__nv_bfloat16*)pqs, (__nv_bfloat16*)pks,
        (__nv_bfloat16*)pvs, 768, 3);

    // 4) attention (flash HMMA) -> packed bf16
    attn_mma<<<512, 256, ATT2_SMEM>>>(
        (const __nv_bfloat16*)pqs, (const __nv_bfloat16*)pks,
        (const __nv_bfloat16*)pvs, (__nv_bfloat16*)patt);

    // 5) Wo + residual z -> out (fp32)
    gemm_mma<<<dim3(2, 256), 128, GEMM_SMEM>>>(
        (const __nv_bfloat16*)patt, (const __nv_bfloat16*)pWo,
        ff_b, z, out, nullptr, nullptr, nullptr, nullptr, nullptr, 256, 2);

    // 6) LN2 -> packed bf16
    ln_kernel<<<T_TOK, 256>>>(out, ln2_g, ln2_b, (__nv_bfloat16*)pzln);

    // 7) W1 + GELU -> packed bf16
    gemm_mma<<<dim3(2, 256), 128, GEMM_SMEM>>>(
        (const __nv_bfloat16*)pzln, (const __nv_bfloat16*)pW1,
        w1_b, nullptr, nullptr, (__nv_bfloat16*)ph1,
        nullptr, nullptr, nullptr, nullptr, 256, 1);

    // 8) W2 + residual -> out
    gemm_mma<<<dim3(2, 256), 128, GEMM_SMEM>>>(
        (const __nv_bfloat16*)ph1, (const __nv_bfloat16*)pW2,
        w2_b, out, out, nullptr, nullptr, nullptr, nullptr, nullptr, 256, 2);
}

// round 12
// speedup vs baseline: 1.0757x; 1.0757x over previous
#include <cuda_runtime.h>
#include <cuda_bf16.h>
#include <math.h>
#include <stdint.h>

// ---------------------------------------------------------------------------
// ResidualRoPETransformer: B=2,U=32,A=512,E=256,NH=8,HD=32, T=32768 tokens
// Round 12: revert GEMM to R10 tiling (R11 reg-blowup regressed); add fused
// MLP kernel (W1+GELU+W2+residual, h1 kept in smem, BN=256 wide CTA).
// ---------------------------------------------------------------------------

#define T_TOK 32768
#define SEQ 512
#define HDIM 32

// ---- scratch (static device globals; no runtime allocation) ----
__device__ __nv_bfloat16 g_Wqkv[768 * 512];   // packed [hi(256)|lo(256)]
__device__ __nv_bfloat16 g_Wo[256 * 512];
__device__ __nv_bfloat16 g_W1[256 * 512];
__device__ __nv_bfloat16 g_W2[256 * 512];
__device__ __nv_bfloat16 g_zln[(size_t)T_TOK * 512];   // packed activations
__device__ __nv_bfloat16 g_att[(size_t)T_TOK * 512];
__device__ __nv_bfloat16 g_qs[(size_t)512 * 512 * 64];  // [bh][a][qh32|ql32] (scaled)
__device__ __nv_bfloat16 g_ks[(size_t)512 * 512 * 64];  // [bh][a][kh32|kl32]
__device__ __nv_bfloat16 g_vs[(size_t)512 * 512 * 64];  // [bh][a][vh32|vl32]
__device__ float2 g_rtbl[512 * 16];                     // (cos, sin) per (a, i)

// ===========================================================================
// PTX helpers (sm_80-level only: cp.async, ldmatrix, mma.sync)
// ===========================================================================
__device__ __forceinline__ uint32_t smem_u32(const void* p) {
    uint32_t a;
    asm("{ .reg .u64 t; cvta.to.shared.u64 t, %1; cvt.u32.u64 %0, t; }"
        : "=r"(a) : "l"(p));
    return a;
}
#define CP_ASYNC16(dst, src) \
    asm volatile("cp.async.cg.shared.global [%0], [%1], 16;" :: "r"(dst), "l"(src))
#define CP_COMMIT() asm volatile("cp.async.commit_group;" ::: "memory")
#define CP_WAIT(n)  asm volatile("cp.async.wait_group %0;" :: "n"(n) : "memory")

#define LDSM_X4(r0, r1, r2, r3, addr) \
    asm volatile("ldmatrix.sync.aligned.m8n8.x4.shared.b16 {%0,%1,%2,%3},[%4];" \
                 : "=r"(r0), "=r"(r1), "=r"(r2), "=r"(r3) : "r"(addr))
#define LDSM_X4_T(r0, r1, r2, r3, addr) \
    asm volatile("ldmatrix.sync.aligned.m8n8.x4.trans.shared.b16 {%0,%1,%2,%3},[%4];" \
                 : "=r"(r0), "=r"(r1), "=r"(r2), "=r"(r3) : "r"(addr))

#define MMA16816(d, a0, a1, a2, a3, b0, b1) \
    asm volatile("mma.sync.aligned.m16n8k16.row.col.f32.bf16.bf16.f32 " \
                 "{%0,%1,%2,%3},{%4,%5,%6,%7},{%8,%9},{%0,%1,%2,%3};" \
                 : "+f"((d)[0]), "+f"((d)[1]), "+f"((d)[2]), "+f"((d)[3]) \
                 : "r"(a0), "r"(a1), "r"(a2), "r"(a3), "r"(b0), "r"(b1))

__device__ __forceinline__ void split_bf16(float x, __nv_bfloat16& h, __nv_bfloat16& l) {
    h = __float2bfloat16(x);
    l = __float2bfloat16(x - __bfloat162float(h));
}
__device__ __forceinline__ uint32_t packbf(float a, float b) {
    __nv_bfloat162 t = __floats2bfloat162_rn(a, b);
    return *(uint32_t*)&t;
}
__device__ __forceinline__ void pack_split(float v0, float v1, uint32_t& hw, uint32_t& lw) {
    __nv_bfloat16 h0, l0, h1, l1;
    split_bf16(v0, h0, l0); split_bf16(v1, h1, l1);
    hw = packbf(__bfloat162float(h0), __bfloat162float(h1));
    lw = packbf(__bfloat162float(l0), __bfloat162float(l1));
}

// ===========================================================================
__device__ __forceinline__ float blockReduceSum256(float v, float* red) {
    int lane = threadIdx.x & 31, w = threadIdx.x >> 5;
#pragma unroll
    for (int o = 16; o; o >>= 1) v += __shfl_xor_sync(0xffffffffu, v, o);
    __syncthreads();
    if (lane == 0) red[w] = v;
    __syncthreads();
    float s = 0.f;
#pragma unroll
    for (int i = 0; i < 8; i++) s += red[i];
    return s;
}

// ---- rope table ----
__global__ void rope_tbl_kernel(float2* tbl) {
    int idx = blockIdx.x * 256 + threadIdx.x;    // 8192
    int a = idx >> 4, i = idx & 15;
    float freq = exp2f(-(float)i * 0.8304820237218406f);
    float s, c;
    sincosf((float)a * freq, &s, &c);
    tbl[idx] = make_float2(c, s);
}

// ---- all weight norms in one launch (grid 1536) ----
__global__ void wnorm_all(const float* __restrict__ pv, const float* __restrict__ pg,
                          const float* __restrict__ fv, const float* __restrict__ fg,
                          const float* __restrict__ w1v, const float* __restrict__ w1g,
                          const float* __restrict__ w2v, const float* __restrict__ w2g,
                          __nv_bfloat16* __restrict__ Wqkv, __nv_bfloat16* __restrict__ Wo,
                          __nv_bfloat16* __restrict__ W1, __nv_bfloat16* __restrict__ W2) {
    __shared__ float red[8];
    int b = blockIdx.x;
    const float *v, *g; __nv_bfloat16* W; int row;
    if (b < 768)       { v = pv;  g = pg;  W = Wqkv; row = b; }
    else if (b < 1024) { v = fv;  g = fg;  W = Wo;   row = b - 768; }
    else if (b < 1280) { v = w1v; g = w1g; W = W1;   row = b - 1024; }
    else               { v = w2v; g = w2g; W = W2;   row = b - 1280; }
    size_t base = (size_t)row * 256;
    float x = v[base + threadIdx.x];
    float ss = blockReduceSum256(x * x, red);
    float w = x * g[row] * rsqrtf(ss);
    __nv_bfloat16 h, l;
    split_bf16(w, h, l);
    size_t ob = (size_t)row * 512 + threadIdx.x;
    W[ob] = h;
    W[ob + 256] = l;
}

// ---- layernorm -> packed hi/lo bf16 [token][512] ----
__global__ void ln_kernel(const float* __restrict__ x, const float* __restrict__ g,
                          const float* __restrict__ b, __nv_bfloat16* __restrict__ y) {
    __shared__ float red[8];
    size_t base = (size_t)blockIdx.x * 256;
    float v = x[base + threadIdx.x];
    float mean = blockReduceSum256(v, red) * (1.f / 256.f);
    float d = v - mean;
    float var = blockReduceSum256(d * d, red) * (1.f / 256.f);
    float o = d * rsqrtf(var + 1e-5f) * g[threadIdx.x] + b[threadIdx.x];
    __nv_bfloat16 h, l;
    split_bf16(o, h, l);
    size_t ob = (size_t)blockIdx.x * 512 + threadIdx.x;
    y[ob] = h;
    y[ob + 256] = l;
}

// ===========================================================================
// mma.sync bf16 GEMM (split-3 packed K'=768). R10 config: 8 warps, 2(M)x4(N),
// warp tile 64x32. mode: 2 bias+residual fp32, 3 qkv: bias+rope -> split Q/K/V
// ===========================================================================
#define ROWP 72
#define STG_BYTES (2 * 128 * ROWP * 2)   // A+B per stage = 36864
#define GEMM_SMEM (2 * STG_BYTES)
#define SCQ 0.17677669529663687f

__global__ __launch_bounds__(256) void gemm_mma(
    const __nv_bfloat16* __restrict__ Ap, const __nv_bfloat16* __restrict__ Wp,
    const float* __restrict__ bias, const float* __restrict__ res,
    float* __restrict__ Cf,
    const float2* __restrict__ rtbl,
    __nv_bfloat16* __restrict__ Oq, __nv_bfloat16* __restrict__ Ok,
    __nv_bfloat16* __restrict__ Ov,
    int N, int mode)
{
    extern __shared__ char dsm[];
    int tid = threadIdx.x, wid = tid >> 5, lane = tid & 31;
    int bm = blockIdx.y * 128, bn = blockIdx.x * 128;
    int wm = (wid & 1) * 64, wn = (wid >> 1) * 32;

    uint32_t sbase = smem_u32(dsm);
    int ldr = tid >> 3;
    int ldc = (tid & 7) * 8;

    float acc[4][4][4];
#pragma unroll
    for (int mi = 0; mi < 4; mi++)
#pragma unroll
        for (int ni = 0; ni < 4; ni++)
#pragma unroll
            for (int e = 0; e < 4; e++) acc[mi][ni][e] = 0.f;

    auto issue_loads = [&](int c) {
        int seg = c >> 2;
        int kg = (c & 3) * 64;
        int aoff = (seg == 2) ? 256 + kg : kg;
        int boff = (seg == 1) ? 256 + kg : kg;
        uint32_t st = sbase + (c & 1) * STG_BYTES;
#pragma unroll
        for (int i = 0; i < 4; i++) {
            int r = ldr + i * 32;
            CP_ASYNC16(st + r * 144 + ldc * 2,
                       Ap + (size_t)(bm + r) * 512 + aoff + ldc);
        }
        uint32_t stB = st + 128 * 144;
#pragma unroll
        for (int i = 0; i < 4; i++) {
            int r = ldr + i * 32;
            CP_ASYNC16(stB + r * 144 + ldc * 2,
                       Wp + (size_t)(bn + r) * 512 + boff + ldc);
        }
        CP_COMMIT();
    };

    issue_loads(0);

    for (int c = 0; c < 12; c++) {
        if (c + 1 < 12) { issue_loads(c + 1); CP_WAIT(1); } else { CP_WAIT(0); }
        __syncthreads();

        uint32_t stA = sbase + (c & 1) * STG_BYTES;
        uint32_t stB = stA + 128 * 144;
#pragma unroll
        for (int kk = 0; kk < 4; kk++) {
            uint32_t a[4][4], b[2][4];
#pragma unroll
            for (int mi = 0; mi < 4; mi++) {
                uint32_t ad = stA + (wm + mi * 16 + (lane & 15)) * 144
                            + (kk * 16 + (lane >> 4) * 8) * 2;
                LDSM_X4(a[mi][0], a[mi][1], a[mi][2], a[mi][3], ad);
            }
#pragma unroll
            for (int nb = 0; nb < 2; nb++) {
                int nrow = wn + nb * 16 + ((lane >> 4) << 3) + (lane & 7);
                int koff = ((lane >> 3) & 1) * 8;
                uint32_t bd = stB + nrow * 144 + (kk * 16 + koff) * 2;
                LDSM_X4(b[nb][0], b[nb][1], b[nb][2], b[nb][3], bd);
            }
#pragma unroll
            for (int mi = 0; mi < 4; mi++) {
#pragma unroll
                for (int nb = 0; nb < 2; nb++) {
                    MMA16816(acc[mi][nb * 2 + 0], a[mi][0], a[mi][1], a[mi][2], a[mi][3],
                             b[nb][0], b[nb][1]);
                    MMA16816(acc[mi][nb * 2 + 1], a[mi][0], a[mi][1], a[mi][2], a[mi][3],
                             b[nb][2], b[nb][3]);
                }
            }
        }
        __syncthreads();
    }

    int cg = (lane & 3) * 2;
    int rg = lane >> 2;
#pragma unroll
    for (int ni = 0; ni < 4; ni++) {
        int c0 = bn + wn + ni * 8 + cg;
        float2 b2 = *(const float2*)(bias + c0);
#pragma unroll
        for (int mi = 0; mi < 4; mi++) {
            int r0 = bm + wm + mi * 16 + rg;
#pragma unroll
            for (int h = 0; h < 2; h++) {
                int r = r0 + h * 8;
                float v0 = acc[mi][ni][h * 2 + 0] + b2.x;
                float v1 = acc[mi][ni][h * 2 + 1] + b2.y;
                if (mode == 2) {
                    float2 rr = *(const float2*)(res + (size_t)r * N + c0);
                    *(float2*)(Cf + (size_t)r * N + c0) =
                        make_float2(v0 + rr.x, v1 + rr.y);
                } else {
                    int hh = c0 / 96;
                    int rem = c0 - hh * 96;
                    int type = rem >> 5;        // 0=q 1=k 2=v
                    int i2 = rem & 31;
                    int a = r & 511;
                    int bh = ((r >> 9) << 3) + hh;
                    size_t ob = ((size_t)bh * 512 + a) * 64 + i2;
                    uint32_t hw, lw;
                    if (type == 2) {
                        pack_split(v0, v1, hw, lw);
                        *(uint32_t*)(Ov + ob) = hw;
                        *(uint32_t*)(Ov + ob + 32) = lw;
                    } else {
                        float2 cs = rtbl[a * 16 + (i2 >> 1)];
                        float q0 = v0 * cs.x - v1 * cs.y;
                        float q1 = v1 * cs.x + v0 * cs.y;
                        if (type == 0) { q0 *= SCQ; q1 *= SCQ; }
                        pack_split(q0, q1, hw, lw);
                        __nv_bfloat16* O = (type == 0) ? Oq : Ok;
                        *(uint32_t*)(O + ob) = hw;
                        *(uint32_t*)(O + ob + 32) = lw;
                    }
                }
            }
        }
    }
}

// ===========================================================================
// Fused MLP: out += gelu(zln@W1^T + b1) @ W2^T + b2   (residual in-place)
// 512 threads, BM=128, BN=256 (full width), warp grid 2(M)x8(N), tile 64x32.
// Phase 1: h1 tile -> smem (split hi/lo, rows of 512 bf16 @ 1040B pitch).
// Phase 2: stream W2 via cp.async pipeline, A-frags from smem h1.
// ===========================================================================
#define MLP_STG 36864                 // W-stage: 256 rows x 144B
#define MLP_P1STG (18432 + 36864)     // A(128x144) + B(256x144) per stage
#define MLP_H1 133120                 // 128 rows x 1040B
#define MLP_SMEM (MLP_H1 + 2 * MLP_STG)   // 206848

__global__ __launch_bounds__(512, 1) void gemm_mlp(
    const __nv_bfloat16* __restrict__ Ap, const __nv_bfloat16* __restrict__ W1p,
    const __nv_bfloat16* __restrict__ W2p,
    const float* __restrict__ b1, const float* __restrict__ b2,
    float* __restrict__ out)
{
    extern __shared__ char dsm[];
    uint32_t sbase = smem_u32(dsm);
    uint32_t h1b = sbase;                       // phase-2 A buffer
    uint32_t w2b = sbase + MLP_H1;              // phase-2 B stages
    int tid = threadIdx.x, wid = tid >> 5, lane = tid & 31;
    int bm = blockIdx.x * 128;
    int wm = (wid & 1) * 64, wn = (wid >> 1) * 32;

    int ldr = tid >> 3;          // 0..63
    int ldc = (tid & 7) * 8;
    int lg8 = ((lane >> 4) << 3) + (lane & 7);
    int koff = ((lane >> 3) & 1) * 8;
    int cg = (lane & 3) * 2;
    int rg = lane >> 2;

    // ---------------- phase 1: h1 = gelu(zln @ W1^T + b1) ----------------
    {
        float acc[4][4][4];
#pragma unroll
        for (int mi = 0; mi < 4; mi++)
#pragma unroll
            for (int ni = 0; ni < 4; ni++)
#pragma unroll
                for (int e = 0; e < 4; e++) acc[mi][ni][e] = 0.f;

        auto issue1 = [&](int c) {
            int seg = c >> 2;
            int kg = (c & 3) * 64;
            int aoff = (seg == 2) ? 256 + kg : kg;
            int boff = (seg == 1) ? 256 + kg : kg;
            uint32_t st = sbase + (c & 1) * MLP_P1STG;
#pragma unroll
            for (int i = 0; i < 2; i++) {
                int r = ldr + i * 64;
                CP_ASYNC16(st + r * 144 + ldc * 2,
                           Ap + (size_t)(bm + r) * 512 + aoff + ldc);
            }
            uint32_t stB = st + 128 * 144;
#pragma unroll
            for (int i = 0; i < 4; i++) {
                int r = ldr + i * 64;
                CP_ASYNC16(stB + r * 144 + ldc * 2,
                           W1p + (size_t)r * 512 + boff + ldc);
            }
            CP_COMMIT();
        };

        issue1(0);
        for (int c = 0; c < 12; c++) {
            if (c + 1 < 12) { issue1(c + 1); CP_WAIT(1); } else { CP_WAIT(0); }
            __syncthreads();
            uint32_t stA = sbase + (c & 1) * MLP_P1STG;
            uint32_t stB = stA + 128 * 144;
#pragma unroll
            for (int kk = 0; kk < 4; kk++) {
                uint32_t a[4][4], b[2][4];
#pragma unroll
                for (int mi = 0; mi < 4; mi++) {
                    uint32_t ad = stA + (wm + mi * 16 + (lane & 15)) * 144
                                + (kk * 16 + (lane >> 4) * 8) * 2;
                    LDSM_X4(a[mi][0], a[mi][1], a[mi][2], a[mi][3], ad);
                }
#pragma unroll
                for (int nb = 0; nb < 2; nb++) {
                    int nrow = wn + nb * 16 + lg8;
                    uint32_t bd = stB + nrow * 144 + (kk * 16 + koff) * 2;
                    LDSM_X4(b[nb][0], b[nb][1], b[nb][2], b[nb][3], bd);
                }
#pragma unroll
                for (int mi = 0; mi < 4; mi++) {
#pragma unroll
                    for (int nb = 0; nb < 2; nb++) {
                        MMA16816(acc[mi][nb * 2 + 0], a[mi][0], a[mi][1], a[mi][2], a[mi][3],
                                 b[nb][0], b[nb][1]);
                        MMA16816(acc[mi][nb * 2 + 1], a[mi][0], a[mi][1], a[mi][2], a[mi][3],
                                 b[nb][2], b[nb][3]);
                    }
                }
            }
            __syncthreads();
        }

        // prefetch W2 chunk 0 while we do the gelu epilogue
        {
            int c = 0;
            int kg = 0, boff = kg;   // seg 0
            uint32_t st = w2b + (c & 1) * MLP_STG;
#pragma unroll
            for (int i = 0; i < 4; i++) {
                int r = ldr + i * 64;
                CP_ASYNC16(st + r * 144 + ldc * 2,
                           W2p + (size_t)r * 512 + boff + ldc);
            }
            CP_COMMIT();
        }

        // epilogue: bias + gelu -> split -> h1 smem
#pragma unroll
        for (int ni = 0; ni < 4; ni++) {
            int c0 = wn + ni * 8 + cg;
            float2 bb = *(const float2*)(b1 + c0);
#pragma unroll
            for (int mi = 0; mi < 4; mi++) {
#pragma unroll
                for (int h = 0; h < 2; h++) {
                    int r = wm + mi * 16 + rg + h * 8;
                    float v0 = acc[mi][ni][h * 2 + 0] + bb.x;
                    float v1 = acc[mi][ni][h * 2 + 1] + bb.y;
                    v0 = 0.5f * v0 * (1.f + erff(v0 * 0.7071067811865476f));
                    v1 = 0.5f * v1 * (1.f + erff(v1 * 0.7071067811865476f));
                    uint32_t hw, lw;
                    pack_split(v0, v1, hw, lw);
                    *(uint32_t*)(dsm + r * 1040 + c0 * 2) = hw;
                    *(uint32_t*)(dsm + r * 1040 + (256 + c0) * 2) = lw;
                }
            }
        }
    }
    __syncthreads();

    // ---------------- phase 2: out += h1 @ W2^T + b2 ----------------
    float acc[4][4][4];
#pragma unroll
    for (int mi = 0; mi < 4; mi++)
#pragma unroll
        for (int ni = 0; ni < 4; ni++)
#pragma unroll
            for (int e = 0; e < 4; e++) acc[mi][ni][e] = 0.f;

    auto issue2 = [&](int c) {
        int seg = c >> 2;
        int kg = (c & 3) * 64;
        int boff = (seg == 1) ? 256 + kg : kg;
        uint32_t st = w2b + (c & 1) * MLP_STG;
#pragma unroll
        for (int i = 0; i < 4; i++) {
            int r = ldr + i * 64;
            CP_ASYNC16(st + r * 144 + ldc * 2,
                       W2p + (size_t)r * 512 + boff + ldc);
        }
        CP_COMMIT();
    };

    for (int c = 0; c < 12; c++) {
        if (c + 1 < 12) { issue2(c + 1); CP_WAIT(1); } else { CP_WAIT(0); }
        __syncthreads();

        int seg = c >> 2;
        int kg = (c & 3) * 64;
        int aoff = (seg == 2) ? 256 + kg : kg;
        uint32_t stB = w2b + (c & 1) * MLP_STG;
#pragma unroll
        for (int kk = 0; kk < 4; kk++) {
            uint32_t a[4][4], b[2][4];
#pragma unroll
            for (int mi = 0; mi < 4; mi++) {
                uint32_t ad = h1b + (wm + mi * 16 + (lane & 15)) * 1040
                            + (aoff + kk * 16 + (lane >> 4) * 8) * 2;
                LDSM_X4(a[mi][0], a[mi][1], a[mi][2], a[mi][3], ad);
            }
#pragma unroll
            for (int nb = 0; nb < 2; nb++) {
                int nrow = wn + nb * 16 + lg8;
                uint32_t bd = stB + nrow * 144 + (kk * 16 + koff) * 2;
                LDSM_X4(b[nb][0], b[nb][1], b[nb][2], b[nb][3], bd);
            }
#pragma unroll
            for (int mi = 0; mi < 4; mi++) {
#pragma unroll
                for (int nb = 0; nb < 2; nb++) {
                    MMA16816(acc[mi][nb * 2 + 0], a[mi][0], a[mi][1], a[mi][2], a[mi][3],
                             b[nb][0], b[nb][1]);
                    MMA16816(acc[mi][nb * 2 + 1], a[mi][0], a[mi][1], a[mi][2], a[mi][3],
                             b[nb][2], b[nb][3]);
                }
            }
        }
        __syncthreads();
    }

    // epilogue: bias + residual (in-place on out)
#pragma unroll
    for (int ni = 0; ni < 4; ni++) {
        int c0 = wn + ni * 8 + cg;
        float2 bb = *(const float2*)(b2 + c0);
#pragma unroll
        for (int mi = 0; mi < 4; mi++) {
#pragma unroll
            for (int h = 0; h < 2; h++) {
                int r = bm + wm + mi * 16 + rg + h * 8;
                float v0 = acc[mi][ni][h * 2 + 0] + bb.x;
                float v1 = acc[mi][ni][h * 2 + 1] + bb.y;
                float2 rr = *(const float2*)(out + (size_t)r * 256 + c0);
                *(float2*)(out + (size_t)r * 256 + c0) =
                    make_float2(v0 + rr.x, v1 + rr.y);
            }
        }
    }
}

// ---------------------------------------------------------------------------
// Flash-style HMMA attention (unchanged, validated R9/R10).
// ---------------------------------------------------------------------------
#define ATT2_SMEM (3 * 73728)

__global__ __launch_bounds__(256) void attn_mma(
    const __nv_bfloat16* __restrict__ Qs, const __nv_bfloat16* __restrict__ Ks,
    const __nv_bfloat16* __restrict__ Vs, __nv_bfloat16* __restrict__ Op)
{
    extern __shared__ char sm[];
    uint32_t sQ = smem_u32(sm);
    uint32_t sK = sQ + 73728;
    uint32_t sV = sQ + 147456;
    int bh = blockIdx.x, tid = threadIdx.x, wid = tid >> 5, lane = tid & 31;

    const __nv_bfloat16* qg = Qs + (size_t)bh * 512 * 64;
    const __nv_bfloat16* kg = Ks + (size_t)bh * 512 * 64;
    const __nv_bfloat16* vg = Vs + (size_t)bh * 512 * 64;
    for (int idx = tid; idx < 4096; idx += 256) {
        int r = idx >> 3, c = idx & 7;
        CP_ASYNC16(sQ + r * 144 + c * 16, qg + r * 64 + c * 8);
        CP_ASYNC16(sK + r * 144 + c * 16, kg + r * 64 + c * 8);
        CP_ASYNC16(sV + r * 144 + c * 16, vg + r * 64 + c * 8);
    }
    CP_COMMIT(); CP_WAIT(0);
    __syncthreads();

    int wm = wid * 64;
    float acc[4][4][4];
    float mst[4][2], lst[4][2];
#pragma unroll
    for (int mi = 0; mi < 4; mi++) {
        mst[mi][0] = -1e30f; mst[mi][1] = -1e30f;
        lst[mi][0] = 0.f;    lst[mi][1] = 0.f;
#pragma unroll
        for (int jv = 0; jv < 4; jv++)
#pragma unroll
            for (int e = 0; e < 4; e++) acc[mi][jv][e] = 0.f;
    }

    int lg8 = ((lane >> 4) << 3) + (lane & 7);
    int lk8 = ((lane >> 3) & 1) * 16;
    int vrow = ((lane >> 3) & 1) * 8 + (lane & 7);
    int vcb = (lane >> 4) * 16;

    for (int kt = 0; kt < 16; kt++) {
        int kvb = kt * 32;

        uint32_t bK[4][4][2];
#pragma unroll
        for (int g16 = 0; g16 < 2; g16++)
#pragma unroll
            for (int kq = 0; kq < 4; kq++) {
                uint32_t ad = sK + (kvb + g16 * 16 + lg8) * 144 + kq * 32 + lk8;
                uint32_t r0, r1, r2, r3;
                LDSM_X4(r0, r1, r2, r3, ad);
                bK[g16 * 2][kq][0] = r0;     bK[g16 * 2][kq][1] = r1;
                bK[g16 * 2 + 1][kq][0] = r2; bK[g16 * 2 + 1][kq][1] = r3;
            }
        uint32_t bVh[4][2][2], bVl[4][2][2];
#pragma unroll
        for (int ks = 0; ks < 2; ks++) {
            uint32_t ad = sV + (kvb + ks * 16 + vrow) * 144 + vcb;
            uint32_t r0, r1, r2, r3;
            LDSM_X4_T(r0, r1, r2, r3, ad);
            bVh[0][ks][0] = r0; bVh[0][ks][1] = r1;
            bVh[1][ks][0] = r2; bVh[1][ks][1] = r3;
            LDSM_X4_T(r0, r1, r2, r3, ad + 32);
            bVh[2][ks][0] = r0; bVh[2][ks][1] = r1;
            bVh[3][ks][0] = r2; bVh[3][ks][1] = r3;
            LDSM_X4_T(r0, r1, r2, r3, ad + 64);
            bVl[0][ks][0] = r0; bVl[0][ks][1] = r1;
            bVl[1][ks][0] = r2; bVl[1][ks][1] = r3;
            LDSM_X4_T(r0, r1, r2, r3, ad + 96);
            bVl[2][ks][0] = r0; bVl[2][ks][1] = r1;
            bVl[3][ks][0] = r2; bVl[3][ks][1] = r3;
        }

#pragma unroll
        for (int mi = 0; mi < 4; mi++) {
            uint32_t aQ[4][4];
#pragma unroll
            for (int kq = 0; kq < 4; kq++) {
                uint32_t ad = sQ + (wm + mi * 16 + (lane & 15)) * 144
                            + kq * 32 + (lane >> 4) * 16;
                LDSM_X4(aQ[kq][0], aQ[kq][1], aQ[kq][2], aQ[kq][3], ad);
            }
            float s[4][4];
#pragma unroll
            for (int j = 0; j < 4; j++) {
#pragma unroll
                for (int e = 0; e < 4; e++) s[j][e] = 0.f;
                MMA16816(s[j], aQ[0][0], aQ[0][1], aQ[0][2], aQ[0][3], bK[j][0][0], bK[j][0][1]);
                MMA16816(s[j], aQ[1][0], aQ[1][1], aQ[1][2], aQ[1][3], bK[j][1][0], bK[j][1][1]);
                MMA16816(s[j], aQ[0][0], aQ[0][1], aQ[0][2], aQ[0][3], bK[j][2][0], bK[j][2][1]);
                MMA16816(s[j], aQ[1][0], aQ[1][1], aQ[1][2], aQ[1][3], bK[j][3][0], bK[j][3][1]);
                MMA16816(s[j], aQ[2][0], aQ[2][1], aQ[2][2], aQ[2][3], bK[j][0][0], bK[j][0][1]);
                MMA16816(s[j], aQ[3][0], aQ[3][1], aQ[3][2], aQ[3][3], bK[j][1][0], bK[j][1][1]);
            }
            float mx0 = -1e30f, mx1 = -1e30f;
#pragma unroll
            for (int j = 0; j < 4; j++) {
                mx0 = fmaxf(mx0, fmaxf(s[j][0], s[j][1]));
                mx1 = fmaxf(mx1, fmaxf(s[j][2], s[j][3]));
            }
            mx0 = fmaxf(mx0, __shfl_xor_sync(0xffffffffu, mx0, 1));
            mx0 = fmaxf(mx0, __shfl_xor_sync(0xffffffffu, mx0, 2));
            mx1 = fmaxf(mx1, __shfl_xor_sync(0xffffffffu, mx1, 1));
            mx1 = fmaxf(mx1, __shfl_xor_sync(0xffffffffu, mx1, 2));
            float mn0 = fmaxf(mst[mi][0], mx0);
            float mn1 = fmaxf(mst[mi][1], mx1);
            float al0 = __expf(mst[mi][0] - mn0);
            float al1 = __expf(mst[mi][1] - mn1);
            mst[mi][0] = mn0; mst[mi][1] = mn1;
            float sm0 = 0.f, sm1 = 0.f;
#pragma unroll
            for (int j = 0; j < 4; j++) {
                s[j][0] = __expf(s[j][0] - mn0); sm0 += s[j][0];
                s[j][1] = __expf(s[j][1] - mn0); sm0 += s[j][1];
                s[j][2] = __expf(s[j][2] - mn1); sm1 += s[j][2];
                s[j][3] = __expf(s[j][3] - mn1); sm1 += s[j][3];
            }
            sm0 += __shfl_xor_sync(0xffffffffu, sm0, 1);
            sm0 += __shfl_xor_sync(0xffffffffu, sm0, 2);
            sm1 += __shfl_xor_sync(0xffffffffu, sm1, 1);
            sm1 += __shfl_xor_sync(0xffffffffu, sm1, 2);
            lst[mi][0] = lst[mi][0] * al0 + sm0;
            lst[mi][1] = lst[mi][1] * al1 + sm1;
#pragma unroll
            for (int jv = 0; jv < 4; jv++) {
                acc[mi][jv][0] *= al0; acc[mi][jv][1] *= al0;
                acc[mi][jv][2] *= al1; acc[mi][jv][3] *= al1;
            }
            uint32_t aPh[2][4], aPl[2][4];
#pragma unroll
            for (int ks = 0; ks < 2; ks++) {
                int j0 = 2 * ks, j1 = 2 * ks + 1;
                aPh[ks][0] = packbf(s[j0][0], s[j0][1]);
                aPh[ks][1] = packbf(s[j0][2], s[j0][3]);
                aPh[ks][2] = packbf(s[j1][0], s[j1][1]);
                aPh[ks][3] = packbf(s[j1][2], s[j1][3]);
                __nv_bfloat162 h0 = *(__nv_bfloat162*)&aPh[ks][0];
                __nv_bfloat162 h1 = *(__nv_bfloat162*)&aPh[ks][1];
                __nv_bfloat162 h2 = *(__nv_bfloat162*)&aPh[ks][2];
                __nv_bfloat162 h3 = *(__nv_bfloat162*)&aPh[ks][3];
                aPl[ks][0] = packbf(s[j0][0] - __bfloat162float(h0.x),
                                    s[j0][1] - __bfloat162float(h0.y));
                aPl[ks][1] = packbf(s[j0][2] - __bfloat162float(h1.x),
                                    s[j0][3] - __bfloat162float(h1.y));
                aPl[ks][2] = packbf(s[j1][0] - __bfloat162float(h2.x),
                                    s[j1][1] - __bfloat162float(h2.y));
                aPl[ks][3] = packbf(s[j1][2] - __bfloat162float(h3.x),
                                    s[j1][3] - __bfloat162float(h3.y));
            }
#pragma unroll
            for (int jv = 0; jv < 4; jv++) {
                MMA16816(acc[mi][jv], aPh[0][0], aPh[0][1], aPh[0][2], aPh[0][3],
                         bVh[jv][0][0], bVh[jv][0][1]);
                MMA16816(acc[mi][jv], aPh[1][0], aPh[1][1], aPh[1][2], aPh[1][3],
                         bVh[jv][1][0], bVh[jv][1][1]);
                MMA16816(acc[mi][jv], aPh[0][0], aPh[0][1], aPh[0][2], aPh[0][3],
                         bVl[jv][0][0], bVl[jv][0][1]);
                MMA16816(acc[mi][jv], aPh[1][0], aPh[1][1], aPh[1][2], aPh[1][3],
                         bVl[jv][1][0], bVl[jv][1][1]);
                MMA16816(acc[mi][jv], aPl[0][0], aPl[0][1], aPl[0][2], aPl[0][3],
                         bVh[jv][0][0], bVh[jv][0][1]);
                MMA16816(acc[mi][jv], aPl[1][0], aPl[1][1], aPl[1][2], aPl[1][3],
                         bVh[jv][1][0], bVh[jv][1][1]);
            }
        }
    }

    int tb = (bh >> 3) * 512;
    int cb = (bh & 7) * 32;
#pragma unroll
    for (int mi = 0; mi < 4; mi++) {
        float i0 = 1.f / lst[mi][0];
        float i1 = 1.f / lst[mi][1];
        int r0 = wm + mi * 16 + (lane >> 2);
#pragma unroll
        for (int jv = 0; jv < 4; jv++) {
            int col = cb + jv * 8 + 2 * (lane & 3);
            uint32_t hw, lw;
            pack_split(acc[mi][jv][0] * i0, acc[mi][jv][1] * i0, hw, lw);
            size_t ob = (size_t)(tb + r0) * 512 + col;
            *(uint32_t*)(Op + ob) = hw;
            *(uint32_t*)(Op + ob + 256) = lw;
            pack_split(acc[mi][jv][2] * i1, acc[mi][jv][3] * i1, hw, lw);
            ob = (size_t)(tb + r0 + 8) * 512 + col;
            *(uint32_t*)(Op + ob) = hw;
            *(uint32_t*)(Op + ob + 256) = lw;
        }
    }
}

// ---------------------------------------------------------------------------
extern "C" void kernel_launch(void* const* d_in, const int* in_sizes, int n_in,
                              void* d_out, int out_size) {
    const float* z      = (const float*)d_in[0];
    const float* ln1_g  = (const float*)d_in[1];
    const float* ln1_b  = (const float*)d_in[2];
    const float* proj_v = (const float*)d_in[3];
    const float* proj_g = (const float*)d_in[4];
    const float* proj_b = (const float*)d_in[5];
    const float* ff_v   = (const float*)d_in[6];
    const float* ff_g   = (const float*)d_in[7];
    const float* ff_b   = (const float*)d_in[8];
    const float* ln2_g  = (const float*)d_in[9];
    const float* ln2_b  = (const float*)d_in[10];
    const float* w1_v   = (const float*)d_in[11];
    const float* w1_g   = (const float*)d_in[12];
    const float* w1_b   = (const float*)d_in[13];
    const float* w2_v   = (const float*)d_in[14];
    const float* w2_g   = (const float*)d_in[15];
    const float* w2_b   = (const float*)d_in[16];
    float* out = (float*)d_out;

    void *pWqkv, *pWo, *pW1, *pW2, *pzln, *pqs, *pks, *pvs, *patt, *ptbl;
    cudaGetSymbolAddress(&pWqkv, g_Wqkv);
    cudaGetSymbolAddress(&pWo, g_Wo);
    cudaGetSymbolAddress(&pW1, g_W1);
    cudaGetSymbolAddress(&pW2, g_W2);
    cudaGetSymbolAddress(&pzln, g_zln);
    cudaGetSymbolAddress(&pqs, g_qs);
    cudaGetSymbolAddress(&pks, g_ks);
    cudaGetSymbolAddress(&pvs, g_vs);
    cudaGetSymbolAddress(&patt, g_att);
    cudaGetSymbolAddress(&ptbl, g_rtbl);

    cudaFuncSetAttribute(gemm_mma, cudaFuncAttributeMaxDynamicSharedMemorySize, GEMM_SMEM);
    cudaFuncSetAttribute(gemm_mlp, cudaFuncAttributeMaxDynamicSharedMemorySize, MLP_SMEM);
    cudaFuncSetAttribute(attn_mma, cudaFuncAttributeMaxDynamicSharedMemorySize, ATT2_SMEM);

    // 0) rope table
    rope_tbl_kernel<<<32, 256>>>((float2*)ptbl);

    // 1) all weight norms
    wnorm_all<<<1536, 256>>>(proj_v, proj_g, ff_v, ff_g, w1_v, w1_g, w2_v, w2_g,
                             (__nv_bfloat16*)pWqkv, (__nv_bfloat16*)pWo,
                             (__nv_bfloat16*)pW1, (__nv_bfloat16*)pW2);

    // 2) LN1 -> packed bf16
    ln_kernel<<<T_TOK, 256>>>(z, ln1_g, ln1_b, (__nv_bfloat16*)pzln);

    // 3) QKV projection with fused bias+RoPE+split scatter
    gemm_mma<<<dim3(6, 256), 256, GEMM_SMEM>>>(
        (const __nv_bfloat16*)pzln, (const __nv_bfloat16*)pWqkv,
        proj_b, nullptr, nullptr,
        (const float2*)ptbl, (__nv_bfloat16*)pqs, (__nv_bfloat16*)pks,
        (__nv_bfloat16*)pvs, 768, 3);

    // 4) attention (flash HMMA) -> packed bf16
    attn_mma<<<512, 256, ATT2_SMEM>>>(
        (const __nv_bfloat16*)pqs, (const __nv_bfloat16*)pks,
        (const __nv_bfloat16*)pvs, (__nv_bfloat16*)patt);

    // 5) Wo + residual z -> out (fp32)
    gemm_mma<<<dim3(2, 256), 256, GEMM_SMEM>>>(
        (const __nv_bfloat16*)patt, (const __nv_bfloat16*)pWo,
        ff_b, z, out,
        nullptr, nullptr, nullptr, nullptr, 256, 2);

    // 6) LN2 -> packed bf16
    ln_kernel<<<T_TOK, 256>>>(out, ln2_g, ln2_b, (__nv_bfloat16*)pzln);

    // 7) fused MLP: out += gelu(zln@W1^T+b1)@W2^T + b2
    gemm_mlp<<<256, 512, MLP_SMEM>>>(
        (const __nv_bfloat16*)pzln, (const __nv_bfloat16*)pW1,
        (const __nv_bfloat16*)pW2, w1_b, w2_b, out);
}

// round 13
// speedup vs baseline: 1.1242x; 1.0451x over previous
#include <cuda_runtime.h>
#include <cuda_bf16.h>
#include <math.h>
#include <stdint.h>

// ---------------------------------------------------------------------------
// ResidualRoPETransformer: B=2,U=32,A=512,E=256,NH=8,HD=32, T=32768 tokens
// Round 13: attention softmax simplified — no max subtraction (scores provably
// bounded |s|<~45 << 88), no online rescale, lane-local sum deferred to epilogue.
// ---------------------------------------------------------------------------

#define T_TOK 32768
#define SEQ 512
#define HDIM 32

// ---- scratch (static device globals; no runtime allocation) ----
__device__ __nv_bfloat16 g_Wqkv[768 * 512];   // packed [hi(256)|lo(256)]
__device__ __nv_bfloat16 g_Wo[256 * 512];
__device__ __nv_bfloat16 g_W1[256 * 512];
__device__ __nv_bfloat16 g_W2[256 * 512];
__device__ __nv_bfloat16 g_zln[(size_t)T_TOK * 512];   // packed activations
__device__ __nv_bfloat16 g_att[(size_t)T_TOK * 512];
__device__ __nv_bfloat16 g_qs[(size_t)512 * 512 * 64];  // [bh][a][qh32|ql32] (scaled)
__device__ __nv_bfloat16 g_ks[(size_t)512 * 512 * 64];  // [bh][a][kh32|kl32]
__device__ __nv_bfloat16 g_vs[(size_t)512 * 512 * 64];  // [bh][a][vh32|vl32]
__device__ float2 g_rtbl[512 * 16];                     // (cos, sin) per (a, i)

// ===========================================================================
// PTX helpers (sm_80-level only: cp.async, ldmatrix, mma.sync)
// ===========================================================================
__device__ __forceinline__ uint32_t smem_u32(const void* p) {
    uint32_t a;
    asm("{ .reg .u64 t; cvta.to.shared.u64 t, %1; cvt.u32.u64 %0, t; }"
        : "=r"(a) : "l"(p));
    return a;
}
#define CP_ASYNC16(dst, src) \
    asm volatile("cp.async.cg.shared.global [%0], [%1], 16;" :: "r"(dst), "l"(src))
#define CP_COMMIT() asm volatile("cp.async.commit_group;" ::: "memory")
#define CP_WAIT(n)  asm volatile("cp.async.wait_group %0;" :: "n"(n) : "memory")

#define LDSM_X4(r0, r1, r2, r3, addr) \
    asm volatile("ldmatrix.sync.aligned.m8n8.x4.shared.b16 {%0,%1,%2,%3},[%4];" \
                 : "=r"(r0), "=r"(r1), "=r"(r2), "=r"(r3) : "r"(addr))
#define LDSM_X4_T(r0, r1, r2, r3, addr) \
    asm volatile("ldmatrix.sync.aligned.m8n8.x4.trans.shared.b16 {%0,%1,%2,%3},[%4];" \
                 : "=r"(r0), "=r"(r1), "=r"(r2), "=r"(r3) : "r"(addr))

#define MMA16816(d, a0, a1, a2, a3, b0, b1) \
    asm volatile("mma.sync.aligned.m16n8k16.row.col.f32.bf16.bf16.f32 " \
                 "{%0,%1,%2,%3},{%4,%5,%6,%7},{%8,%9},{%0,%1,%2,%3};" \
                 : "+f"((d)[0]), "+f"((d)[1]), "+f"((d)[2]), "+f"((d)[3]) \
                 : "r"(a0), "r"(a1), "r"(a2), "r"(a3), "r"(b0), "r"(b1))

__device__ __forceinline__ void split_bf16(float x, __nv_bfloat16& h, __nv_bfloat16& l) {
    h = __float2bfloat16(x);
    l = __float2bfloat16(x - __bfloat162float(h));
}
__device__ __forceinline__ uint32_t packbf(float a, float b) {
    __nv_bfloat162 t = __floats2bfloat162_rn(a, b);
    return *(uint32_t*)&t;
}
__device__ __forceinline__ void pack_split(float v0, float v1, uint32_t& hw, uint32_t& lw) {
    __nv_bfloat16 h0, l0, h1, l1;
    split_bf16(v0, h0, l0); split_bf16(v1, h1, l1);
    hw = packbf(__bfloat162float(h0), __bfloat162float(h1));
    lw = packbf(__bfloat162float(l0), __bfloat162float(l1));
}

// ===========================================================================
__device__ __forceinline__ float blockReduceSum256(float v, float* red) {
    int lane = threadIdx.x & 31, w = threadIdx.x >> 5;
#pragma unroll
    for (int o = 16; o; o >>= 1) v += __shfl_xor_sync(0xffffffffu, v, o);
    __syncthreads();
    if (lane == 0) red[w] = v;
    __syncthreads();
    float s = 0.f;
#pragma unroll
    for (int i = 0; i < 8; i++) s += red[i];
    return s;
}

// ---- rope table ----
__global__ void rope_tbl_kernel(float2* tbl) {
    int idx = blockIdx.x * 256 + threadIdx.x;    // 8192
    int a = idx >> 4, i = idx & 15;
    float freq = exp2f(-(float)i * 0.8304820237218406f);
    float s, c;
    sincosf((float)a * freq, &s, &c);
    tbl[idx] = make_float2(c, s);
}

// ---- all weight norms in one launch (grid 1536) ----
__global__ void wnorm_all(const float* __restrict__ pv, const float* __restrict__ pg,
                          const float* __restrict__ fv, const float* __restrict__ fg,
                          const float* __restrict__ w1v, const float* __restrict__ w1g,
                          const float* __restrict__ w2v, const float* __restrict__ w2g,
                          __nv_bfloat16* __restrict__ Wqkv, __nv_bfloat16* __restrict__ Wo,
                          __nv_bfloat16* __restrict__ W1, __nv_bfloat16* __restrict__ W2) {
    __shared__ float red[8];
    int b = blockIdx.x;
    const float *v, *g; __nv_bfloat16* W; int row;
    if (b < 768)       { v = pv;  g = pg;  W = Wqkv; row = b; }
    else if (b < 1024) { v = fv;  g = fg;  W = Wo;   row = b - 768; }
    else if (b < 1280) { v = w1v; g = w1g; W = W1;   row = b - 1024; }
    else               { v = w2v; g = w2g; W = W2;   row = b - 1280; }
    size_t base = (size_t)row * 256;
    float x = v[base + threadIdx.x];
    float ss = blockReduceSum256(x * x, red);
    float w = x * g[row] * rsqrtf(ss);
    __nv_bfloat16 h, l;
    split_bf16(w, h, l);
    size_t ob = (size_t)row * 512 + threadIdx.x;
    W[ob] = h;
    W[ob + 256] = l;
}

// ---- layernorm -> packed hi/lo bf16 [token][512] ----
__global__ void ln_kernel(const float* __restrict__ x, const float* __restrict__ g,
                          const float* __restrict__ b, __nv_bfloat16* __restrict__ y) {
    __shared__ float red[8];
    size_t base = (size_t)blockIdx.x * 256;
    float v = x[base + threadIdx.x];
    float mean = blockReduceSum256(v, red) * (1.f / 256.f);
    float d = v - mean;
    float var = blockReduceSum256(d * d, red) * (1.f / 256.f);
    float o = d * rsqrtf(var + 1e-5f) * g[threadIdx.x] + b[threadIdx.x];
    __nv_bfloat16 h, l;
    split_bf16(o, h, l);
    size_t ob = (size_t)blockIdx.x * 512 + threadIdx.x;
    y[ob] = h;
    y[ob + 256] = l;
}

// ===========================================================================
// mma.sync bf16 GEMM (split-3 packed K'=768). R10 config: 8 warps, 2(M)x4(N),
// warp tile 64x32. mode: 2 bias+residual fp32, 3 qkv: bias+rope -> split Q/K/V
// ===========================================================================
#define ROWP 72
#define STG_BYTES (2 * 128 * ROWP * 2)   // A+B per stage = 36864
#define GEMM_SMEM (2 * STG_BYTES)
#define SCQ 0.17677669529663687f

__global__ __launch_bounds__(256) void gemm_mma(
    const __nv_bfloat16* __restrict__ Ap, const __nv_bfloat16* __restrict__ Wp,
    const float* __restrict__ bias, const float* __restrict__ res,
    float* __restrict__ Cf,
    const float2* __restrict__ rtbl,
    __nv_bfloat16* __restrict__ Oq, __nv_bfloat16* __restrict__ Ok,
    __nv_bfloat16* __restrict__ Ov,
    int N, int mode)
{
    extern __shared__ char dsm[];
    int tid = threadIdx.x, wid = tid >> 5, lane = tid & 31;
    int bm = blockIdx.y * 128, bn = blockIdx.x * 128;
    int wm = (wid & 1) * 64, wn = (wid >> 1) * 32;

    uint32_t sbase = smem_u32(dsm);
    int ldr = tid >> 3;
    int ldc = (tid & 7) * 8;

    float acc[4][4][4];
#pragma unroll
    for (int mi = 0; mi < 4; mi++)
#pragma unroll
        for (int ni = 0; ni < 4; ni++)
#pragma unroll
            for (int e = 0; e < 4; e++) acc[mi][ni][e] = 0.f;

    auto issue_loads = [&](int c) {
        int seg = c >> 2;
        int kg = (c & 3) * 64;
        int aoff = (seg == 2) ? 256 + kg : kg;
        int boff = (seg == 1) ? 256 + kg : kg;
        uint32_t st = sbase + (c & 1) * STG_BYTES;
#pragma unroll
        for (int i = 0; i < 4; i++) {
            int r = ldr + i * 32;
            CP_ASYNC16(st + r * 144 + ldc * 2,
                       Ap + (size_t)(bm + r) * 512 + aoff + ldc);
        }
        uint32_t stB = st + 128 * 144;
#pragma unroll
        for (int i = 0; i < 4; i++) {
            int r = ldr + i * 32;
            CP_ASYNC16(stB + r * 144 + ldc * 2,
                       Wp + (size_t)(bn + r) * 512 + boff + ldc);
        }
        CP_COMMIT();
    };

    issue_loads(0);

    for (int c = 0; c < 12; c++) {
        if (c + 1 < 12) { issue_loads(c + 1); CP_WAIT(1); } else { CP_WAIT(0); }
        __syncthreads();

        uint32_t stA = sbase + (c & 1) * STG_BYTES;
        uint32_t stB = stA + 128 * 144;
#pragma unroll
        for (int kk = 0; kk < 4; kk++) {
            uint32_t a[4][4], b[2][4];
#pragma unroll
            for (int mi = 0; mi < 4; mi++) {
                uint32_t ad = stA + (wm + mi * 16 + (lane & 15)) * 144
                            + (kk * 16 + (lane >> 4) * 8) * 2;
                LDSM_X4(a[mi][0], a[mi][1], a[mi][2], a[mi][3], ad);
            }
#pragma unroll
            for (int nb = 0; nb < 2; nb++) {
                int nrow = wn + nb * 16 + ((lane >> 4) << 3) + (lane & 7);
                int koff = ((lane >> 3) & 1) * 8;
                uint32_t bd = stB + nrow * 144 + (kk * 16 + koff) * 2;
                LDSM_X4(b[nb][0], b[nb][1], b[nb][2], b[nb][3], bd);
            }
#pragma unroll
            for (int mi = 0; mi < 4; mi++) {
#pragma unroll
                for (int nb = 0; nb < 2; nb++) {
                    MMA16816(acc[mi][nb * 2 + 0], a[mi][0], a[mi][1], a[mi][2], a[mi][3],
                             b[nb][0], b[nb][1]);
                    MMA16816(acc[mi][nb * 2 + 1], a[mi][0], a[mi][1], a[mi][2], a[mi][3],
                             b[nb][2], b[nb][3]);
                }
            }
        }
        __syncthreads();
    }

    int cg = (lane & 3) * 2;
    int rg = lane >> 2;
#pragma unroll
    for (int ni = 0; ni < 4; ni++) {
        int c0 = bn + wn + ni * 8 + cg;
        float2 b2 = *(const float2*)(bias + c0);
#pragma unroll
        for (int mi = 0; mi < 4; mi++) {
            int r0 = bm + wm + mi * 16 + rg;
#pragma unroll
            for (int h = 0; h < 2; h++) {
                int r = r0 + h * 8;
                float v0 = acc[mi][ni][h * 2 + 0] + b2.x;
                float v1 = acc[mi][ni][h * 2 + 1] + b2.y;
                if (mode == 2) {
                    float2 rr = *(const float2*)(res + (size_t)r * N + c0);
                    *(float2*)(Cf + (size_t)r * N + c0) =
                        make_float2(v0 + rr.x, v1 + rr.y);
                } else {
                    int hh = c0 / 96;
                    int rem = c0 - hh * 96;
                    int type = rem >> 5;        // 0=q 1=k 2=v
                    int i2 = rem & 31;
                    int a = r & 511;
                    int bh = ((r >> 9) << 3) + hh;
                    size_t ob = ((size_t)bh * 512 + a) * 64 + i2;
                    uint32_t hw, lw;
                    if (type == 2) {
                        pack_split(v0, v1, hw, lw);
                        *(uint32_t*)(Ov + ob) = hw;
                        *(uint32_t*)(Ov + ob + 32) = lw;
                    } else {
                        float2 cs = rtbl[a * 16 + (i2 >> 1)];
                        float q0 = v0 * cs.x - v1 * cs.y;
                        float q1 = v1 * cs.x + v0 * cs.y;
                        if (type == 0) { q0 *= SCQ; q1 *= SCQ; }
                        pack_split(q0, q1, hw, lw);
                        __nv_bfloat16* O = (type == 0) ? Oq : Ok;
                        *(uint32_t*)(O + ob) = hw;
                        *(uint32_t*)(O + ob + 32) = lw;
                    }
                }
            }
        }
    }
}

// ===========================================================================
// Fused MLP: out += gelu(zln@W1^T + b1) @ W2^T + b2   (unchanged from R12)
// ===========================================================================
#define MLP_STG 36864                 // W-stage: 256 rows x 144B
#define MLP_P1STG (18432 + 36864)     // A(128x144) + B(256x144) per stage
#define MLP_H1 133120                 // 128 rows x 1040B
#define MLP_SMEM (MLP_H1 + 2 * MLP_STG)   // 206848

__global__ __launch_bounds__(512, 1) void gemm_mlp(
    const __nv_bfloat16* __restrict__ Ap, const __nv_bfloat16* __restrict__ W1p,
    const __nv_bfloat16* __restrict__ W2p,
    const float* __restrict__ b1, const float* __restrict__ b2,
    float* __restrict__ out)
{
    extern __shared__ char dsm[];
    uint32_t sbase = smem_u32(dsm);
    uint32_t h1b = sbase;
    uint32_t w2b = sbase + MLP_H1;
    int tid = threadIdx.x, wid = tid >> 5, lane = tid & 31;
    int bm = blockIdx.x * 128;
    int wm = (wid & 1) * 64, wn = (wid >> 1) * 32;

    int ldr = tid >> 3;
    int ldc = (tid & 7) * 8;
    int lg8 = ((lane >> 4) << 3) + (lane & 7);
    int koff = ((lane >> 3) & 1) * 8;
    int cg = (lane & 3) * 2;
    int rg = lane >> 2;

    // ---------------- phase 1: h1 = gelu(zln @ W1^T + b1) ----------------
    {
        float acc[4][4][4];
#pragma unroll
        for (int mi = 0; mi < 4; mi++)
#pragma unroll
            for (int ni = 0; ni < 4; ni++)
#pragma unroll
                for (int e = 0; e < 4; e++) acc[mi][ni][e] = 0.f;

        auto issue1 = [&](int c) {
            int seg = c >> 2;
            int kg = (c & 3) * 64;
            int aoff = (seg == 2) ? 256 + kg : kg;
            int boff = (seg == 1) ? 256 + kg : kg;
            uint32_t st = sbase + (c & 1) * MLP_P1STG;
#pragma unroll
            for (int i = 0; i < 2; i++) {
                int r = ldr + i * 64;
                CP_ASYNC16(st + r * 144 + ldc * 2,
                           Ap + (size_t)(bm + r) * 512 + aoff + ldc);
            }
            uint32_t stB = st + 128 * 144;
#pragma unroll
            for (int i = 0; i < 4; i++) {
                int r = ldr + i * 64;
                CP_ASYNC16(stB + r * 144 + ldc * 2,
                           W1p + (size_t)r * 512 + boff + ldc);
            }
            CP_COMMIT();
        };

        issue1(0);
        for (int c = 0; c < 12; c++) {
            if (c + 1 < 12) { issue1(c + 1); CP_WAIT(1); } else { CP_WAIT(0); }
            __syncthreads();
            uint32_t stA = sbase + (c & 1) * MLP_P1STG;
            uint32_t stB = stA + 128 * 144;
#pragma unroll
            for (int kk = 0; kk < 4; kk++) {
                uint32_t a[4][4], b[2][4];
#pragma unroll
                for (int mi = 0; mi < 4; mi++) {
                    uint32_t ad = stA + (wm + mi * 16 + (lane & 15)) * 144
                                + (kk * 16 + (lane >> 4) * 8) * 2;
                    LDSM_X4(a[mi][0], a[mi][1], a[mi][2], a[mi][3], ad);
                }
#pragma unroll
                for (int nb = 0; nb < 2; nb++) {
                    int nrow = wn + nb * 16 + lg8;
                    uint32_t bd = stB + nrow * 144 + (kk * 16 + koff) * 2;
                    LDSM_X4(b[nb][0], b[nb][1], b[nb][2], b[nb][3], bd);
                }
#pragma unroll
                for (int mi = 0; mi < 4; mi++) {
#pragma unroll
                    for (int nb = 0; nb < 2; nb++) {
                        MMA16816(acc[mi][nb * 2 + 0], a[mi][0], a[mi][1], a[mi][2], a[mi][3],
                                 b[nb][0], b[nb][1]);
                        MMA16816(acc[mi][nb * 2 + 1], a[mi][0], a[mi][1], a[mi][2], a[mi][3],
                                 b[nb][2], b[nb][3]);
                    }
                }
            }
            __syncthreads();
        }

        // prefetch W2 chunk 0 while we do the gelu epilogue
        {
            uint32_t st = w2b;
#pragma unroll
            for (int i = 0; i < 4; i++) {
                int r = ldr + i * 64;
                CP_ASYNC16(st + r * 144 + ldc * 2,
                           W2p + (size_t)r * 512 + ldc);
            }
            CP_COMMIT();
        }

        // epilogue: bias + gelu -> split -> h1 smem
#pragma unroll
        for (int ni = 0; ni < 4; ni++) {
            int c0 = wn + ni * 8 + cg;
            float2 bb = *(const float2*)(b1 + c0);
#pragma unroll
            for (int mi = 0; mi < 4; mi++) {
#pragma unroll
                for (int h = 0; h < 2; h++) {
                    int r = wm + mi * 16 + rg + h * 8;
                    float v0 = acc[mi][ni][h * 2 + 0] + bb.x;
                    float v1 = acc[mi][ni][h * 2 + 1] + bb.y;
                    v0 = 0.5f * v0 * (1.f + erff(v0 * 0.7071067811865476f));
                    v1 = 0.5f * v1 * (1.f + erff(v1 * 0.7071067811865476f));
                    uint32_t hw, lw;
                    pack_split(v0, v1, hw, lw);
                    *(uint32_t*)(dsm + r * 1040 + c0 * 2) = hw;
                    *(uint32_t*)(dsm + r * 1040 + (256 + c0) * 2) = lw;
                }
            }
        }
    }
    __syncthreads();

    // ---------------- phase 2: out += h1 @ W2^T + b2 ----------------
    float acc[4][4][4];
#pragma unroll
    for (int mi = 0; mi < 4; mi++)
#pragma unroll
        for (int ni = 0; ni < 4; ni++)
#pragma unroll
            for (int e = 0; e < 4; e++) acc[mi][ni][e] = 0.f;

    auto issue2 = [&](int c) {
        int seg = c >> 2;
        int kg = (c & 3) * 64;
        int boff = (seg == 1) ? 256 + kg : kg;
        uint32_t st = w2b + (c & 1) * MLP_STG;
#pragma unroll
        for (int i = 0; i < 4; i++) {
            int r = ldr + i * 64;
            CP_ASYNC16(st + r * 144 + ldc * 2,
                       W2p + (size_t)r * 512 + boff + ldc);
        }
        CP_COMMIT();
    };

    for (int c = 0; c < 12; c++) {
        if (c + 1 < 12) { issue2(c + 1); CP_WAIT(1); } else { CP_WAIT(0); }
        __syncthreads();

        int seg = c >> 2;
        int kg = (c & 3) * 64;
        int aoff = (seg == 2) ? 256 + kg : kg;
        uint32_t stB = w2b + (c & 1) * MLP_STG;
#pragma unroll
        for (int kk = 0; kk < 4; kk++) {
            uint32_t a[4][4], b[2][4];
#pragma unroll
            for (int mi = 0; mi < 4; mi++) {
                uint32_t ad = h1b + (wm + mi * 16 + (lane & 15)) * 1040
                            + (aoff + kk * 16 + (lane >> 4) * 8) * 2;
                LDSM_X4(a[mi][0], a[mi][1], a[mi][2], a[mi][3], ad);
            }
#pragma unroll
            for (int nb = 0; nb < 2; nb++) {
                int nrow = wn + nb * 16 + lg8;
                uint32_t bd = stB + nrow * 144 + (kk * 16 + koff) * 2;
                LDSM_X4(b[nb][0], b[nb][1], b[nb][2], b[nb][3], bd);
            }
#pragma unroll
            for (int mi = 0; mi < 4; mi++) {
#pragma unroll
                for (int nb = 0; nb < 2; nb++) {
                    MMA16816(acc[mi][nb * 2 + 0], a[mi][0], a[mi][1], a[mi][2], a[mi][3],
                             b[nb][0], b[nb][1]);
                    MMA16816(acc[mi][nb * 2 + 1], a[mi][0], a[mi][1], a[mi][2], a[mi][3],
                             b[nb][2], b[nb][3]);
                }
            }
        }
        __syncthreads();
    }

#pragma unroll
    for (int ni = 0; ni < 4; ni++) {
        int c0 = wn + ni * 8 + cg;
        float2 bb = *(const float2*)(b2 + c0);
#pragma unroll
        for (int mi = 0; mi < 4; mi++) {
#pragma unroll
            for (int h = 0; h < 2; h++) {
                int r = bm + wm + mi * 16 + rg + h * 8;
                float v0 = acc[mi][ni][h * 2 + 0] + bb.x;
                float v1 = acc[mi][ni][h * 2 + 1] + bb.y;
                float2 rr = *(const float2*)(out + (size_t)r * 256 + c0);
                *(float2*)(out + (size_t)r * 256 + c0) =
                    make_float2(v0 + rr.x, v1 + rr.y);
            }
        }
    }
}

// ---------------------------------------------------------------------------
// Flash-style HMMA attention — R13: no max subtraction (shift-invariant
// softmax; scores bounded), no online rescale, lane-local sums reduced once.
// ---------------------------------------------------------------------------
#define ATT2_SMEM (3 * 73728)

__global__ __launch_bounds__(256) void attn_mma(
    const __nv_bfloat16* __restrict__ Qs, const __nv_bfloat16* __restrict__ Ks,
    const __nv_bfloat16* __restrict__ Vs, __nv_bfloat16* __restrict__ Op)
{
    extern __shared__ char sm[];
    uint32_t sQ = smem_u32(sm);
    uint32_t sK = sQ + 73728;
    uint32_t sV = sQ + 147456;
    int bh = blockIdx.x, tid = threadIdx.x, wid = tid >> 5, lane = tid & 31;

    const __nv_bfloat16* qg = Qs + (size_t)bh * 512 * 64;
    const __nv_bfloat16* kg = Ks + (size_t)bh * 512 * 64;
    const __nv_bfloat16* vg = Vs + (size_t)bh * 512 * 64;
    for (int idx = tid; idx < 4096; idx += 256) {
        int r = idx >> 3, c = idx & 7;
        CP_ASYNC16(sQ + r * 144 + c * 16, qg + r * 64 + c * 8);
        CP_ASYNC16(sK + r * 144 + c * 16, kg + r * 64 + c * 8);
        CP_ASYNC16(sV + r * 144 + c * 16, vg + r * 64 + c * 8);
    }
    CP_COMMIT(); CP_WAIT(0);
    __syncthreads();

    int wm = wid * 64;
    float acc[4][4][4];
    float lst[4][2];
#pragma unroll
    for (int mi = 0; mi < 4; mi++) {
        lst[mi][0] = 0.f; lst[mi][1] = 0.f;
#pragma unroll
        for (int jv = 0; jv < 4; jv++)
#pragma unroll
            for (int e = 0; e < 4; e++) acc[mi][jv][e] = 0.f;
    }

    int lg8 = ((lane >> 4) << 3) + (lane & 7);
    int lk8 = ((lane >> 3) & 1) * 16;
    int vrow = ((lane >> 3) & 1) * 8 + (lane & 7);
    int vcb = (lane >> 4) * 16;

    for (int kt = 0; kt < 16; kt++) {
        int kvb = kt * 32;

        uint32_t bK[4][4][2];
#pragma unroll
        for (int g16 = 0; g16 < 2; g16++)
#pragma unroll
            for (int kq = 0; kq < 4; kq++) {
                uint32_t ad = sK + (kvb + g16 * 16 + lg8) * 144 + kq * 32 + lk8;
                uint32_t r0, r1, r2, r3;
                LDSM_X4(r0, r1, r2, r3, ad);
                bK[g16 * 2][kq][0] = r0;     bK[g16 * 2][kq][1] = r1;
                bK[g16 * 2 + 1][kq][0] = r2; bK[g16 * 2 + 1][kq][1] = r3;
            }
        uint32_t bVh[4][2][2], bVl[4][2][2];
#pragma unroll
        for (int ks = 0; ks < 2; ks++) {
            uint32_t ad = sV + (kvb + ks * 16 + vrow) * 144 + vcb;
            uint32_t r0, r1, r2, r3;
            LDSM_X4_T(r0, r1, r2, r3, ad);
            bVh[0][ks][0] = r0; bVh[0][ks][1] = r1;
            bVh[1][ks][0] = r2; bVh[1][ks][1] = r3;
            LDSM_X4_T(r0, r1, r2, r3, ad + 32);
            bVh[2][ks][0] = r0; bVh[2][ks][1] = r1;
            bVh[3][ks][0] = r2; bVh[3][ks][1] = r3;
            LDSM_X4_T(r0, r1, r2, r3, ad + 64);
            bVl[0][ks][0] = r0; bVl[0][ks][1] = r1;
            bVl[1][ks][0] = r2; bVl[1][ks][1] = r3;
            LDSM_X4_T(r0, r1, r2, r3, ad + 96);
            bVl[2][ks][0] = r0; bVl[2][ks][1] = r1;
            bVl[3][ks][0] = r2; bVl[3][ks][1] = r3;
        }

#pragma unroll
        for (int mi = 0; mi < 4; mi++) {
            uint32_t aQ[4][4];
#pragma unroll
            for (int kq = 0; kq < 4; kq++) {
                uint32_t ad = sQ + (wm + mi * 16 + (lane & 15)) * 144
                            + kq * 32 + (lane >> 4) * 16;
                LDSM_X4(aQ[kq][0], aQ[kq][1], aQ[kq][2], aQ[kq][3], ad);
            }
            float s[4][4];
#pragma unroll
            for (int j = 0; j < 4; j++) {
#pragma unroll
                for (int e = 0; e < 4; e++) s[j][e] = 0.f;
                MMA16816(s[j], aQ[0][0], aQ[0][1], aQ[0][2], aQ[0][3], bK[j][0][0], bK[j][0][1]);
                MMA16816(s[j], aQ[1][0], aQ[1][1], aQ[1][2], aQ[1][3], bK[j][1][0], bK[j][1][1]);
                MMA16816(s[j], aQ[0][0], aQ[0][1], aQ[0][2], aQ[0][3], bK[j][2][0], bK[j][2][1]);
                MMA16816(s[j], aQ[1][0], aQ[1][1], aQ[1][2], aQ[1][3], bK[j][3][0], bK[j][3][1]);
                MMA16816(s[j], aQ[2][0], aQ[2][1], aQ[2][2], aQ[2][3], bK[j][0][0], bK[j][0][1]);
                MMA16816(s[j], aQ[3][0], aQ[3][1], aQ[3][2], aQ[3][3], bK[j][1][0], bK[j][1][1]);
            }
            // exp (no max subtraction — softmax shift-invariance, scores bounded)
            float sm0 = 0.f, sm1 = 0.f;
#pragma unroll
            for (int j = 0; j < 4; j++) {
                s[j][0] = __expf(s[j][0]); sm0 += s[j][0];
                s[j][1] = __expf(s[j][1]); sm0 += s[j][1];
                s[j][2] = __expf(s[j][2]); sm1 += s[j][2];
                s[j][3] = __expf(s[j][3]); sm1 += s[j][3];
            }
            lst[mi][0] += sm0;
            lst[mi][1] += sm1;
            // pack P hi/lo A-frags (C-frag layout == A-frag layout)
            uint32_t aPh[2][4], aPl[2][4];
#pragma unroll
            for (int ks = 0; ks < 2; ks++) {
                int j0 = 2 * ks, j1 = 2 * ks + 1;
                aPh[ks][0] = packbf(s[j0][0], s[j0][1]);
                aPh[ks][1] = packbf(s[j0][2], s[j0][3]);
                aPh[ks][2] = packbf(s[j1][0], s[j1][1]);
                aPh[ks][3] = packbf(s[j1][2], s[j1][3]);
                __nv_bfloat162 h0 = *(__nv_bfloat162*)&aPh[ks][0];
                __nv_bfloat162 h1 = *(__nv_bfloat162*)&aPh[ks][1];
                __nv_bfloat162 h2 = *(__nv_bfloat162*)&aPh[ks][2];
                __nv_bfloat162 h3 = *(__nv_bfloat162*)&aPh[ks][3];
                aPl[ks][0] = packbf(s[j0][0] - __bfloat162float(h0.x),
                                    s[j0][1] - __bfloat162float(h0.y));
                aPl[ks][1] = packbf(s[j0][2] - __bfloat162float(h1.x),
                                    s[j0][3] - __bfloat162float(h1.y));
                aPl[ks][2] = packbf(s[j1][0] - __bfloat162float(h2.x),
                                    s[j1][1] - __bfloat162float(h2.y));
                aPl[ks][3] = packbf(s[j1][2] - __bfloat162float(h3.x),
                                    s[j1][3] - __bfloat162float(h3.y));
            }
#pragma unroll
            for (int jv = 0; jv < 4; jv++) {
                MMA16816(acc[mi][jv], aPh[0][0], aPh[0][1], aPh[0][2], aPh[0][3],
                         bVh[jv][0][0], bVh[jv][0][1]);
                MMA16816(acc[mi][jv], aPh[1][0], aPh[1][1], aPh[1][2], aPh[1][3],
                         bVh[jv][1][0], bVh[jv][1][1]);
                MMA16816(acc[mi][jv], aPh[0][0], aPh[0][1], aPh[0][2], aPh[0][3],
                         bVl[jv][0][0], bVl[jv][0][1]);
                MMA16816(acc[mi][jv], aPh[1][0], aPh[1][1], aPh[1][2], aPh[1][3],
                         bVl[jv][1][0], bVl[jv][1][1]);
                MMA16816(acc[mi][jv], aPl[0][0], aPl[0][1], aPl[0][2], aPl[0][3],
                         bVh[jv][0][0], bVh[jv][0][1]);
                MMA16816(acc[mi][jv], aPl[1][0], aPl[1][1], aPl[1][2], aPl[1][3],
                         bVh[jv][1][0], bVh[jv][1][1]);
            }
        }
    }

    // final cross-lane row-sum reduction (rows span 4 lanes: xor 1 and 2)
#pragma unroll
    for (int mi = 0; mi < 4; mi++) {
        lst[mi][0] += __shfl_xor_sync(0xffffffffu, lst[mi][0], 1);
        lst[mi][0] += __shfl_xor_sync(0xffffffffu, lst[mi][0], 2);
        lst[mi][1] += __shfl_xor_sync(0xffffffffu, lst[mi][1], 1);
        lst[mi][1] += __shfl_xor_sync(0xffffffffu, lst[mi][1], 2);
    }

    int tb = (bh >> 3) * 512;
    int cb = (bh & 7) * 32;
#pragma unroll
    for (int mi = 0; mi < 4; mi++) {
        float i0 = 1.f / lst[mi][0];
        float i1 = 1.f / lst[mi][1];
        int r0 = wm + mi * 16 + (lane >> 2);
#pragma unroll
        for (int jv = 0; jv < 4; jv++) {
            int col = cb + jv * 8 + 2 * (lane & 3);
            uint32_t hw, lw;
            pack_split(acc[mi][jv][0] * i0, acc[mi][jv][1] * i0, hw, lw);
            size_t ob = (size_t)(tb + r0) * 512 + col;
            *(uint32_t*)(Op + ob) = hw;
            *(uint32_t*)(Op + ob + 256) = lw;
            pack_split(acc[mi][jv][2] * i1, acc[mi][jv][3] * i1, hw, lw);
            ob = (size_t)(tb + r0 + 8) * 512 + col;
            *(uint32_t*)(Op + ob) = hw;
            *(uint32_t*)(Op + ob + 256) = lw;
        }
    }
}

// ---------------------------------------------------------------------------
extern "C" void kernel_launch(void* const* d_in, const int* in_sizes, int n_in,
                              void* d_out, int out_size) {
    const float* z      = (const float*)d_in[0];
    const float* ln1_g  = (const float*)d_in[1];
    const float* ln1_b  = (const float*)d_in[2];
    const float* proj_v = (const float*)d_in[3];
    const float* proj_g = (const float*)d_in[4];
    const float* proj_b = (const float*)d_in[5];
    const float* ff_v   = (const float*)d_in[6];
    const float* ff_g   = (const float*)d_in[7];
    const float* ff_b   = (const float*)d_in[8];
    const float* ln2_g  = (const float*)d_in[9];
    const float* ln2_b  = (const float*)d_in[10];
    const float* w1_v   = (const float*)d_in[11];
    const float* w1_g   = (const float*)d_in[12];
    const float* w1_b   = (const float*)d_in[13];
    const float* w2_v   = (const float*)d_in[14];
    const float* w2_g   = (const float*)d_in[15];
    const float* w2_b   = (const float*)d_in[16];
    float* out = (float*)d_out;

    void *pWqkv, *pWo, *pW1, *pW2, *pzln, *pqs, *pks, *pvs, *patt, *ptbl;
    cudaGetSymbolAddress(&pWqkv, g_Wqkv);
    cudaGetSymbolAddress(&pWo, g_Wo);
    cudaGetSymbolAddress(&pW1, g_W1);
    cudaGetSymbolAddress(&pW2, g_W2);
    cudaGetSymbolAddress(&pzln, g_zln);
    cudaGetSymbolAddress(&pqs, g_qs);
    cudaGetSymbolAddress(&pks, g_ks);
    cudaGetSymbolAddress(&pvs, g_vs);
    cudaGetSymbolAddress(&patt, g_att);
    cudaGetSymbolAddress(&ptbl, g_rtbl);

    cudaFuncSetAttribute(gemm_mma, cudaFuncAttributeMaxDynamicSharedMemorySize, GEMM_SMEM);
    cudaFuncSetAttribute(gemm_mlp, cudaFuncAttributeMaxDynamicSharedMemorySize, MLP_SMEM);
    cudaFuncSetAttribute(attn_mma, cudaFuncAttributeMaxDynamicSharedMemorySize, ATT2_SMEM);

    // 0) rope table
    rope_tbl_kernel<<<32, 256>>>((float2*)ptbl);

    // 1) all weight norms
    wnorm_all<<<1536, 256>>>(proj_v, proj_g, ff_v, ff_g, w1_v, w1_g, w2_v, w2_g,
                             (__nv_bfloat16*)pWqkv, (__nv_bfloat16*)pWo,
                             (__nv_bfloat16*)pW1, (__nv_bfloat16*)pW2);

    // 2) LN1 -> packed bf16
    ln_kernel<<<T_TOK, 256>>>(z, ln1_g, ln1_b, (__nv_bfloat16*)pzln);

    // 3) QKV projection with fused bias+RoPE+split scatter
    gemm_mma<<<dim3(6, 256), 256, GEMM_SMEM>>>(
        (const __nv_bfloat16*)pzln, (const __nv_bfloat16*)pWqkv,
        proj_b, nullptr, nullptr,
        (const float2*)ptbl, (__nv_bfloat16*)pqs, (__nv_bfloat16*)pks,
        (__nv_bfloat16*)pvs, 768, 3);

    // 4) attention (flash HMMA, max-free softmax) -> packed bf16
    attn_mma<<<512, 256, ATT2_SMEM>>>(
        (const __nv_bfloat16*)pqs, (const __nv_bfloat16*)pks,
        (const __nv_bfloat16*)pvs, (__nv_bfloat16*)patt);

    // 5) Wo + residual z -> out (fp32)
    gemm_mma<<<dim3(2, 256), 256, GEMM_SMEM>>>(
        (const __nv_bfloat16*)patt, (const __nv_bfloat16*)pWo,
        ff_b, z, out,
        nullptr, nullptr, nullptr, nullptr, 256, 2);

    // 6) LN2 -> packed bf16
    ln_kernel<<<T_TOK, 256>>>(out, ln2_g, ln2_b, (__nv_bfloat16*)pzln);

    // 7) fused MLP: out += gelu(zln@W1^T+b1)@W2^T + b2
    gemm_mlp<<<256, 512, MLP_SMEM>>>(
        (const __nv_bfloat16*)pzln, (const __nv_bfloat16*)pW1,
        (const __nv_bfloat16*)pW2, w1_b, w2_b, out);
}

// round 14
// speedup vs baseline: 1.2331x; 1.0969x over previous
#include <cuda_runtime.h>
#include <cuda_bf16.h>
#include <math.h>
#include <stdint.h>

// ---------------------------------------------------------------------------
// ResidualRoPETransformer: B=2,U=32,A=512,E=256,NH=8,HD=32, T=32768 tokens
// Round 14: gemm_mma -> 3-stage cp.async ring with ONE barrier per chunk;
// ln_kernel -> warp-per-token. Attention/MLP unchanged (R13-validated).
// ---------------------------------------------------------------------------

#define T_TOK 32768
#define SEQ 512
#define HDIM 32

// ---- scratch (static device globals; no runtime allocation) ----
__device__ __nv_bfloat16 g_Wqkv[768 * 512];   // packed [hi(256)|lo(256)]
__device__ __nv_bfloat16 g_Wo[256 * 512];
__device__ __nv_bfloat16 g_W1[256 * 512];
__device__ __nv_bfloat16 g_W2[256 * 512];
__device__ __nv_bfloat16 g_zln[(size_t)T_TOK * 512];   // packed activations
__device__ __nv_bfloat16 g_att[(size_t)T_TOK * 512];
__device__ __nv_bfloat16 g_qs[(size_t)512 * 512 * 64];  // [bh][a][qh32|ql32] (scaled)
__device__ __nv_bfloat16 g_ks[(size_t)512 * 512 * 64];  // [bh][a][kh32|kl32]
__device__ __nv_bfloat16 g_vs[(size_t)512 * 512 * 64];  // [bh][a][vh32|vl32]
__device__ float2 g_rtbl[512 * 16];                     // (cos, sin) per (a, i)

// ===========================================================================
// PTX helpers (sm_80-level only: cp.async, ldmatrix, mma.sync)
// ===========================================================================
__device__ __forceinline__ uint32_t smem_u32(const void* p) {
    uint32_t a;
    asm("{ .reg .u64 t; cvta.to.shared.u64 t, %1; cvt.u32.u64 %0, t; }"
        : "=r"(a) : "l"(p));
    return a;
}
#define CP_ASYNC16(dst, src) \
    asm volatile("cp.async.cg.shared.global [%0], [%1], 16;" :: "r"(dst), "l"(src))
#define CP_COMMIT() asm volatile("cp.async.commit_group;" ::: "memory")
#define CP_WAIT(n)  asm volatile("cp.async.wait_group %0;" :: "n"(n) : "memory")

#define LDSM_X4(r0, r1, r2, r3, addr) \
    asm volatile("ldmatrix.sync.aligned.m8n8.x4.shared.b16 {%0,%1,%2,%3},[%4];" \
                 : "=r"(r0), "=r"(r1), "=r"(r2), "=r"(r3) : "r"(addr))
#define LDSM_X4_T(r0, r1, r2, r3, addr) \
    asm volatile("ldmatrix.sync.aligned.m8n8.x4.trans.shared.b16 {%0,%1,%2,%3},[%4];" \
                 : "=r"(r0), "=r"(r1), "=r"(r2), "=r"(r3) : "r"(addr))

#define MMA16816(d, a0, a1, a2, a3, b0, b1) \
    asm volatile("mma.sync.aligned.m16n8k16.row.col.f32.bf16.bf16.f32 " \
                 "{%0,%1,%2,%3},{%4,%5,%6,%7},{%8,%9},{%0,%1,%2,%3};" \
                 : "+f"((d)[0]), "+f"((d)[1]), "+f"((d)[2]), "+f"((d)[3]) \
                 : "r"(a0), "r"(a1), "r"(a2), "r"(a3), "r"(b0), "r"(b1))

__device__ __forceinline__ void split_bf16(float x, __nv_bfloat16& h, __nv_bfloat16& l) {
    h = __float2bfloat16(x);
    l = __float2bfloat16(x - __bfloat162float(h));
}
__device__ __forceinline__ uint32_t packbf(float a, float b) {
    __nv_bfloat162 t = __floats2bfloat162_rn(a, b);
    return *(uint32_t*)&t;
}
__device__ __forceinline__ void pack_split(float v0, float v1, uint32_t& hw, uint32_t& lw) {
    __nv_bfloat16 h0, l0, h1, l1;
    split_bf16(v0, h0, l0); split_bf16(v1, h1, l1);
    hw = packbf(__bfloat162float(h0), __bfloat162float(h1));
    lw = packbf(__bfloat162float(l0), __bfloat162float(l1));
}

// ===========================================================================
__device__ __forceinline__ float blockReduceSum256(float v, float* red) {
    int lane = threadIdx.x & 31, w = threadIdx.x >> 5;
#pragma unroll
    for (int o = 16; o; o >>= 1) v += __shfl_xor_sync(0xffffffffu, v, o);
    __syncthreads();
    if (lane == 0) red[w] = v;
    __syncthreads();
    float s = 0.f;
#pragma unroll
    for (int i = 0; i < 8; i++) s += red[i];
    return s;
}

// ---- rope table ----
__global__ void rope_tbl_kernel(float2* tbl) {
    int idx = blockIdx.x * 256 + threadIdx.x;    // 8192
    int a = idx >> 4, i = idx & 15;
    float freq = exp2f(-(float)i * 0.8304820237218406f);
    float s, c;
    sincosf((float)a * freq, &s, &c);
    tbl[idx] = make_float2(c, s);
}

// ---- all weight norms in one launch (grid 1536) ----
__global__ void wnorm_all(const float* __restrict__ pv, const float* __restrict__ pg,
                          const float* __restrict__ fv, const float* __restrict__ fg,
                          const float* __restrict__ w1v, const float* __restrict__ w1g,
                          const float* __restrict__ w2v, const float* __restrict__ w2g,
                          __nv_bfloat16* __restrict__ Wqkv, __nv_bfloat16* __restrict__ Wo,
                          __nv_bfloat16* __restrict__ W1, __nv_bfloat16* __restrict__ W2) {
    __shared__ float red[8];
    int b = blockIdx.x;
    const float *v, *g; __nv_bfloat16* W; int row;
    if (b < 768)       { v = pv;  g = pg;  W = Wqkv; row = b; }
    else if (b < 1024) { v = fv;  g = fg;  W = Wo;   row = b - 768; }
    else if (b < 1280) { v = w1v; g = w1g; W = W1;   row = b - 1024; }
    else               { v = w2v; g = w2g; W = W2;   row = b - 1280; }
    size_t base = (size_t)row * 256;
    float x = v[base + threadIdx.x];
    float ss = blockReduceSum256(x * x, red);
    float w = x * g[row] * rsqrtf(ss);
    __nv_bfloat16 h, l;
    split_bf16(w, h, l);
    size_t ob = (size_t)row * 512 + threadIdx.x;
    W[ob] = h;
    W[ob + 256] = l;
}

// ---- layernorm, warp-per-token (grid 4096, 8 tokens/block) ----
__global__ __launch_bounds__(256) void ln_kernel(
    const float* __restrict__ x, const float* __restrict__ g,
    const float* __restrict__ b, __nv_bfloat16* __restrict__ y) {
    int wid = threadIdx.x >> 5, lane = threadIdx.x & 31;
    int t = blockIdx.x * 8 + wid;
    const float4* xr = (const float4*)(x + (size_t)t * 256);
    float4 v0 = xr[lane];
    float4 v1 = xr[lane + 32];
    float s = v0.x + v0.y + v0.z + v0.w + v1.x + v1.y + v1.z + v1.w;
#pragma unroll
    for (int o = 16; o; o >>= 1) s += __shfl_xor_sync(0xffffffffu, s, o);
    float mean = s * (1.f / 256.f);
    float d0 = v0.x - mean, d1 = v0.y - mean, d2 = v0.z - mean, d3 = v0.w - mean;
    float d4 = v1.x - mean, d5 = v1.y - mean, d6 = v1.z - mean, d7 = v1.w - mean;
    float vv = d0*d0 + d1*d1 + d2*d2 + d3*d3 + d4*d4 + d5*d5 + d6*d6 + d7*d7;
#pragma unroll
    for (int o = 16; o; o >>= 1) vv += __shfl_xor_sync(0xffffffffu, vv, o);
    float inv = rsqrtf(vv * (1.f / 256.f) + 1e-5f);
    float4 g0 = *(const float4*)(g + lane * 4);
    float4 g1 = *(const float4*)(g + 128 + lane * 4);
    float4 b0 = *(const float4*)(b + lane * 4);
    float4 b1 = *(const float4*)(b + 128 + lane * 4);
    float o0 = d0 * inv * g0.x + b0.x, o1 = d1 * inv * g0.y + b0.y;
    float o2 = d2 * inv * g0.z + b0.z, o3 = d3 * inv * g0.w + b0.w;
    float o4 = d4 * inv * g1.x + b1.x, o5 = d5 * inv * g1.y + b1.y;
    float o6 = d6 * inv * g1.z + b1.z, o7 = d7 * inv * g1.w + b1.w;
    uint32_t hw0, lw0, hw1, lw1;
    __nv_bfloat16* yt = y + (size_t)t * 512;
    pack_split(o0, o1, hw0, lw0); pack_split(o2, o3, hw1, lw1);
    *(uint2*)(yt + lane * 4) = make_uint2(hw0, hw1);
    *(uint2*)(yt + 256 + lane * 4) = make_uint2(lw0, lw1);
    pack_split(o4, o5, hw0, lw0); pack_split(o6, o7, hw1, lw1);
    *(uint2*)(yt + 128 + lane * 4) = make_uint2(hw0, hw1);
    *(uint2*)(yt + 256 + 128 + lane * 4) = make_uint2(lw0, lw1);
}

// ===========================================================================
// mma.sync bf16 GEMM (split-3 packed K'=768). 8 warps, 2(M)x4(N), tile 64x32.
// R14: 3-stage cp.async ring, single __syncthreads per chunk.
// mode: 2 bias+residual fp32, 3 qkv: bias+rope -> split Q/K/V
// ===========================================================================
#define ROWP 72
#define STG_BYTES (2 * 128 * ROWP * 2)   // A+B per stage = 36864
#define GEMM_SMEM (3 * STG_BYTES)        // 110592
#define SCQ 0.17677669529663687f

__global__ __launch_bounds__(256) void gemm_mma(
    const __nv_bfloat16* __restrict__ Ap, const __nv_bfloat16* __restrict__ Wp,
    const float* __restrict__ bias, const float* __restrict__ res,
    float* __restrict__ Cf,
    const float2* __restrict__ rtbl,
    __nv_bfloat16* __restrict__ Oq, __nv_bfloat16* __restrict__ Ok,
    __nv_bfloat16* __restrict__ Ov,
    int N, int mode)
{
    extern __shared__ char dsm[];
    int tid = threadIdx.x, wid = tid >> 5, lane = tid & 31;
    int bm = blockIdx.y * 128, bn = blockIdx.x * 128;
    int wm = (wid & 1) * 64, wn = (wid >> 1) * 32;

    uint32_t sbase = smem_u32(dsm);
    int ldr = tid >> 3;
    int ldc = (tid & 7) * 8;

    float acc[4][4][4];
#pragma unroll
    for (int mi = 0; mi < 4; mi++)
#pragma unroll
        for (int ni = 0; ni < 4; ni++)
#pragma unroll
            for (int e = 0; e < 4; e++) acc[mi][ni][e] = 0.f;

    auto issue_loads = [&](int c) {
        int seg = c >> 2;
        int kg = (c & 3) * 64;
        int aoff = (seg == 2) ? 256 + kg : kg;
        int boff = (seg == 1) ? 256 + kg : kg;
        uint32_t st = sbase + (c % 3) * STG_BYTES;
#pragma unroll
        for (int i = 0; i < 4; i++) {
            int r = ldr + i * 32;
            CP_ASYNC16(st + r * 144 + ldc * 2,
                       Ap + (size_t)(bm + r) * 512 + aoff + ldc);
        }
        uint32_t stB = st + 128 * 144;
#pragma unroll
        for (int i = 0; i < 4; i++) {
            int r = ldr + i * 32;
            CP_ASYNC16(stB + r * 144 + ldc * 2,
                       Wp + (size_t)(bn + r) * 512 + boff + ldc);
        }
        CP_COMMIT();
    };

    issue_loads(0);
    issue_loads(1);
    CP_WAIT(1);
    __syncthreads();

    for (int c = 0; c < 12; c++) {
        uint32_t stA = sbase + (c % 3) * STG_BYTES;
        uint32_t stB = stA + 128 * 144;
#pragma unroll
        for (int kk = 0; kk < 4; kk++) {
            uint32_t a[4][4], b[2][4];
#pragma unroll
            for (int mi = 0; mi < 4; mi++) {
                uint32_t ad = stA + (wm + mi * 16 + (lane & 15)) * 144
                            + (kk * 16 + (lane >> 4) * 8) * 2;
                LDSM_X4(a[mi][0], a[mi][1], a[mi][2], a[mi][3], ad);
            }
#pragma unroll
            for (int nb = 0; nb < 2; nb++) {
                int nrow = wn + nb * 16 + ((lane >> 4) << 3) + (lane & 7);
                int koff = ((lane >> 3) & 1) * 8;
                uint32_t bd = stB + nrow * 144 + (kk * 16 + koff) * 2;
                LDSM_X4(b[nb][0], b[nb][1], b[nb][2], b[nb][3], bd);
            }
#pragma unroll
            for (int mi = 0; mi < 4; mi++) {
#pragma unroll
                for (int nb = 0; nb < 2; nb++) {
                    MMA16816(acc[mi][nb * 2 + 0], a[mi][0], a[mi][1], a[mi][2], a[mi][3],
                             b[nb][0], b[nb][1]);
                    MMA16816(acc[mi][nb * 2 + 1], a[mi][0], a[mi][1], a[mi][2], a[mi][3],
                             b[nb][2], b[nb][3]);
                }
            }
        }
        // pipeline: issue c+2 (overwrites stage read in iter c-1; barrier at end
        // of iter c-1 already drained those readers), wait for group c+1, sync.
        if (c + 2 < 12) { issue_loads(c + 2); CP_WAIT(1); __syncthreads(); }
        else if (c + 1 < 12) { CP_WAIT(0); __syncthreads(); }
    }

    int cg = (lane & 3) * 2;
    int rg = lane >> 2;
#pragma unroll
    for (int ni = 0; ni < 4; ni++) {
        int c0 = bn + wn + ni * 8 + cg;
        float2 b2 = *(const float2*)(bias + c0);
#pragma unroll
        for (int mi = 0; mi < 4; mi++) {
            int r0 = bm + wm + mi * 16 + rg;
#pragma unroll
            for (int h = 0; h < 2; h++) {
                int r = r0 + h * 8;
                float v0 = acc[mi][ni][h * 2 + 0] + b2.x;
                float v1 = acc[mi][ni][h * 2 + 1] + b2.y;
                if (mode == 2) {
                    float2 rr = *(const float2*)(res + (size_t)r * N + c0);
                    *(float2*)(Cf + (size_t)r * N + c0) =
                        make_float2(v0 + rr.x, v1 + rr.y);
                } else {
                    int hh = c0 / 96;
                    int rem = c0 - hh * 96;
                    int type = rem >> 5;        // 0=q 1=k 2=v
                    int i2 = rem & 31;
                    int a = r & 511;
                    int bh = ((r >> 9) << 3) + hh;
                    size_t ob = ((size_t)bh * 512 + a) * 64 + i2;
                    uint32_t hw, lw;
                    if (type == 2) {
                        pack_split(v0, v1, hw, lw);
                        *(uint32_t*)(Ov + ob) = hw;
                        *(uint32_t*)(Ov + ob + 32) = lw;
                    } else {
                        float2 cs = rtbl[a * 16 + (i2 >> 1)];
                        float q0 = v0 * cs.x - v1 * cs.y;
                        float q1 = v1 * cs.x + v0 * cs.y;
                        if (type == 0) { q0 *= SCQ; q1 *= SCQ; }
                        pack_split(q0, q1, hw, lw);
                        __nv_bfloat16* O = (type == 0) ? Oq : Ok;
                        *(uint32_t*)(O + ob) = hw;
                        *(uint32_t*)(O + ob + 32) = lw;
                    }
                }
            }
        }
    }
}

// ===========================================================================
// Fused MLP: out += gelu(zln@W1^T + b1) @ W2^T + b2   (unchanged from R12)
// ===========================================================================
#define MLP_STG 36864                 // W-stage: 256 rows x 144B
#define MLP_P1STG (18432 + 36864)     // A(128x144) + B(256x144) per stage
#define MLP_H1 133120                 // 128 rows x 1040B
#define MLP_SMEM (MLP_H1 + 2 * MLP_STG)   // 206848

__global__ __launch_bounds__(512, 1) void gemm_mlp(
    const __nv_bfloat16* __restrict__ Ap, const __nv_bfloat16* __restrict__ W1p,
    const __nv_bfloat16* __restrict__ W2p,
    const float* __restrict__ b1, const float* __restrict__ b2,
    float* __restrict__ out)
{
    extern __shared__ char dsm[];
    uint32_t sbase = smem_u32(dsm);
    uint32_t h1b = sbase;
    uint32_t w2b = sbase + MLP_H1;
    int tid = threadIdx.x, wid = tid >> 5, lane = tid & 31;
    int bm = blockIdx.x * 128;
    int wm = (wid & 1) * 64, wn = (wid >> 1) * 32;

    int ldr = tid >> 3;
    int ldc = (tid & 7) * 8;
    int lg8 = ((lane >> 4) << 3) + (lane & 7);
    int koff = ((lane >> 3) & 1) * 8;
    int cg = (lane & 3) * 2;
    int rg = lane >> 2;

    // ---------------- phase 1: h1 = gelu(zln @ W1^T + b1) ----------------
    {
        float acc[4][4][4];
#pragma unroll
        for (int mi = 0; mi < 4; mi++)
#pragma unroll
            for (int ni = 0; ni < 4; ni++)
#pragma unroll
                for (int e = 0; e < 4; e++) acc[mi][ni][e] = 0.f;

        auto issue1 = [&](int c) {
            int seg = c >> 2;
            int kg = (c & 3) * 64;
            int aoff = (seg == 2) ? 256 + kg : kg;
            int boff = (seg == 1) ? 256 + kg : kg;
            uint32_t st = sbase + (c & 1) * MLP_P1STG;
#pragma unroll
            for (int i = 0; i < 2; i++) {
                int r = ldr + i * 64;
                CP_ASYNC16(st + r * 144 + ldc * 2,
                           Ap + (size_t)(bm + r) * 512 + aoff + ldc);
            }
            uint32_t stB = st + 128 * 144;
#pragma unroll
            for (int i = 0; i < 4; i++) {
                int r = ldr + i * 64;
                CP_ASYNC16(stB + r * 144 + ldc * 2,
                           W1p + (size_t)r * 512 + boff + ldc);
            }
            CP_COMMIT();
        };

        issue1(0);
        for (int c = 0; c < 12; c++) {
            if (c + 1 < 12) { issue1(c + 1); CP_WAIT(1); } else { CP_WAIT(0); }
            __syncthreads();
            uint32_t stA = sbase + (c & 1) * MLP_P1STG;
            uint32_t stB = stA + 128 * 144;
#pragma unroll
            for (int kk = 0; kk < 4; kk++) {
                uint32_t a[4][4], b[2][4];
#pragma unroll
                for (int mi = 0; mi < 4; mi++) {
                    uint32_t ad = stA + (wm + mi * 16 + (lane & 15)) * 144
                                + (kk * 16 + (lane >> 4) * 8) * 2;
                    LDSM_X4(a[mi][0], a[mi][1], a[mi][2], a[mi][3], ad);
                }
#pragma unroll
                for (int nb = 0; nb < 2; nb++) {
                    int nrow = wn + nb * 16 + lg8;
                    uint32_t bd = stB + nrow * 144 + (kk * 16 + koff) * 2;
                    LDSM_X4(b[nb][0], b[nb][1], b[nb][2], b[nb][3], bd);
                }
#pragma unroll
                for (int mi = 0; mi < 4; mi++) {
#pragma unroll
                    for (int nb = 0; nb < 2; nb++) {
                        MMA16816(acc[mi][nb * 2 + 0], a[mi][0], a[mi][1], a[mi][2], a[mi][3],
                                 b[nb][0], b[nb][1]);
                        MMA16816(acc[mi][nb * 2 + 1], a[mi][0], a[mi][1], a[mi][2], a[mi][3],
                                 b[nb][2], b[nb][3]);
                    }
                }
            }
            __syncthreads();
        }

        // prefetch W2 chunk 0 while we do the gelu epilogue
        {
            uint32_t st = w2b;
#pragma unroll
            for (int i = 0; i < 4; i++) {
                int r = ldr + i * 64;
                CP_ASYNC16(st + r * 144 + ldc * 2,
                           W2p + (size_t)r * 512 + ldc);
            }
            CP_COMMIT();
        }

        // epilogue: bias + gelu -> split -> h1 smem
#pragma unroll
        for (int ni = 0; ni < 4; ni++) {
            int c0 = wn + ni * 8 + cg;
            float2 bb = *(const float2*)(b1 + c0);
#pragma unroll
            for (int mi = 0; mi < 4; mi++) {
#pragma unroll
                for (int h = 0; h < 2; h++) {
                    int r = wm + mi * 16 + rg + h * 8;
                    float v0 = acc[mi][ni][h * 2 + 0] + bb.x;
                    float v1 = acc[mi][ni][h * 2 + 1] + bb.y;
                    v0 = 0.5f * v0 * (1.f + erff(v0 * 0.7071067811865476f));
                    v1 = 0.5f * v1 * (1.f + erff(v1 * 0.7071067811865476f));
                    uint32_t hw, lw;
                    pack_split(v0, v1, hw, lw);
                    *(uint32_t*)(dsm + r * 1040 + c0 * 2) = hw;
                    *(uint32_t*)(dsm + r * 1040 + (256 + c0) * 2) = lw;
                }
            }
        }
    }
    __syncthreads();

    // ---------------- phase 2: out += h1 @ W2^T + b2 ----------------
    float acc[4][4][4];
#pragma unroll
    for (int mi = 0; mi < 4; mi++)
#pragma unroll
        for (int ni = 0; ni < 4; ni++)
#pragma unroll
            for (int e = 0; e < 4; e++) acc[mi][ni][e] = 0.f;

    auto issue2 = [&](int c) {
        int seg = c >> 2;
        int kg = (c & 3) * 64;
        int boff = (seg == 1) ? 256 + kg : kg;
        uint32_t st = w2b + (c & 1) * MLP_STG;
#pragma unroll
        for (int i = 0; i < 4; i++) {
            int r = ldr + i * 64;
            CP_ASYNC16(st + r * 144 + ldc * 2,
                       W2p + (size_t)r * 512 + boff + ldc);
        }
        CP_COMMIT();
    };

    for (int c = 0; c < 12; c++) {
        if (c + 1 < 12) { issue2(c + 1); CP_WAIT(1); } else { CP_WAIT(0); }
        __syncthreads();

        int seg = c >> 2;
        int kg = (c & 3) * 64;
        int aoff = (seg == 2) ? 256 + kg : kg;
        uint32_t stB = w2b + (c & 1) * MLP_STG;
#pragma unroll
        for (int kk = 0; kk < 4; kk++) {
            uint32_t a[4][4], b[2][4];
#pragma unroll
            for (int mi = 0; mi < 4; mi++) {
                uint32_t ad = h1b + (wm + mi * 16 + (lane & 15)) * 1040
                            + (aoff + kk * 16 + (lane >> 4) * 8) * 2;
                LDSM_X4(a[mi][0], a[mi][1], a[mi][2], a[mi][3], ad);
            }
#pragma unroll
            for (int nb = 0; nb < 2; nb++) {
                int nrow = wn + nb * 16 + lg8;
                uint32_t bd = stB + nrow * 144 + (kk * 16 + koff) * 2;
                LDSM_X4(b[nb][0], b[nb][1], b[nb][2], b[nb][3], bd);
            }
#pragma unroll
            for (int mi = 0; mi < 4; mi++) {
#pragma unroll
                for (int nb = 0; nb < 2; nb++) {
                    MMA16816(acc[mi][nb * 2 + 0], a[mi][0], a[mi][1], a[mi][2], a[mi][3],
                             b[nb][0], b[nb][1]);
                    MMA16816(acc[mi][nb * 2 + 1], a[mi][0], a[mi][1], a[mi][2], a[mi][3],
                             b[nb][2], b[nb][3]);
                }
            }
        }
        __syncthreads();
    }

#pragma unroll
    for (int ni = 0; ni < 4; ni++) {
        int c0 = wn + ni * 8 + cg;
        float2 bb = *(const float2*)(b2 + c0);
#pragma unroll
        for (int mi = 0; mi < 4; mi++) {
#pragma unroll
            for (int h = 0; h < 2; h++) {
                int r = bm + wm + mi * 16 + rg + h * 8;
                float v0 = acc[mi][ni][h * 2 + 0] + bb.x;
                float v1 = acc[mi][ni][h * 2 + 1] + bb.y;
                float2 rr = *(const float2*)(out + (size_t)r * 256 + c0);
                *(float2*)(out + (size_t)r * 256 + c0) =
                    make_float2(v0 + rr.x, v1 + rr.y);
            }
        }
    }
}

// ---------------------------------------------------------------------------
// Flash-style HMMA attention (R13 max-free softmax, validated).
// ---------------------------------------------------------------------------
#define ATT2_SMEM (3 * 73728)

__global__ __launch_bounds__(256) void attn_mma(
    const __nv_bfloat16* __restrict__ Qs, const __nv_bfloat16* __restrict__ Ks,
    const __nv_bfloat16* __restrict__ Vs, __nv_bfloat16* __restrict__ Op)
{
    extern __shared__ char sm[];
    uint32_t sQ = smem_u32(sm);
    uint32_t sK = sQ + 73728;
    uint32_t sV = sQ + 147456;
    int bh = blockIdx.x, tid = threadIdx.x, wid = tid >> 5, lane = tid & 31;

    const __nv_bfloat16* qg = Qs + (size_t)bh * 512 * 64;
    const __nv_bfloat16* kg = Ks + (size_t)bh * 512 * 64;
    const __nv_bfloat16* vg = Vs + (size_t)bh * 512 * 64;
    for (int idx = tid; idx < 4096; idx += 256) {
        int r = idx >> 3, c = idx & 7;
        CP_ASYNC16(sQ + r * 144 + c * 16, qg + r * 64 + c * 8);
        CP_ASYNC16(sK + r * 144 + c * 16, kg + r * 64 + c * 8);
        CP_ASYNC16(sV + r * 144 + c * 16, vg + r * 64 + c * 8);
    }
    CP_COMMIT(); CP_WAIT(0);
    __syncthreads();

    int wm = wid * 64;
    float acc[4][4][4];
    float lst[4][2];
#pragma unroll
    for (int mi = 0; mi < 4; mi++) {
        lst[mi][0] = 0.f; lst[mi][1] = 0.f;
#pragma unroll
        for (int jv = 0; jv < 4; jv++)
#pragma unroll
            for (int e = 0; e < 4; e++) acc[mi][jv][e] = 0.f;
    }

    int lg8 = ((lane >> 4) << 3) + (lane & 7);
    int lk8 = ((lane >> 3) & 1) * 16;
    int vrow = ((lane >> 3) & 1) * 8 + (lane & 7);
    int vcb = (lane >> 4) * 16;

    for (int kt = 0; kt < 16; kt++) {
        int kvb = kt * 32;

        uint32_t bK[4][4][2];
#pragma unroll
        for (int g16 = 0; g16 < 2; g16++)
#pragma unroll
            for (int kq = 0; kq < 4; kq++) {
                uint32_t ad = sK + (kvb + g16 * 16 + lg8) * 144 + kq * 32 + lk8;
                uint32_t r0, r1, r2, r3;
                LDSM_X4(r0, r1, r2, r3, ad);
                bK[g16 * 2][kq][0] = r0;     bK[g16 * 2][kq][1] = r1;
                bK[g16 * 2 + 1][kq][0] = r2; bK[g16 * 2 + 1][kq][1] = r3;
            }
        uint32_t bVh[4][2][2], bVl[4][2][2];
#pragma unroll
        for (int ks = 0; ks < 2; ks++) {
            uint32_t ad = sV + (kvb + ks * 16 + vrow) * 144 + vcb;
            uint32_t r0, r1, r2, r3;
            LDSM_X4_T(r0, r1, r2, r3, ad);
            bVh[0][ks][0] = r0; bVh[0][ks][1] = r1;
            bVh[1][ks][0] = r2; bVh[1][ks][1] = r3;
            LDSM_X4_T(r0, r1, r2, r3, ad + 32);
            bVh[2][ks][0] = r0; bVh[2][ks][1] = r1;
            bVh[3][ks][0] = r2; bVh[3][ks][1] = r3;
            LDSM_X4_T(r0, r1, r2, r3, ad + 64);
            bVl[0][ks][0] = r0; bVl[0][ks][1] = r1;
            bVl[1][ks][0] = r2; bVl[1][ks][1] = r3;
            LDSM_X4_T(r0, r1, r2, r3, ad + 96);
            bVl[2][ks][0] = r0; bVl[2][ks][1] = r1;
            bVl[3][ks][0] = r2; bVl[3][ks][1] = r3;
        }

#pragma unroll
        for (int mi = 0; mi < 4; mi++) {
            uint32_t aQ[4][4];
#pragma unroll
            for (int kq = 0; kq < 4; kq++) {
                uint32_t ad = sQ + (wm + mi * 16 + (lane & 15)) * 144
                            + kq * 32 + (lane >> 4) * 16;
                LDSM_X4(aQ[kq][0], aQ[kq][1], aQ[kq][2], aQ[kq][3], ad);
            }
            float s[4][4];
#pragma unroll
            for (int j = 0; j < 4; j++) {
#pragma unroll
                for (int e = 0; e < 4; e++) s[j][e] = 0.f;
                MMA16816(s[j], aQ[0][0], aQ[0][1], aQ[0][2], aQ[0][3], bK[j][0][0], bK[j][0][1]);
                MMA16816(s[j], aQ[1][0], aQ[1][1], aQ[1][2], aQ[1][3], bK[j][1][0], bK[j][1][1]);
                MMA16816(s[j], aQ[0][0], aQ[0][1], aQ[0][2], aQ[0][3], bK[j][2][0], bK[j][2][1]);
                MMA16816(s[j], aQ[1][0], aQ[1][1], aQ[1][2], aQ[1][3], bK[j][3][0], bK[j][3][1]);
                MMA16816(s[j], aQ[2][0], aQ[2][1], aQ[2][2], aQ[2][3], bK[j][0][0], bK[j][0][1]);
                MMA16816(s[j], aQ[3][0], aQ[3][1], aQ[3][2], aQ[3][3], bK[j][1][0], bK[j][1][1]);
            }
            // exp (no max subtraction — softmax shift-invariance, scores bounded)
            float sm0 = 0.f, sm1 = 0.f;
#pragma unroll
            for (int j = 0; j < 4; j++) {
                s[j][0] = __expf(s[j][0]); sm0 += s[j][0];
                s[j][1] = __expf(s[j][1]); sm0 += s[j][1];
                s[j][2] = __expf(s[j][2]); sm1 += s[j][2];
                s[j][3] = __expf(s[j][3]); sm1 += s[j][3];
            }
            lst[mi][0] += sm0;
            lst[mi][1] += sm1;
            uint32_t aPh[2][4], aPl[2][4];
#pragma unroll
            for (int ks = 0; ks < 2; ks++) {
                int j0 = 2 * ks, j1 = 2 * ks + 1;
                aPh[ks][0] = packbf(s[j0][0], s[j0][1]);
                aPh[ks][1] = packbf(s[j0][2], s[j0][3]);
                aPh[ks][2] = packbf(s[j1][0], s[j1][1]);
                aPh[ks][3] = packbf(s[j1][2], s[j1][3]);
                __nv_bfloat162 h0 = *(__nv_bfloat162*)&aPh[ks][0];
                __nv_bfloat162 h1 = *(__nv_bfloat162*)&aPh[ks][1];
                __nv_bfloat162 h2 = *(__nv_bfloat162*)&aPh[ks][2];
                __nv_bfloat162 h3 = *(__nv_bfloat162*)&aPh[ks][3];
                aPl[ks][0] = packbf(s[j0][0] - __bfloat162float(h0.x),
                                    s[j0][1] - __bfloat162float(h0.y));
                aPl[ks][1] = packbf(s[j0][2] - __bfloat162float(h1.x),
                                    s[j0][3] - __bfloat162float(h1.y));
                aPl[ks][2] = packbf(s[j1][0] - __bfloat162float(h2.x),
                                    s[j1][1] - __bfloat162float(h2.y));
                aPl[ks][3] = packbf(s[j1][2] - __bfloat162float(h3.x),
                                    s[j1][3] - __bfloat162float(h3.y));
            }
#pragma unroll
            for (int jv = 0; jv < 4; jv++) {
                MMA16816(acc[mi][jv], aPh[0][0], aPh[0][1], aPh[0][2], aPh[0][3],
                         bVh[jv][0][0], bVh[jv][0][1]);
                MMA16816(acc[mi][jv], aPh[1][0], aPh[1][1], aPh[1][2], aPh[1][3],
                         bVh[jv][1][0], bVh[jv][1][1]);
                MMA16816(acc[mi][jv], aPh[0][0], aPh[0][1], aPh[0][2], aPh[0][3],
                         bVl[jv][0][0], bVl[jv][0][1]);
                MMA16816(acc[mi][jv], aPh[1][0], aPh[1][1], aPh[1][2], aPh[1][3],
                         bVl[jv][1][0], bVl[jv][1][1]);
                MMA16816(acc[mi][jv], aPl[0][0], aPl[0][1], aPl[0][2], aPl[0][3],
                         bVh[jv][0][0], bVh[jv][0][1]);
                MMA16816(acc[mi][jv], aPl[1][0], aPl[1][1], aPl[1][2], aPl[1][3],
                         bVh[jv][1][0], bVh[jv][1][1]);
            }
        }
    }

#pragma unroll
    for (int mi = 0; mi < 4; mi++) {
        lst[mi][0] += __shfl_xor_sync(0xffffffffu, lst[mi][0], 1);
        lst[mi][0] += __shfl_xor_sync(0xffffffffu, lst[mi][0], 2);
        lst[mi][1] += __shfl_xor_sync(0xffffffffu, lst[mi][1], 1);
        lst[mi][1] += __shfl_xor_sync(0xffffffffu, lst[mi][1], 2);
    }

    int tb = (bh >> 3) * 512;
    int cb = (bh & 7) * 32;
#pragma unroll
    for (int mi = 0; mi < 4; mi++) {
        float i0 = 1.f / lst[mi][0];
        float i1 = 1.f / lst[mi][1];
        int r0 = wm + mi * 16 + (lane >> 2);
#pragma unroll
        for (int jv = 0; jv < 4; jv++) {
            int col = cb + jv * 8 + 2 * (lane & 3);
            uint32_t hw, lw;
            pack_split(acc[mi][jv][0] * i0, acc[mi][jv][1] * i0, hw, lw);
            size_t ob = (size_t)(tb + r0) * 512 + col;
            *(uint32_t*)(Op + ob) = hw;
            *(uint32_t*)(Op + ob + 256) = lw;
            pack_split(acc[mi][jv][2] * i1, acc[mi][jv][3] * i1, hw, lw);
            ob = (size_t)(tb + r0 + 8) * 512 + col;
            *(uint32_t*)(Op + ob) = hw;
            *(uint32_t*)(Op + ob + 256) = lw;
        }
    }
}

// ---------------------------------------------------------------------------
extern "C" void kernel_launch(void* const* d_in, const int* in_sizes, int n_in,
                              void* d_out, int out_size) {
    const float* z      = (const float*)d_in[0];
    const float* ln1_g  = (const float*)d_in[1];
    const float* ln1_b  = (const float*)d_in[2];
    const float* proj_v = (const float*)d_in[3];
    const float* proj_g = (const float*)d_in[4];
    const float* proj_b = (const float*)d_in[5];
    const float* ff_v   = (const float*)d_in[6];
    const float* ff_g   = (const float*)d_in[7];
    const float* ff_b   = (const float*)d_in[8];
    const float* ln2_g  = (const float*)d_in[9];
    const float* ln2_b  = (const float*)d_in[10];
    const float* w1_v   = (const float*)d_in[11];
    const float* w1_g   = (const float*)d_in[12];
    const float* w1_b   = (const float*)d_in[13];
    const float* w2_v   = (const float*)d_in[14];
    const float* w2_g   = (const float*)d_in[15];
    const float* w2_b   = (const float*)d_in[16];
    float* out = (float*)d_out;

    void *pWqkv, *pWo, *pW1, *pW2, *pzln, *pqs, *pks, *pvs, *patt, *ptbl;
    cudaGetSymbolAddress(&pWqkv, g_Wqkv);
    cudaGetSymbolAddress(&pWo, g_Wo);
    cudaGetSymbolAddress(&pW1, g_W1);
    cudaGetSymbolAddress(&pW2, g_W2);
    cudaGetSymbolAddress(&pzln, g_zln);
    cudaGetSymbolAddress(&pqs, g_qs);
    cudaGetSymbolAddress(&pks, g_ks);
    cudaGetSymbolAddress(&pvs, g_vs);
    cudaGetSymbolAddress(&patt, g_att);
    cudaGetSymbolAddress(&ptbl, g_rtbl);

    cudaFuncSetAttribute(gemm_mma, cudaFuncAttributeMaxDynamicSharedMemorySize, GEMM_SMEM);
    cudaFuncSetAttribute(gemm_mlp, cudaFuncAttributeMaxDynamicSharedMemorySize, MLP_SMEM);
    cudaFuncSetAttribute(attn_mma, cudaFuncAttributeMaxDynamicSharedMemorySize, ATT2_SMEM);

    // 0) rope table
    rope_tbl_kernel<<<32, 256>>>((float2*)ptbl);

    // 1) all weight norms
    wnorm_all<<<1536, 256>>>(proj_v, proj_g, ff_v, ff_g, w1_v, w1_g, w2_v, w2_g,
                             (__nv_bfloat16*)pWqkv, (__nv_bfloat16*)pWo,
                             (__nv_bfloat16*)pW1, (__nv_bfloat16*)pW2);

    // 2) LN1 -> packed bf16 (warp-per-token)
    ln_kernel<<<4096, 256>>>(z, ln1_g, ln1_b, (__nv_bfloat16*)pzln);

    // 3) QKV projection with fused bias+RoPE+split scatter
    gemm_mma<<<dim3(6, 256), 256, GEMM_SMEM>>>(
        (const __nv_bfloat16*)pzln, (const __nv_bfloat16*)pWqkv,
        proj_b, nullptr, nullptr,
        (const float2*)ptbl, (__nv_bfloat16*)pqs, (__nv_bfloat16*)pks,
        (__nv_bfloat16*)pvs, 768, 3);

    // 4) attention (flash HMMA, max-free softmax) -> packed bf16
    attn_mma<<<512, 256, ATT2_SMEM>>>(
        (const __nv_bfloat16*)pqs, (const __nv_bfloat16*)pks,
        (const __nv_bfloat16*)pvs, (__nv_bfloat16*)patt);

    // 5) Wo + residual z -> out (fp32)
    gemm_mma<<<dim3(2, 256), 256, GEMM_SMEM>>>(
        (const __nv_bfloat16*)patt, (const __nv_bfloat16*)pWo,
        ff_b, z, out,
        nullptr, nullptr, nullptr, nullptr, 256, 2);

    // 6) LN2 -> packed bf16 (warp-per-token)
    ln_kernel<<<4096, 256>>>(out, ln2_g, ln2_b, (__nv_bfloat16*)pzln);

    // 7) fused MLP: out += gelu(zln@W1^T+b1)@W2^T + b2
    gemm_mlp<<<256, 512, MLP_SMEM>>>(
        (const __nv_bfloat16*)pzln, (const __nv_bfloat16*)pW1,
        (const __nv_bfloat16*)pW2, w1_b, w2_b, out);
}

// round 15
// speedup vs baseline: 1.2569x; 1.0193x over previous
#include <cuda_runtime.h>
#include <cuda_bf16.h>
#include <math.h>
#include <stdint.h>

// ---------------------------------------------------------------------------
// ResidualRoPETransformer: B=2,U=32,A=512,E=256,NH=8,HD=32, T=32768 tokens
// Round 15: fuse Wo+residual+LN2 into one wide kernel; exp2f softmax with
// log2e folded into Q scale. gemm_mma/attn/MLP otherwise R14-validated.
// ---------------------------------------------------------------------------

#define T_TOK 32768
#define SEQ 512
#define HDIM 32

// ---- scratch (static device globals; no runtime allocation) ----
__device__ __nv_bfloat16 g_Wqkv[768 * 512];   // packed [hi(256)|lo(256)]
__device__ __nv_bfloat16 g_Wo[256 * 512];
__device__ __nv_bfloat16 g_W1[256 * 512];
__device__ __nv_bfloat16 g_W2[256 * 512];
__device__ __nv_bfloat16 g_zln[(size_t)T_TOK * 512];   // packed activations
__device__ __nv_bfloat16 g_att[(size_t)T_TOK * 512];
__device__ __nv_bfloat16 g_qs[(size_t)512 * 512 * 64];  // [bh][a][qh32|ql32] (scaled)
__device__ __nv_bfloat16 g_ks[(size_t)512 * 512 * 64];  // [bh][a][kh32|kl32]
__device__ __nv_bfloat16 g_vs[(size_t)512 * 512 * 64];  // [bh][a][vh32|vl32]
__device__ float2 g_rtbl[512 * 16];                     // (cos, sin) per (a, i)

// ===========================================================================
// PTX helpers (sm_80-level only: cp.async, ldmatrix, mma.sync)
// ===========================================================================
__device__ __forceinline__ uint32_t smem_u32(const void* p) {
    uint32_t a;
    asm("{ .reg .u64 t; cvta.to.shared.u64 t, %1; cvt.u32.u64 %0, t; }"
        : "=r"(a) : "l"(p));
    return a;
}
#define CP_ASYNC16(dst, src) \
    asm volatile("cp.async.cg.shared.global [%0], [%1], 16;" :: "r"(dst), "l"(src))
#define CP_COMMIT() asm volatile("cp.async.commit_group;" ::: "memory")
#define CP_WAIT(n)  asm volatile("cp.async.wait_group %0;" :: "n"(n) : "memory")

#define LDSM_X4(r0, r1, r2, r3, addr) \
    asm volatile("ldmatrix.sync.aligned.m8n8.x4.shared.b16 {%0,%1,%2,%3},[%4];" \
                 : "=r"(r0), "=r"(r1), "=r"(r2), "=r"(r3) : "r"(addr))
#define LDSM_X4_T(r0, r1, r2, r3, addr) \
    asm volatile("ldmatrix.sync.aligned.m8n8.x4.trans.shared.b16 {%0,%1,%2,%3},[%4];" \
                 : "=r"(r0), "=r"(r1), "=r"(r2), "=r"(r3) : "r"(addr))

#define MMA16816(d, a0, a1, a2, a3, b0, b1) \
    asm volatile("mma.sync.aligned.m16n8k16.row.col.f32.bf16.bf16.f32 " \
                 "{%0,%1,%2,%3},{%4,%5,%6,%7},{%8,%9},{%0,%1,%2,%3};" \
                 : "+f"((d)[0]), "+f"((d)[1]), "+f"((d)[2]), "+f"((d)[3]) \
                 : "r"(a0), "r"(a1), "r"(a2), "r"(a3), "r"(b0), "r"(b1))

__device__ __forceinline__ void split_bf16(float x, __nv_bfloat16& h, __nv_bfloat16& l) {
    h = __float2bfloat16(x);
    l = __float2bfloat16(x - __bfloat162float(h));
}
__device__ __forceinline__ uint32_t packbf(float a, float b) {
    __nv_bfloat162 t = __floats2bfloat162_rn(a, b);
    return *(uint32_t*)&t;
}
__device__ __forceinline__ void pack_split(float v0, float v1, uint32_t& hw, uint32_t& lw) {
    __nv_bfloat16 h0, l0, h1, l1;
    split_bf16(v0, h0, l0); split_bf16(v1, h1, l1);
    hw = packbf(__bfloat162float(h0), __bfloat162float(h1));
    lw = packbf(__bfloat162float(l0), __bfloat162float(l1));
}

// ===========================================================================
__device__ __forceinline__ float blockReduceSum256(float v, float* red) {
    int lane = threadIdx.x & 31, w = threadIdx.x >> 5;
#pragma unroll
    for (int o = 16; o; o >>= 1) v += __shfl_xor_sync(0xffffffffu, v, o);
    __syncthreads();
    if (lane == 0) red[w] = v;
    __syncthreads();
    float s = 0.f;
#pragma unroll
    for (int i = 0; i < 8; i++) s += red[i];
    return s;
}

// ---- rope table ----
__global__ void rope_tbl_kernel(float2* tbl) {
    int idx = blockIdx.x * 256 + threadIdx.x;    // 8192
    int a = idx >> 4, i = idx & 15;
    float freq = exp2f(-(float)i * 0.8304820237218406f);
    float s, c;
    sincosf((float)a * freq, &s, &c);
    tbl[idx] = make_float2(c, s);
}

// ---- all weight norms in one launch (grid 1536) ----
__global__ void wnorm_all(const float* __restrict__ pv, const float* __restrict__ pg,
                          const float* __restrict__ fv, const float* __restrict__ fg,
                          const float* __restrict__ w1v, const float* __restrict__ w1g,
                          const float* __restrict__ w2v, const float* __restrict__ w2g,
                          __nv_bfloat16* __restrict__ Wqkv, __nv_bfloat16* __restrict__ Wo,
                          __nv_bfloat16* __restrict__ W1, __nv_bfloat16* __restrict__ W2) {
    __shared__ float red[8];
    int b = blockIdx.x;
    const float *v, *g; __nv_bfloat16* W; int row;
    if (b < 768)       { v = pv;  g = pg;  W = Wqkv; row = b; }
    else if (b < 1024) { v = fv;  g = fg;  W = Wo;   row = b - 768; }
    else if (b < 1280) { v = w1v; g = w1g; W = W1;   row = b - 1024; }
    else               { v = w2v; g = w2g; W = W2;   row = b - 1280; }
    size_t base = (size_t)row * 256;
    float x = v[base + threadIdx.x];
    float ss = blockReduceSum256(x * x, red);
    float w = x * g[row] * rsqrtf(ss);
    __nv_bfloat16 h, l;
    split_bf16(w, h, l);
    size_t ob = (size_t)row * 512 + threadIdx.x;
    W[ob] = h;
    W[ob + 256] = l;
}

// ---- layernorm, warp-per-token (grid 4096, 8 tokens/block) ----
__global__ __launch_bounds__(256) void ln_kernel(
    const float* __restrict__ x, const float* __restrict__ g,
    const float* __restrict__ b, __nv_bfloat16* __restrict__ y) {
    int wid = threadIdx.x >> 5, lane = threadIdx.x & 31;
    int t = blockIdx.x * 8 + wid;
    const float4* xr = (const float4*)(x + (size_t)t * 256);
    float4 v0 = xr[lane];
    float4 v1 = xr[lane + 32];
    float s = v0.x + v0.y + v0.z + v0.w + v1.x + v1.y + v1.z + v1.w;
#pragma unroll
    for (int o = 16; o; o >>= 1) s += __shfl_xor_sync(0xffffffffu, s, o);
    float mean = s * (1.f / 256.f);
    float d0 = v0.x - mean, d1 = v0.y - mean, d2 = v0.z - mean, d3 = v0.w - mean;
    float d4 = v1.x - mean, d5 = v1.y - mean, d6 = v1.z - mean, d7 = v1.w - mean;
    float vv = d0*d0 + d1*d1 + d2*d2 + d3*d3 + d4*d4 + d5*d5 + d6*d6 + d7*d7;
#pragma unroll
    for (int o = 16; o; o >>= 1) vv += __shfl_xor_sync(0xffffffffu, vv, o);
    float inv = rsqrtf(vv * (1.f / 256.f) + 1e-5f);
    float4 g0 = *(const float4*)(g + lane * 4);
    float4 g1 = *(const float4*)(g + 128 + lane * 4);
    float4 b0 = *(const float4*)(b + lane * 4);
    float4 b1 = *(const float4*)(b + 128 + lane * 4);
    float o0 = d0 * inv * g0.x + b0.x, o1 = d1 * inv * g0.y + b0.y;
    float o2 = d2 * inv * g0.z + b0.z, o3 = d3 * inv * g0.w + b0.w;
    float o4 = d4 * inv * g1.x + b1.x, o5 = d5 * inv * g1.y + b1.y;
    float o6 = d6 * inv * g1.z + b1.z, o7 = d7 * inv * g1.w + b1.w;
    uint32_t hw0, lw0, hw1, lw1;
    __nv_bfloat16* yt = y + (size_t)t * 512;
    pack_split(o0, o1, hw0, lw0); pack_split(o2, o3, hw1, lw1);
    *(uint2*)(yt + lane * 4) = make_uint2(hw0, hw1);
    *(uint2*)(yt + 256 + lane * 4) = make_uint2(lw0, lw1);
    pack_split(o4, o5, hw0, lw0); pack_split(o6, o7, hw1, lw1);
    *(uint2*)(yt + 128 + lane * 4) = make_uint2(hw0, hw1);
    *(uint2*)(yt + 256 + 128 + lane * 4) = make_uint2(lw0, lw1);
}

// ===========================================================================
// mma.sync bf16 GEMM (split-3 packed K'=768). 8 warps, 2(M)x4(N), tile 64x32.
// 3-stage cp.async ring, single __syncthreads per chunk (R14-validated).
// mode: 2 bias+residual fp32, 3 qkv: bias+rope -> split Q/K/V
// ===========================================================================
#define ROWP 72
#define STG_BYTES (2 * 128 * ROWP * 2)   // A+B per stage = 36864
#define GEMM_SMEM (3 * STG_BYTES)        // 110592
// log2(e)/sqrt(32): fold softmax base-2 conversion into Q scaling
#define SCQE 0.2550348637156874f

__global__ __launch_bounds__(256) void gemm_mma(
    const __nv_bfloat16* __restrict__ Ap, const __nv_bfloat16* __restrict__ Wp,
    const float* __restrict__ bias, const float* __restrict__ res,
    float* __restrict__ Cf,
    const float2* __restrict__ rtbl,
    __nv_bfloat16* __restrict__ Oq, __nv_bfloat16* __restrict__ Ok,
    __nv_bfloat16* __restrict__ Ov,
    int N, int mode)
{
    extern __shared__ char dsm[];
    int tid = threadIdx.x, wid = tid >> 5, lane = tid & 31;
    int bm = blockIdx.y * 128, bn = blockIdx.x * 128;
    int wm = (wid & 1) * 64, wn = (wid >> 1) * 32;

    uint32_t sbase = smem_u32(dsm);
    int ldr = tid >> 3;
    int ldc = (tid & 7) * 8;

    float acc[4][4][4];
#pragma unroll
    for (int mi = 0; mi < 4; mi++)
#pragma unroll
        for (int ni = 0; ni < 4; ni++)
#pragma unroll
            for (int e = 0; e < 4; e++) acc[mi][ni][e] = 0.f;

    auto issue_loads = [&](int c) {
        int seg = c >> 2;
        int kg = (c & 3) * 64;
        int aoff = (seg == 2) ? 256 + kg : kg;
        int boff = (seg == 1) ? 256 + kg : kg;
        uint32_t st = sbase + (c % 3) * STG_BYTES;
#pragma unroll
        for (int i = 0; i < 4; i++) {
            int r = ldr + i * 32;
            CP_ASYNC16(st + r * 144 + ldc * 2,
                       Ap + (size_t)(bm + r) * 512 + aoff + ldc);
        }
        uint32_t stB = st + 128 * 144;
#pragma unroll
        for (int i = 0; i < 4; i++) {
            int r = ldr + i * 32;
            CP_ASYNC16(stB + r * 144 + ldc * 2,
                       Wp + (size_t)(bn + r) * 512 + boff + ldc);
        }
        CP_COMMIT();
    };

    issue_loads(0);
    issue_loads(1);
    CP_WAIT(1);
    __syncthreads();

    for (int c = 0; c < 12; c++) {
        uint32_t stA = sbase + (c % 3) * STG_BYTES;
        uint32_t stB = stA + 128 * 144;
#pragma unroll
        for (int kk = 0; kk < 4; kk++) {
            uint32_t a[4][4], b[2][4];
#pragma unroll
            for (int mi = 0; mi < 4; mi++) {
                uint32_t ad = stA + (wm + mi * 16 + (lane & 15)) * 144
                            + (kk * 16 + (lane >> 4) * 8) * 2;
                LDSM_X4(a[mi][0], a[mi][1], a[mi][2], a[mi][3], ad);
            }
#pragma unroll
            for (int nb = 0; nb < 2; nb++) {
                int nrow = wn + nb * 16 + ((lane >> 4) << 3) + (lane & 7);
                int koff = ((lane >> 3) & 1) * 8;
                uint32_t bd = stB + nrow * 144 + (kk * 16 + koff) * 2;
                LDSM_X4(b[nb][0], b[nb][1], b[nb][2], b[nb][3], bd);
            }
#pragma unroll
            for (int mi = 0; mi < 4; mi++) {
#pragma unroll
                for (int nb = 0; nb < 2; nb++) {
                    MMA16816(acc[mi][nb * 2 + 0], a[mi][0], a[mi][1], a[mi][2], a[mi][3],
                             b[nb][0], b[nb][1]);
                    MMA16816(acc[mi][nb * 2 + 1], a[mi][0], a[mi][1], a[mi][2], a[mi][3],
                             b[nb][2], b[nb][3]);
                }
            }
        }
        if (c + 2 < 12) { issue_loads(c + 2); CP_WAIT(1); __syncthreads(); }
        else if (c + 1 < 12) { CP_WAIT(0); __syncthreads(); }
    }

    int cg = (lane & 3) * 2;
    int rg = lane >> 2;
#pragma unroll
    for (int ni = 0; ni < 4; ni++) {
        int c0 = bn + wn + ni * 8 + cg;
        float2 b2 = *(const float2*)(bias + c0);
#pragma unroll
        for (int mi = 0; mi < 4; mi++) {
            int r0 = bm + wm + mi * 16 + rg;
#pragma unroll
            for (int h = 0; h < 2; h++) {
                int r = r0 + h * 8;
                float v0 = acc[mi][ni][h * 2 + 0] + b2.x;
                float v1 = acc[mi][ni][h * 2 + 1] + b2.y;
                if (mode == 2) {
                    float2 rr = *(const float2*)(res + (size_t)r * N + c0);
                    *(float2*)(Cf + (size_t)r * N + c0) =
                        make_float2(v0 + rr.x, v1 + rr.y);
                } else {
                    int hh = c0 / 96;
                    int rem = c0 - hh * 96;
                    int type = rem >> 5;        // 0=q 1=k 2=v
                    int i2 = rem & 31;
                    int a = r & 511;
                    int bh = ((r >> 9) << 3) + hh;
                    size_t ob = ((size_t)bh * 512 + a) * 64 + i2;
                    uint32_t hw, lw;
                    if (type == 2) {
                        pack_split(v0, v1, hw, lw);
                        *(uint32_t*)(Ov + ob) = hw;
                        *(uint32_t*)(Ov + ob + 32) = lw;
                    } else {
                        float2 cs = rtbl[a * 16 + (i2 >> 1)];
                        float q0 = v0 * cs.x - v1 * cs.y;
                        float q1 = v1 * cs.x + v0 * cs.y;
                        if (type == 0) { q0 *= SCQE; q1 *= SCQE; }
                        pack_split(q0, q1, hw, lw);
                        __nv_bfloat16* O = (type == 0) ? Oq : Ok;
                        *(uint32_t*)(O + ob) = hw;
                        *(uint32_t*)(O + ob + 32) = lw;
                    }
                }
            }
        }
    }
}

// ===========================================================================
// Fused Wo + residual + LN2: out = att@Wo^T + ff_b + z ; zln = LN(out)
// BM=128, BN=256 (full width), 512 thr, warp grid 2(M)x8(N), tile 64x32.
// 3-stage ring; after mainloop: epilogue -> global out + smem mid (fp32),
// then warp-per-row LN -> packed zln.
// ===========================================================================
#define WOLN_STG ((128 + 256) * 144)        // 55296 per stage
#define WOLN_SMEM (3 * WOLN_STG)            // 165888 (mid aliases base: 135168)

__global__ __launch_bounds__(512, 1) void gemm_wo_ln(
    const __nv_bfloat16* __restrict__ Ap, const __nv_bfloat16* __restrict__ Wp,
    const float* __restrict__ bias, const float* __restrict__ res,
    float* __restrict__ out,
    const float* __restrict__ lng, const float* __restrict__ lnb,
    __nv_bfloat16* __restrict__ zln)
{
    extern __shared__ char dsm[];
    uint32_t sbase = smem_u32(dsm);
    float* mid = (float*)dsm;               // [128][264] fp32, aliases stages
    int tid = threadIdx.x, wid = tid >> 5, lane = tid & 31;
    int bm = blockIdx.x * 128;
    int wm = (wid & 1) * 64, wn = (wid >> 1) * 32;

    int ldr = tid >> 3;          // 0..63
    int ldc = (tid & 7) * 8;
    int lg8 = ((lane >> 4) << 3) + (lane & 7);
    int koff = ((lane >> 3) & 1) * 8;
    int cg = (lane & 3) * 2;
    int rg = lane >> 2;

    float acc[4][4][4];
#pragma unroll
    for (int mi = 0; mi < 4; mi++)
#pragma unroll
        for (int ni = 0; ni < 4; ni++)
#pragma unroll
            for (int e = 0; e < 4; e++) acc[mi][ni][e] = 0.f;

    auto issue_loads = [&](int c) {
        int seg = c >> 2;
        int kg = (c & 3) * 64;
        int aoff = (seg == 2) ? 256 + kg : kg;
        int boff = (seg == 1) ? 256 + kg : kg;
        uint32_t st = sbase + (c % 3) * WOLN_STG;
#pragma unroll
        for (int i = 0; i < 2; i++) {
            int r = ldr + i * 64;
            CP_ASYNC16(st + r * 144 + ldc * 2,
                       Ap + (size_t)(bm + r) * 512 + aoff + ldc);
        }
        uint32_t stB = st + 128 * 144;
#pragma unroll
        for (int i = 0; i < 4; i++) {
            int r = ldr + i * 64;
            CP_ASYNC16(stB + r * 144 + ldc * 2,
                       Wp + (size_t)r * 512 + boff + ldc);
        }
        CP_COMMIT();
    };

    issue_loads(0);
    issue_loads(1);
    CP_WAIT(1);
    __syncthreads();

    for (int c = 0; c < 12; c++) {
        uint32_t stA = sbase + (c % 3) * WOLN_STG;
        uint32_t stB = stA + 128 * 144;
#pragma unroll
        for (int kk = 0; kk < 4; kk++) {
            uint32_t a[4][4], b[2][4];
#pragma unroll
            for (int mi = 0; mi < 4; mi++) {
                uint32_t ad = stA + (wm + mi * 16 + (lane & 15)) * 144
                            + (kk * 16 + (lane >> 4) * 8) * 2;
                LDSM_X4(a[mi][0], a[mi][1], a[mi][2], a[mi][3], ad);
            }
#pragma unroll
            for (int nb = 0; nb < 2; nb++) {
                int nrow = wn + nb * 16 + lg8;
                uint32_t bd = stB + nrow * 144 + (kk * 16 + koff) * 2;
                LDSM_X4(b[nb][0], b[nb][1], b[nb][2], b[nb][3], bd);
            }
#pragma unroll
            for (int mi = 0; mi < 4; mi++) {
#pragma unroll
                for (int nb = 0; nb < 2; nb++) {
                    MMA16816(acc[mi][nb * 2 + 0], a[mi][0], a[mi][1], a[mi][2], a[mi][3],
                             b[nb][0], b[nb][1]);
                    MMA16816(acc[mi][nb * 2 + 1], a[mi][0], a[mi][1], a[mi][2], a[mi][3],
                             b[nb][2], b[nb][3]);
                }
            }
        }
        if (c + 2 < 12) { issue_loads(c + 2); CP_WAIT(1); __syncthreads(); }
        else if (c + 1 < 12) { CP_WAIT(0); __syncthreads(); }
    }
    __syncthreads();   // drain readers of last stage before overwriting with mid

    // epilogue: bias + residual z -> global out AND smem mid (pitch 264 floats)
#pragma unroll
    for (int ni = 0; ni < 4; ni++) {
        int c0 = wn + ni * 8 + cg;
        float2 bb = *(const float2*)(bias + c0);
#pragma unroll
        for (int mi = 0; mi < 4; mi++) {
#pragma unroll
            for (int h = 0; h < 2; h++) {
                int r = wm + mi * 16 + rg + h * 8;
                int gr = bm + r;
                float2 rr = *(const float2*)(res + (size_t)gr * 256 + c0);
                float v0 = acc[mi][ni][h * 2 + 0] + bb.x + rr.x;
                float v1 = acc[mi][ni][h * 2 + 1] + bb.y + rr.y;
                *(float2*)(out + (size_t)gr * 256 + c0) = make_float2(v0, v1);
                *(float2*)(mid + r * 264 + c0) = make_float2(v0, v1);
            }
        }
    }
    __syncthreads();

    // LN pass: warp w handles rows w*8 .. w*8+7
#pragma unroll
    for (int i = 0; i < 8; i++) {
        int r = wid * 8 + i;
        const float4* xr = (const float4*)(mid + r * 264);
        float4 v0 = xr[lane];
        float4 v1 = xr[lane + 32];
        float s = v0.x + v0.y + v0.z + v0.w + v1.x + v1.y + v1.z + v1.w;
#pragma unroll
        for (int o = 16; o; o >>= 1) s += __shfl_xor_sync(0xffffffffu, s, o);
        float mean = s * (1.f / 256.f);
        float d0 = v0.x - mean, d1 = v0.y - mean, d2 = v0.z - mean, d3 = v0.w - mean;
        float d4 = v1.x - mean, d5 = v1.y - mean, d6 = v1.z - mean, d7 = v1.w - mean;
        float vv = d0*d0 + d1*d1 + d2*d2 + d3*d3 + d4*d4 + d5*d5 + d6*d6 + d7*d7;
#pragma unroll
        for (int o = 16; o; o >>= 1) vv += __shfl_xor_sync(0xffffffffu, vv, o);
        float inv = rsqrtf(vv * (1.f / 256.f) + 1e-5f);
        float4 g0 = *(const float4*)(lng + lane * 4);
        float4 g1 = *(const float4*)(lng + 128 + lane * 4);
        float4 b0 = *(const float4*)(lnb + lane * 4);
        float4 b1 = *(const float4*)(lnb + 128 + lane * 4);
        float o0 = d0 * inv * g0.x + b0.x, o1 = d1 * inv * g0.y + b0.y;
        float o2 = d2 * inv * g0.z + b0.z, o3 = d3 * inv * g0.w + b0.w;
        float o4 = d4 * inv * g1.x + b1.x, o5 = d5 * inv * g1.y + b1.y;
        float o6 = d6 * inv * g1.z + b1.z, o7 = d7 * inv * g1.w + b1.w;
        uint32_t hw0, lw0, hw1, lw1;
        __nv_bfloat16* yt = zln + (size_t)(bm + r) * 512;
        pack_split(o0, o1, hw0, lw0); pack_split(o2, o3, hw1, lw1);
        *(uint2*)(yt + lane * 4) = make_uint2(hw0, hw1);
        *(uint2*)(yt + 256 + lane * 4) = make_uint2(lw0, lw1);
        pack_split(o4, o5, hw0, lw0); pack_split(o6, o7, hw1, lw1);
        *(uint2*)(yt + 128 + lane * 4) = make_uint2(hw0, hw1);
        *(uint2*)(yt + 256 + 128 + lane * 4) = make_uint2(lw0, lw1);
    }
}

// ===========================================================================
// Fused MLP: out += gelu(zln@W1^T + b1) @ W2^T + b2   (unchanged from R12)
// ===========================================================================
#define MLP_STG 36864                 // W-stage: 256 rows x 144B
#define MLP_P1STG (18432 + 36864)     // A(128x144) + B(256x144) per stage
#define MLP_H1 133120                 // 128 rows x 1040B
#define MLP_SMEM (MLP_H1 + 2 * MLP_STG)   // 206848

__global__ __launch_bounds__(512, 1) void gemm_mlp(
    const __nv_bfloat16* __restrict__ Ap, const __nv_bfloat16* __restrict__ W1p,
    const __nv_bfloat16* __restrict__ W2p,
    const float* __restrict__ b1, const float* __restrict__ b2,
    float* __restrict__ out)
{
    extern __shared__ char dsm[];
    uint32_t sbase = smem_u32(dsm);
    uint32_t h1b = sbase;
    uint32_t w2b = sbase + MLP_H1;
    int tid = threadIdx.x, wid = tid >> 5, lane = tid & 31;
    int bm = blockIdx.x * 128;
    int wm = (wid & 1) * 64, wn = (wid >> 1) * 32;

    int ldr = tid >> 3;
    int ldc = (tid & 7) * 8;
    int lg8 = ((lane >> 4) << 3) + (lane & 7);
    int koff = ((lane >> 3) & 1) * 8;
    int cg = (lane & 3) * 2;
    int rg = lane >> 2;

    // ---------------- phase 1: h1 = gelu(zln @ W1^T + b1) ----------------
    {
        float acc[4][4][4];
#pragma unroll
        for (int mi = 0; mi < 4; mi++)
#pragma unroll
            for (int ni = 0; ni < 4; ni++)
#pragma unroll
                for (int e = 0; e < 4; e++) acc[mi][ni][e] = 0.f;

        auto issue1 = [&](int c) {
            int seg = c >> 2;
            int kg = (c & 3) * 64;
            int aoff = (seg == 2) ? 256 + kg : kg;
            int boff = (seg == 1) ? 256 + kg : kg;
            uint32_t st = sbase + (c & 1) * MLP_P1STG;
#pragma unroll
            for (int i = 0; i < 2; i++) {
                int r = ldr + i * 64;
                CP_ASYNC16(st + r * 144 + ldc * 2,
                           Ap + (size_t)(bm + r) * 512 + aoff + ldc);
            }
            uint32_t stB = st + 128 * 144;
#pragma unroll
            for (int i = 0; i < 4; i++) {
                int r = ldr + i * 64;
                CP_ASYNC16(stB + r * 144 + ldc * 2,
                           W1p + (size_t)r * 512 + boff + ldc);
            }
            CP_COMMIT();
        };

        issue1(0);
        for (int c = 0; c < 12; c++) {
            if (c + 1 < 12) { issue1(c + 1); CP_WAIT(1); } else { CP_WAIT(0); }
            __syncthreads();
            uint32_t stA = sbase + (c & 1) * MLP_P1STG;
            uint32_t stB = stA + 128 * 144;
#pragma unroll
            for (int kk = 0; kk < 4; kk++) {
                uint32_t a[4][4], b[2][4];
#pragma unroll
                for (int mi = 0; mi < 4; mi++) {
                    uint32_t ad = stA + (wm + mi * 16 + (lane & 15)) * 144
                                + (kk * 16 + (lane >> 4) * 8) * 2;
                    LDSM_X4(a[mi][0], a[mi][1], a[mi][2], a[mi][3], ad);
                }
#pragma unroll
                for (int nb = 0; nb < 2; nb++) {
                    int nrow = wn + nb * 16 + lg8;
                    uint32_t bd = stB + nrow * 144 + (kk * 16 + koff) * 2;
                    LDSM_X4(b[nb][0], b[nb][1], b[nb][2], b[nb][3], bd);
                }
#pragma unroll
                for (int mi = 0; mi < 4; mi++) {
#pragma unroll
                    for (int nb = 0; nb < 2; nb++) {
                        MMA16816(acc[mi][nb * 2 + 0], a[mi][0], a[mi][1], a[mi][2], a[mi][3],
                                 b[nb][0], b[nb][1]);
                        MMA16816(acc[mi][nb * 2 + 1], a[mi][0], a[mi][1], a[mi][2], a[mi][3],
                                 b[nb][2], b[nb][3]);
                    }
                }
            }
            __syncthreads();
        }

        // prefetch W2 chunk 0 while we do the gelu epilogue
        {
            uint32_t st = w2b;
#pragma unroll
            for (int i = 0; i < 4; i++) {
                int r = ldr + i * 64;
                CP_ASYNC16(st + r * 144 + ldc * 2,
                           W2p + (size_t)r * 512 + ldc);
            }
            CP_COMMIT();
        }

        // epilogue: bias + gelu -> split -> h1 smem
#pragma unroll
        for (int ni = 0; ni < 4; ni++) {
            int c0 = wn + ni * 8 + cg;
            float2 bb = *(const float2*)(b1 + c0);
#pragma unroll
            for (int mi = 0; mi < 4; mi++) {
#pragma unroll
                for (int h = 0; h < 2; h++) {
                    int r = wm + mi * 16 + rg + h * 8;
                    float v0 = acc[mi][ni][h * 2 + 0] + bb.x;
                    float v1 = acc[mi][ni][h * 2 + 1] + bb.y;
                    v0 = 0.5f * v0 * (1.f + erff(v0 * 0.7071067811865476f));
                    v1 = 0.5f * v1 * (1.f + erff(v1 * 0.7071067811865476f));
                    uint32_t hw, lw;
                    pack_split(v0, v1, hw, lw);
                    *(uint32_t*)(dsm + r * 1040 + c0 * 2) = hw;
                    *(uint32_t*)(dsm + r * 1040 + (256 + c0) * 2) = lw;
                }
            }
        }
    }
    __syncthreads();

    // ---------------- phase 2: out += h1 @ W2^T + b2 ----------------
    float acc[4][4][4];
#pragma unroll
    for (int mi = 0; mi < 4; mi++)
#pragma unroll
        for (int ni = 0; ni < 4; ni++)
#pragma unroll
            for (int e = 0; e < 4; e++) acc[mi][ni][e] = 0.f;

    auto issue2 = [&](int c) {
        int seg = c >> 2;
        int kg = (c & 3) * 64;
        int boff = (seg == 1) ? 256 + kg : kg;
        uint32_t st = w2b + (c & 1) * MLP_STG;
#pragma unroll
        for (int i = 0; i < 4; i++) {
            int r = ldr + i * 64;
            CP_ASYNC16(st + r * 144 + ldc * 2,
                       W2p + (size_t)r * 512 + boff + ldc);
        }
        CP_COMMIT();
    };

    for (int c = 0; c < 12; c++) {
        if (c + 1 < 12) { issue2(c + 1); CP_WAIT(1); } else { CP_WAIT(0); }
        __syncthreads();

        int seg = c >> 2;
        int kg = (c & 3) * 64;
        int aoff = (seg == 2) ? 256 + kg : kg;
        uint32_t stB = w2b + (c & 1) * MLP_STG;
#pragma unroll
        for (int kk = 0; kk < 4; kk++) {
            uint32_t a[4][4], b[2][4];
#pragma unroll
            for (int mi = 0; mi < 4; mi++) {
                uint32_t ad = h1b + (wm + mi * 16 + (lane & 15)) * 1040
                            + (aoff + kk * 16 + (lane >> 4) * 8) * 2;
                LDSM_X4(a[mi][0], a[mi][1], a[mi][2], a[mi][3], ad);
            }
#pragma unroll
            for (int nb = 0; nb < 2; nb++) {
                int nrow = wn + nb * 16 + lg8;
                uint32_t bd = stB + nrow * 144 + (kk * 16 + koff) * 2;
                LDSM_X4(b[nb][0], b[nb][1], b[nb][2], b[nb][3], bd);
            }
#pragma unroll
            for (int mi = 0; mi < 4; mi++) {
#pragma unroll
                for (int nb = 0; nb < 2; nb++) {
                    MMA16816(acc[mi][nb * 2 + 0], a[mi][0], a[mi][1], a[mi][2], a[mi][3],
                             b[nb][0], b[nb][1]);
                    MMA16816(acc[mi][nb * 2 + 1], a[mi][0], a[mi][1], a[mi][2], a[mi][3],
                             b[nb][2], b[nb][3]);
                }
            }
        }
        __syncthreads();
    }

#pragma unroll
    for (int ni = 0; ni < 4; ni++) {
        int c0 = wn + ni * 8 + cg;
        float2 bb = *(const float2*)(b2 + c0);
#pragma unroll
        for (int mi = 0; mi < 4; mi++) {
#pragma unroll
            for (int h = 0; h < 2; h++) {
                int r = bm + wm + mi * 16 + rg + h * 8;
                float v0 = acc[mi][ni][h * 2 + 0] + bb.x;
                float v1 = acc[mi][ni][h * 2 + 1] + bb.y;
                float2 rr = *(const float2*)(out + (size_t)r * 256 + c0);
                *(float2*)(out + (size_t)r * 256 + c0) =
                    make_float2(v0 + rr.x, v1 + rr.y);
            }
        }
    }
}

// ---------------------------------------------------------------------------
// Flash-style HMMA attention (max-free softmax; base-2 exp, log2e pre-folded).
// ---------------------------------------------------------------------------
#define ATT2_SMEM (3 * 73728)

__global__ __launch_bounds__(256) void attn_mma(
    const __nv_bfloat16* __restrict__ Qs, const __nv_bfloat16* __restrict__ Ks,
    const __nv_bfloat16* __restrict__ Vs, __nv_bfloat16* __restrict__ Op)
{
    extern __shared__ char sm[];
    uint32_t sQ = smem_u32(sm);
    uint32_t sK = sQ + 73728;
    uint32_t sV = sQ + 147456;
    int bh = blockIdx.x, tid = threadIdx.x, wid = tid >> 5, lane = tid & 31;

    const __nv_bfloat16* qg = Qs + (size_t)bh * 512 * 64;
    const __nv_bfloat16* kg = Ks + (size_t)bh * 512 * 64;
    const __nv_bfloat16* vg = Vs + (size_t)bh * 512 * 64;
    for (int idx = tid; idx < 4096; idx += 256) {
        int r = idx >> 3, c = idx & 7;
        CP_ASYNC16(sQ + r * 144 + c * 16, qg + r * 64 + c * 8);
        CP_ASYNC16(sK + r * 144 + c * 16, kg + r * 64 + c * 8);
        CP_ASYNC16(sV + r * 144 + c * 16, vg + r * 64 + c * 8);
    }
    CP_COMMIT(); CP_WAIT(0);
    __syncthreads();

    int wm = wid * 64;
    float acc[4][4][4];
    float lst[4][2];
#pragma unroll
    for (int mi = 0; mi < 4; mi++) {
        lst[mi][0] = 0.f; lst[mi][1] = 0.f;
#pragma unroll
        for (int jv = 0; jv < 4; jv++)
#pragma unroll
            for (int e = 0; e < 4; e++) acc[mi][jv][e] = 0.f;
    }

    int lg8 = ((lane >> 4) << 3) + (lane & 7);
    int lk8 = ((lane >> 3) & 1) * 16;
    int vrow = ((lane >> 3) & 1) * 8 + (lane & 7);
    int vcb = (lane >> 4) * 16;

    for (int kt = 0; kt < 16; kt++) {
        int kvb = kt * 32;

        uint32_t bK[4][4][2];
#pragma unroll
        for (int g16 = 0; g16 < 2; g16++)
#pragma unroll
            for (int kq = 0; kq < 4; kq++) {
                uint32_t ad = sK + (kvb + g16 * 16 + lg8) * 144 + kq * 32 + lk8;
                uint32_t r0, r1, r2, r3;
                LDSM_X4(r0, r1, r2, r3, ad);
                bK[g16 * 2][kq][0] = r0;     bK[g16 * 2][kq][1] = r1;
                bK[g16 * 2 + 1][kq][0] = r2; bK[g16 * 2 + 1][kq][1] = r3;
            }
        uint32_t bVh[4][2][2], bVl[4][2][2];
#pragma unroll
        for (int ks = 0; ks < 2; ks++) {
            uint32_t ad = sV + (kvb + ks * 16 + vrow) * 144 + vcb;
            uint32_t r0, r1, r2, r3;
            LDSM_X4_T(r0, r1, r2, r3, ad);
            bVh[0][ks][0] = r0; bVh[0][ks][1] = r1;
            bVh[1][ks][0] = r2; bVh[1][ks][1] = r3;
            LDSM_X4_T(r0, r1, r2, r3, ad + 32);
            bVh[2][ks][0] = r0; bVh[2][ks][1] = r1;
            bVh[3][ks][0] = r2; bVh[3][ks][1] = r3;
            LDSM_X4_T(r0, r1, r2, r3, ad + 64);
            bVl[0][ks][0] = r0; bVl[0][ks][1] = r1;
            bVl[1][ks][0] = r2; bVl[1][ks][1] = r3;
            LDSM_X4_T(r0, r1, r2, r3, ad + 96);
            bVl[2][ks][0] = r0; bVl[2][ks][1] = r1;
            bVl[3][ks][0] = r2; bVl[3][ks][1] = r3;
        }

#pragma unroll
        for (int mi = 0; mi < 4; mi++) {
            uint32_t aQ[4][4];
#pragma unroll
            for (int kq = 0; kq < 4; kq++) {
                uint32_t ad = sQ + (wm + mi * 16 + (lane & 15)) * 144
                            + kq * 32 + (lane >> 4) * 16;
                LDSM_X4(aQ[kq][0], aQ[kq][1], aQ[kq][2], aQ[kq][3], ad);
            }
            float s[4][4];
#pragma unroll
            for (int j = 0; j < 4; j++) {
#pragma unroll
                for (int e = 0; e < 4; e++) s[j][e] = 0.f;
                MMA16816(s[j], aQ[0][0], aQ[0][1], aQ[0][2], aQ[0][3], bK[j][0][0], bK[j][0][1]);
                MMA16816(s[j], aQ[1][0], aQ[1][1], aQ[1][2], aQ[1][3], bK[j][1][0], bK[j][1][1]);
                MMA16816(s[j], aQ[0][0], aQ[0][1], aQ[0][2], aQ[0][3], bK[j][2][0], bK[j][2][1]);
                MMA16816(s[j], aQ[1][0], aQ[1][1], aQ[1][2], aQ[1][3], bK[j][3][0], bK[j][3][1]);
                MMA16816(s[j], aQ[2][0], aQ[2][1], aQ[2][2], aQ[2][3], bK[j][0][0], bK[j][0][1]);
                MMA16816(s[j], aQ[3][0], aQ[3][1], aQ[3][2], aQ[3][3], bK[j][1][0], bK[j][1][1]);
            }
            // base-2 exp (log2e folded into Q scale); no max subtraction
            float sm0 = 0.f, sm1 = 0.f;
#pragma unroll
            for (int j = 0; j < 4; j++) {
                s[j][0] = exp2f(s[j][0]); sm0 += s[j][0];
                s[j][1] = exp2f(s[j][1]); sm0 += s[j][1];
                s[j][2] = exp2f(s[j][2]); sm1 += s[j][2];
                s[j][3] = exp2f(s[j][3]); sm1 += s[j][3];
            }
            lst[mi][0] += sm0;
            lst[mi][1] += sm1;
            uint32_t aPh[2][4], aPl[2][4];
#pragma unroll
            for (int ks = 0; ks < 2; ks++) {
                int j0 = 2 * ks, j1 = 2 * ks + 1;
                aPh[ks][0] = packbf(s[j0][0], s[j0][1]);
                aPh[ks][1] = packbf(s[j0][2], s[j0][3]);
                aPh[ks][2] = packbf(s[j1][0], s[j1][1]);
                aPh[ks][3] = packbf(s[j1][2], s[j1][3]);
                __nv_bfloat162 h0 = *(__nv_bfloat162*)&aPh[ks][0];
                __nv_bfloat162 h1 = *(__nv_bfloat162*)&aPh[ks][1];
                __nv_bfloat162 h2 = *(__nv_bfloat162*)&aPh[ks][2];
                __nv_bfloat162 h3 = *(__nv_bfloat162*)&aPh[ks][3];
                aPl[ks][0] = packbf(s[j0][0] - __bfloat162float(h0.x),
                                    s[j0][1] - __bfloat162float(h0.y));
                aPl[ks][1] = packbf(s[j0][2] - __bfloat162float(h1.x),
                                    s[j0][3] - __bfloat162float(h1.y));
                aPl[ks][2] = packbf(s[j1][0] - __bfloat162float(h2.x),
                                    s[j1][1] - __bfloat162float(h2.y));
                aPl[ks][3] = packbf(s[j1][2] - __bfloat162float(h3.x),
                                    s[j1][3] - __bfloat162float(h3.y));
            }
#pragma unroll
            for (int jv = 0; jv < 4; jv++) {
                MMA16816(acc[mi][jv], aPh[0][0], aPh[0][1], aPh[0][2], aPh[0][3],
                         bVh[jv][0][0], bVh[jv][0][1]);
                MMA16816(acc[mi][jv], aPh[1][0], aPh[1][1], aPh[1][2], aPh[1][3],
                         bVh[jv][1][0], bVh[jv][1][1]);
                MMA16816(acc[mi][jv], aPh[0][0], aPh[0][1], aPh[0][2], aPh[0][3],
                         bVl[jv][0][0], bVl[jv][0][1]);
                MMA16816(acc[mi][jv], aPh[1][0], aPh[1][1], aPh[1][2], aPh[1][3],
                         bVl[jv][1][0], bVl[jv][1][1]);
                MMA16816(acc[mi][jv], aPl[0][0], aPl[0][1], aPl[0][2], aPl[0][3],
                         bVh[jv][0][0], bVh[jv][0][1]);
                MMA16816(acc[mi][jv], aPl[1][0], aPl[1][1], aPl[1][2], aPl[1][3],
                         bVh[jv][1][0], bVh[jv][1][1]);
            }
        }
    }

#pragma unroll
    for (int mi = 0; mi < 4; mi++) {
        lst[mi][0] += __shfl_xor_sync(0xffffffffu, lst[mi][0], 1);
        lst[mi][0] += __shfl_xor_sync(0xffffffffu, lst[mi][0], 2);
        lst[mi][1] += __shfl_xor_sync(0xffffffffu, lst[mi][1], 1);
        lst[mi][1] += __shfl_xor_sync(0xffffffffu, lst[mi][1], 2);
    }

    int tb = (bh >> 3) * 512;
    int cb = (bh & 7) * 32;
#pragma unroll
    for (int mi = 0; mi < 4; mi++) {
        float i0 = 1.f / lst[mi][0];
        float i1 = 1.f / lst[mi][1];
        int r0 = wm + mi * 16 + (lane >> 2);
#pragma unroll
        for (int jv = 0; jv < 4; jv++) {
            int col = cb + jv * 8 + 2 * (lane & 3);
            uint32_t hw, lw;
            pack_split(acc[mi][jv][0] * i0, acc[mi][jv][1] * i0, hw, lw);
            size_t ob = (size_t)(tb + r0) * 512 + col;
            *(uint32_t*)(Op + ob) = hw;
            *(uint32_t*)(Op + ob + 256) = lw;
            pack_split(acc[mi][jv][2] * i1, acc[mi][jv][3] * i1, hw, lw);
            ob = (size_t)(tb + r0 + 8) * 512 + col;
            *(uint32_t*)(Op + ob) = hw;
            *(uint32_t*)(Op + ob + 256) = lw;
        }
    }
}

// ---------------------------------------------------------------------------
extern "C" void kernel_launch(void* const* d_in, const int* in_sizes, int n_in,
                              void* d_out, int out_size) {
    const float* z      = (const float*)d_in[0];
    const float* ln1_g  = (const float*)d_in[1];
    const float* ln1_b  = (const float*)d_in[2];
    const float* proj_v = (const float*)d_in[3];
    const float* proj_g = (const float*)d_in[4];
    const float* proj_b = (const float*)d_in[5];
    const float* ff_v   = (const float*)d_in[6];
    const float* ff_g   = (const float*)d_in[7];
    const float* ff_b   = (const float*)d_in[8];
    const float* ln2_g  = (const float*)d_in[9];
    const float* ln2_b  = (const float*)d_in[10];
    const float* w1_v   = (const float*)d_in[11];
    const float* w1_g   = (const float*)d_in[12];
    const float* w1_b   = (const float*)d_in[13];
    const float* w2_v   = (const float*)d_in[14];
    const float* w2_g   = (const float*)d_in[15];
    const float* w2_b   = (const float*)d_in[16];
    float* out = (float*)d_out;

    void *pWqkv, *pWo, *pW1, *pW2, *pzln, *pqs, *pks, *pvs, *patt, *ptbl;
    cudaGetSymbolAddress(&pWqkv, g_Wqkv);
    cudaGetSymbolAddress(&pWo, g_Wo);
    cudaGetSymbolAddress(&pW1, g_W1);
    cudaGetSymbolAddress(&pW2, g_W2);
    cudaGetSymbolAddress(&pzln, g_zln);
    cudaGetSymbolAddress(&pqs, g_qs);
    cudaGetSymbolAddress(&pks, g_ks);
    cudaGetSymbolAddress(&pvs, g_vs);
    cudaGetSymbolAddress(&patt, g_att);
    cudaGetSymbolAddress(&ptbl, g_rtbl);

    cudaFuncSetAttribute(gemm_mma, cudaFuncAttributeMaxDynamicSharedMemorySize, GEMM_SMEM);
    cudaFuncSetAttribute(gemm_wo_ln, cudaFuncAttributeMaxDynamicSharedMemorySize, WOLN_SMEM);
    cudaFuncSetAttribute(gemm_mlp, cudaFuncAttributeMaxDynamicSharedMemorySize, MLP_SMEM);
    cudaFuncSetAttribute(attn_mma, cudaFuncAttributeMaxDynamicSharedMemorySize, ATT2_SMEM);

    // 0) rope table
    rope_tbl_kernel<<<32, 256>>>((float2*)ptbl);

    // 1) all weight norms
    wnorm_all<<<1536, 256>>>(proj_v, proj_g, ff_v, ff_g, w1_v, w1_g, w2_v, w2_g,
                             (__nv_bfloat16*)pWqkv, (__nv_bfloat16*)pWo,
                             (__nv_bfloat16*)pW1, (__nv_bfloat16*)pW2);

    // 2) LN1 -> packed bf16 (warp-per-token)
    ln_kernel<<<4096, 256>>>(z, ln1_g, ln1_b, (__nv_bfloat16*)pzln);

    // 3) QKV projection with fused bias+RoPE+split scatter (Q scaled by log2e/sqrt(32))
    gemm_mma<<<dim3(6, 256), 256, GEMM_SMEM>>>(
        (const __nv_bfloat16*)pzln, (const __nv_bfloat16*)pWqkv,
        proj_b, nullptr, nullptr,
        (const float2*)ptbl, (__nv_bfloat16*)pqs, (__nv_bfloat16*)pks,
        (__nv_bfloat16*)pvs, 768, 3);

    // 4) attention (flash HMMA, max-free base-2 softmax) -> packed bf16
    attn_mma<<<512, 256, ATT2_SMEM>>>(
        (const __nv_bfloat16*)pqs, (const __nv_bfloat16*)pks,
        (const __nv_bfloat16*)pvs, (__nv_bfloat16*)patt);

    // 5) fused Wo + residual z + LN2 -> out (fp32) and zln (packed bf16)
    gemm_wo_ln<<<256, 512, WOLN_SMEM>>>(
        (const __nv_bfloat16*)patt, (const __nv_bfloat16*)pWo,
        ff_b, z, out, ln2_g, ln2_b, (__nv_bfloat16*)pzln);

    // 6) fused MLP: out += gelu(zln@W1^T+b1)@W2^T + b2
    gemm_mlp<<<256, 512, MLP_SMEM>>>(
        (const __nv_bfloat16*)pzln, (const __nv_bfloat16*)pW1,
        (const __nv_bfloat16*)pW2, w1_b, w2_b, out);
}

// round 16
// speedup vs baseline: 1.2731x; 1.0129x over previous
#include <cuda_runtime.h>
#include <cuda_bf16.h>
#include <math.h>
#include <stdint.h>

// ---------------------------------------------------------------------------
// ResidualRoPETransformer: B=2,U=32,A=512,E=256,NH=8,HD=32, T=32768 tokens
// Round 16: attention v3 — 2 CTAs per bh (256 q-rows each), Q-fragments
// hoisted out of the kv loop (loop-invariant), K/V LDSM only per tile.
// Rest of pipeline R15-validated, unchanged.
// ---------------------------------------------------------------------------

#define T_TOK 32768
#define SEQ 512
#define HDIM 32

// ---- scratch (static device globals; no runtime allocation) ----
__device__ __nv_bfloat16 g_Wqkv[768 * 512];   // packed [hi(256)|lo(256)]
__device__ __nv_bfloat16 g_Wo[256 * 512];
__device__ __nv_bfloat16 g_W1[256 * 512];
__device__ __nv_bfloat16 g_W2[256 * 512];
__device__ __nv_bfloat16 g_zln[(size_t)T_TOK * 512];   // packed activations
__device__ __nv_bfloat16 g_att[(size_t)T_TOK * 512];
__device__ __nv_bfloat16 g_qs[(size_t)512 * 512 * 64];  // [bh][a][qh32|ql32] (scaled)
__device__ __nv_bfloat16 g_ks[(size_t)512 * 512 * 64];  // [bh][a][kh32|kl32]
__device__ __nv_bfloat16 g_vs[(size_t)512 * 512 * 64];  // [bh][a][vh32|vl32]
__device__ float2 g_rtbl[512 * 16];                     // (cos, sin) per (a, i)

// ===========================================================================
// PTX helpers (sm_80-level only: cp.async, ldmatrix, mma.sync)
// ===========================================================================
__device__ __forceinline__ uint32_t smem_u32(const void* p) {
    uint32_t a;
    asm("{ .reg .u64 t; cvta.to.shared.u64 t, %1; cvt.u32.u64 %0, t; }"
        : "=r"(a) : "l"(p));
    return a;
}
#define CP_ASYNC16(dst, src) \
    asm volatile("cp.async.cg.shared.global [%0], [%1], 16;" :: "r"(dst), "l"(src))
#define CP_COMMIT() asm volatile("cp.async.commit_group;" ::: "memory")
#define CP_WAIT(n)  asm volatile("cp.async.wait_group %0;" :: "n"(n) : "memory")

#define LDSM_X4(r0, r1, r2, r3, addr) \
    asm volatile("ldmatrix.sync.aligned.m8n8.x4.shared.b16 {%0,%1,%2,%3},[%4];" \
                 : "=r"(r0), "=r"(r1), "=r"(r2), "=r"(r3) : "r"(addr))
#define LDSM_X4_T(r0, r1, r2, r3, addr) \
    asm volatile("ldmatrix.sync.aligned.m8n8.x4.trans.shared.b16 {%0,%1,%2,%3},[%4];" \
                 : "=r"(r0), "=r"(r1), "=r"(r2), "=r"(r3) : "r"(addr))

#define MMA16816(d, a0, a1, a2, a3, b0, b1) \
    asm volatile("mma.sync.aligned.m16n8k16.row.col.f32.bf16.bf16.f32 " \
                 "{%0,%1,%2,%3},{%4,%5,%6,%7},{%8,%9},{%0,%1,%2,%3};" \
                 : "+f"((d)[0]), "+f"((d)[1]), "+f"((d)[2]), "+f"((d)[3]) \
                 : "r"(a0), "r"(a1), "r"(a2), "r"(a3), "r"(b0), "r"(b1))

__device__ __forceinline__ void split_bf16(float x, __nv_bfloat16& h, __nv_bfloat16& l) {
    h = __float2bfloat16(x);
    l = __float2bfloat16(x - __bfloat162float(h));
}
__device__ __forceinline__ uint32_t packbf(float a, float b) {
    __nv_bfloat162 t = __floats2bfloat162_rn(a, b);
    return *(uint32_t*)&t;
}
__device__ __forceinline__ void pack_split(float v0, float v1, uint32_t& hw, uint32_t& lw) {
    __nv_bfloat16 h0, l0, h1, l1;
    split_bf16(v0, h0, l0); split_bf16(v1, h1, l1);
    hw = packbf(__bfloat162float(h0), __bfloat162float(h1));
    lw = packbf(__bfloat162float(l0), __bfloat162float(l1));
}

// ===========================================================================
__device__ __forceinline__ float blockReduceSum256(float v, float* red) {
    int lane = threadIdx.x & 31, w = threadIdx.x >> 5;
#pragma unroll
    for (int o = 16; o; o >>= 1) v += __shfl_xor_sync(0xffffffffu, v, o);
    __syncthreads();
    if (lane == 0) red[w] = v;
    __syncthreads();
    float s = 0.f;
#pragma unroll
    for (int i = 0; i < 8; i++) s += red[i];
    return s;
}

// ---- rope table ----
__global__ void rope_tbl_kernel(float2* tbl) {
    int idx = blockIdx.x * 256 + threadIdx.x;    // 8192
    int a = idx >> 4, i = idx & 15;
    float freq = exp2f(-(float)i * 0.8304820237218406f);
    float s, c;
    sincosf((float)a * freq, &s, &c);
    tbl[idx] = make_float2(c, s);
}

// ---- all weight norms in one launch (grid 1536) ----
__global__ void wnorm_all(const float* __restrict__ pv, const float* __restrict__ pg,
                          const float* __restrict__ fv, const float* __restrict__ fg,
                          const float* __restrict__ w1v, const float* __restrict__ w1g,
                          const float* __restrict__ w2v, const float* __restrict__ w2g,
                          __nv_bfloat16* __restrict__ Wqkv, __nv_bfloat16* __restrict__ Wo,
                          __nv_bfloat16* __restrict__ W1, __nv_bfloat16* __restrict__ W2) {
    __shared__ float red[8];
    int b = blockIdx.x;
    const float *v, *g; __nv_bfloat16* W; int row;
    if (b < 768)       { v = pv;  g = pg;  W = Wqkv; row = b; }
    else if (b < 1024) { v = fv;  g = fg;  W = Wo;   row = b - 768; }
    else if (b < 1280) { v = w1v; g = w1g; W = W1;   row = b - 1024; }
    else               { v = w2v; g = w2g; W = W2;   row = b - 1280; }
    size_t base = (size_t)row * 256;
    float x = v[base + threadIdx.x];
    float ss = blockReduceSum256(x * x, red);
    float w = x * g[row] * rsqrtf(ss);
    __nv_bfloat16 h, l;
    split_bf16(w, h, l);
    size_t ob = (size_t)row * 512 + threadIdx.x;
    W[ob] = h;
    W[ob + 256] = l;
}

// ---- layernorm, warp-per-token (grid 4096, 8 tokens/block) ----
__global__ __launch_bounds__(256) void ln_kernel(
    const float* __restrict__ x, const float* __restrict__ g,
    const float* __restrict__ b, __nv_bfloat16* __restrict__ y) {
    int wid = threadIdx.x >> 5, lane = threadIdx.x & 31;
    int t = blockIdx.x * 8 + wid;
    const float4* xr = (const float4*)(x + (size_t)t * 256);
    float4 v0 = xr[lane];
    float4 v1 = xr[lane + 32];
    float s = v0.x + v0.y + v0.z + v0.w + v1.x + v1.y + v1.z + v1.w;
#pragma unroll
    for (int o = 16; o; o >>= 1) s += __shfl_xor_sync(0xffffffffu, s, o);
    float mean = s * (1.f / 256.f);
    float d0 = v0.x - mean, d1 = v0.y - mean, d2 = v0.z - mean, d3 = v0.w - mean;
    float d4 = v1.x - mean, d5 = v1.y - mean, d6 = v1.z - mean, d7 = v1.w - mean;
    float vv = d0*d0 + d1*d1 + d2*d2 + d3*d3 + d4*d4 + d5*d5 + d6*d6 + d7*d7;
#pragma unroll
    for (int o = 16; o; o >>= 1) vv += __shfl_xor_sync(0xffffffffu, vv, o);
    float inv = rsqrtf(vv * (1.f / 256.f) + 1e-5f);
    float4 g0 = *(const float4*)(g + lane * 4);
    float4 g1 = *(const float4*)(g + 128 + lane * 4);
    float4 b0 = *(const float4*)(b + lane * 4);
    float4 b1 = *(const float4*)(b + 128 + lane * 4);
    float o0 = d0 * inv * g0.x + b0.x, o1 = d1 * inv * g0.y + b0.y;
    float o2 = d2 * inv * g0.z + b0.z, o3 = d3 * inv * g0.w + b0.w;
    float o4 = d4 * inv * g1.x + b1.x, o5 = d5 * inv * g1.y + b1.y;
    float o6 = d6 * inv * g1.z + b1.z, o7 = d7 * inv * g1.w + b1.w;
    uint32_t hw0, lw0, hw1, lw1;
    __nv_bfloat16* yt = y + (size_t)t * 512;
    pack_split(o0, o1, hw0, lw0); pack_split(o2, o3, hw1, lw1);
    *(uint2*)(yt + lane * 4) = make_uint2(hw0, hw1);
    *(uint2*)(yt + 256 + lane * 4) = make_uint2(lw0, lw1);
    pack_split(o4, o5, hw0, lw0); pack_split(o6, o7, hw1, lw1);
    *(uint2*)(yt + 128 + lane * 4) = make_uint2(hw0, hw1);
    *(uint2*)(yt + 256 + 128 + lane * 4) = make_uint2(lw0, lw1);
}

// ===========================================================================
// mma.sync bf16 GEMM (split-3 packed K'=768). 8 warps, 2(M)x4(N), tile 64x32.
// 3-stage cp.async ring, single __syncthreads per chunk.
// mode: 2 bias+residual fp32, 3 qkv: bias+rope -> split Q/K/V
// ===========================================================================
#define ROWP 72
#define STG_BYTES (2 * 128 * ROWP * 2)   // A+B per stage = 36864
#define GEMM_SMEM (3 * STG_BYTES)        // 110592
// log2(e)/sqrt(32): fold softmax base-2 conversion into Q scaling
#define SCQE 0.2550348637156874f

__global__ __launch_bounds__(256) void gemm_mma(
    const __nv_bfloat16* __restrict__ Ap, const __nv_bfloat16* __restrict__ Wp,
    const float* __restrict__ bias, const float* __restrict__ res,
    float* __restrict__ Cf,
    const float2* __restrict__ rtbl,
    __nv_bfloat16* __restrict__ Oq, __nv_bfloat16* __restrict__ Ok,
    __nv_bfloat16* __restrict__ Ov,
    int N, int mode)
{
    extern __shared__ char dsm[];
    int tid = threadIdx.x, wid = tid >> 5, lane = tid & 31;
    int bm = blockIdx.y * 128, bn = blockIdx.x * 128;
    int wm = (wid & 1) * 64, wn = (wid >> 1) * 32;

    uint32_t sbase = smem_u32(dsm);
    int ldr = tid >> 3;
    int ldc = (tid & 7) * 8;

    float acc[4][4][4];
#pragma unroll
    for (int mi = 0; mi < 4; mi++)
#pragma unroll
        for (int ni = 0; ni < 4; ni++)
#pragma unroll
            for (int e = 0; e < 4; e++) acc[mi][ni][e] = 0.f;

    auto issue_loads = [&](int c) {
        int seg = c >> 2;
        int kg = (c & 3) * 64;
        int aoff = (seg == 2) ? 256 + kg : kg;
        int boff = (seg == 1) ? 256 + kg : kg;
        uint32_t st = sbase + (c % 3) * STG_BYTES;
#pragma unroll
        for (int i = 0; i < 4; i++) {
            int r = ldr + i * 32;
            CP_ASYNC16(st + r * 144 + ldc * 2,
                       Ap + (size_t)(bm + r) * 512 + aoff + ldc);
        }
        uint32_t stB = st + 128 * 144;
#pragma unroll
        for (int i = 0; i < 4; i++) {
            int r = ldr + i * 32;
            CP_ASYNC16(stB + r * 144 + ldc * 2,
                       Wp + (size_t)(bn + r) * 512 + boff + ldc);
        }
        CP_COMMIT();
    };

    issue_loads(0);
    issue_loads(1);
    CP_WAIT(1);
    __syncthreads();

    for (int c = 0; c < 12; c++) {
        uint32_t stA = sbase + (c % 3) * STG_BYTES;
        uint32_t stB = stA + 128 * 144;
#pragma unroll
        for (int kk = 0; kk < 4; kk++) {
            uint32_t a[4][4], b[2][4];
#pragma unroll
            for (int mi = 0; mi < 4; mi++) {
                uint32_t ad = stA + (wm + mi * 16 + (lane & 15)) * 144
                            + (kk * 16 + (lane >> 4) * 8) * 2;
                LDSM_X4(a[mi][0], a[mi][1], a[mi][2], a[mi][3], ad);
            }
#pragma unroll
            for (int nb = 0; nb < 2; nb++) {
                int nrow = wn + nb * 16 + ((lane >> 4) << 3) + (lane & 7);
                int koff = ((lane >> 3) & 1) * 8;
                uint32_t bd = stB + nrow * 144 + (kk * 16 + koff) * 2;
                LDSM_X4(b[nb][0], b[nb][1], b[nb][2], b[nb][3], bd);
            }
#pragma unroll
            for (int mi = 0; mi < 4; mi++) {
#pragma unroll
                for (int nb = 0; nb < 2; nb++) {
                    MMA16816(acc[mi][nb * 2 + 0], a[mi][0], a[mi][1], a[mi][2], a[mi][3],
                             b[nb][0], b[nb][1]);
                    MMA16816(acc[mi][nb * 2 + 1], a[mi][0], a[mi][1], a[mi][2], a[mi][3],
                             b[nb][2], b[nb][3]);
                }
            }
        }
        if (c + 2 < 12) { issue_loads(c + 2); CP_WAIT(1); __syncthreads(); }
        else if (c + 1 < 12) { CP_WAIT(0); __syncthreads(); }
    }

    int cg = (lane & 3) * 2;
    int rg = lane >> 2;
#pragma unroll
    for (int ni = 0; ni < 4; ni++) {
        int c0 = bn + wn + ni * 8 + cg;
        float2 b2 = *(const float2*)(bias + c0);
#pragma unroll
        for (int mi = 0; mi < 4; mi++) {
            int r0 = bm + wm + mi * 16 + rg;
#pragma unroll
            for (int h = 0; h < 2; h++) {
                int r = r0 + h * 8;
                float v0 = acc[mi][ni][h * 2 + 0] + b2.x;
                float v1 = acc[mi][ni][h * 2 + 1] + b2.y;
                if (mode == 2) {
                    float2 rr = *(const float2*)(res + (size_t)r * N + c0);
                    *(float2*)(Cf + (size_t)r * N + c0) =
                        make_float2(v0 + rr.x, v1 + rr.y);
                } else {
                    int hh = c0 / 96;
                    int rem = c0 - hh * 96;
                    int type = rem >> 5;        // 0=q 1=k 2=v
                    int i2 = rem & 31;
                    int a = r & 511;
                    int bh = ((r >> 9) << 3) + hh;
                    size_t ob = ((size_t)bh * 512 + a) * 64 + i2;
                    uint32_t hw, lw;
                    if (type == 2) {
                        pack_split(v0, v1, hw, lw);
                        *(uint32_t*)(Ov + ob) = hw;
                        *(uint32_t*)(Ov + ob + 32) = lw;
                    } else {
                        float2 cs = rtbl[a * 16 + (i2 >> 1)];
                        float q0 = v0 * cs.x - v1 * cs.y;
                        float q1 = v1 * cs.x + v0 * cs.y;
                        if (type == 0) { q0 *= SCQE; q1 *= SCQE; }
                        pack_split(q0, q1, hw, lw);
                        __nv_bfloat16* O = (type == 0) ? Oq : Ok;
                        *(uint32_t*)(O + ob) = hw;
                        *(uint32_t*)(O + ob + 32) = lw;
                    }
                }
            }
        }
    }
}

// ===========================================================================
// Fused Wo + residual + LN2 (R15-validated, unchanged)
// ===========================================================================
#define WOLN_STG ((128 + 256) * 144)        // 55296 per stage
#define WOLN_SMEM (3 * WOLN_STG)            // 165888

__global__ __launch_bounds__(512, 1) void gemm_wo_ln(
    const __nv_bfloat16* __restrict__ Ap, const __nv_bfloat16* __restrict__ Wp,
    const float* __restrict__ bias, const float* __restrict__ res,
    float* __restrict__ out,
    const float* __restrict__ lng, const float* __restrict__ lnb,
    __nv_bfloat16* __restrict__ zln)
{
    extern __shared__ char dsm[];
    uint32_t sbase = smem_u32(dsm);
    float* mid = (float*)dsm;               // [128][264] fp32, aliases stages
    int tid = threadIdx.x, wid = tid >> 5, lane = tid & 31;
    int bm = blockIdx.x * 128;
    int wm = (wid & 1) * 64, wn = (wid >> 1) * 32;

    int ldr = tid >> 3;          // 0..63
    int ldc = (tid & 7) * 8;
    int lg8 = ((lane >> 4) << 3) + (lane & 7);
    int koff = ((lane >> 3) & 1) * 8;
    int cg = (lane & 3) * 2;
    int rg = lane >> 2;

    float acc[4][4][4];
#pragma unroll
    for (int mi = 0; mi < 4; mi++)
#pragma unroll
        for (int ni = 0; ni < 4; ni++)
#pragma unroll
            for (int e = 0; e < 4; e++) acc[mi][ni][e] = 0.f;

    auto issue_loads = [&](int c) {
        int seg = c >> 2;
        int kg = (c & 3) * 64;
        int aoff = (seg == 2) ? 256 + kg : kg;
        int boff = (seg == 1) ? 256 + kg : kg;
        uint32_t st = sbase + (c % 3) * WOLN_STG;
#pragma unroll
        for (int i = 0; i < 2; i++) {
            int r = ldr + i * 64;
            CP_ASYNC16(st + r * 144 + ldc * 2,
                       Ap + (size_t)(bm + r) * 512 + aoff + ldc);
        }
        uint32_t stB = st + 128 * 144;
#pragma unroll
        for (int i = 0; i < 4; i++) {
            int r = ldr + i * 64;
            CP_ASYNC16(stB + r * 144 + ldc * 2,
                       Wp + (size_t)r * 512 + boff + ldc);
        }
        CP_COMMIT();
    };

    issue_loads(0);
    issue_loads(1);
    CP_WAIT(1);
    __syncthreads();

    for (int c = 0; c < 12; c++) {
        uint32_t stA = sbase + (c % 3) * WOLN_STG;
        uint32_t stB = stA + 128 * 144;
#pragma unroll
        for (int kk = 0; kk < 4; kk++) {
            uint32_t a[4][4], b[2][4];
#pragma unroll
            for (int mi = 0; mi < 4; mi++) {
                uint32_t ad = stA + (wm + mi * 16 + (lane & 15)) * 144
                            + (kk * 16 + (lane >> 4) * 8) * 2;
                LDSM_X4(a[mi][0], a[mi][1], a[mi][2], a[mi][3], ad);
            }
#pragma unroll
            for (int nb = 0; nb < 2; nb++) {
                int nrow = wn + nb * 16 + lg8;
                uint32_t bd = stB + nrow * 144 + (kk * 16 + koff) * 2;
                LDSM_X4(b[nb][0], b[nb][1], b[nb][2], b[nb][3], bd);
            }
#pragma unroll
            for (int mi = 0; mi < 4; mi++) {
#pragma unroll
                for (int nb = 0; nb < 2; nb++) {
                    MMA16816(acc[mi][nb * 2 + 0], a[mi][0], a[mi][1], a[mi][2], a[mi][3],
                             b[nb][0], b[nb][1]);
                    MMA16816(acc[mi][nb * 2 + 1], a[mi][0], a[mi][1], a[mi][2], a[mi][3],
                             b[nb][2], b[nb][3]);
                }
            }
        }
        if (c + 2 < 12) { issue_loads(c + 2); CP_WAIT(1); __syncthreads(); }
        else if (c + 1 < 12) { CP_WAIT(0); __syncthreads(); }
    }
    __syncthreads();

#pragma unroll
    for (int ni = 0; ni < 4; ni++) {
        int c0 = wn + ni * 8 + cg;
        float2 bb = *(const float2*)(bias + c0);
#pragma unroll
        for (int mi = 0; mi < 4; mi++) {
#pragma unroll
            for (int h = 0; h < 2; h++) {
                int r = wm + mi * 16 + rg + h * 8;
                int gr = bm + r;
                float2 rr = *(const float2*)(res + (size_t)gr * 256 + c0);
                float v0 = acc[mi][ni][h * 2 + 0] + bb.x + rr.x;
                float v1 = acc[mi][ni][h * 2 + 1] + bb.y + rr.y;
                *(float2*)(out + (size_t)gr * 256 + c0) = make_float2(v0, v1);
                *(float2*)(mid + r * 264 + c0) = make_float2(v0, v1);
            }
        }
    }
    __syncthreads();

#pragma unroll
    for (int i = 0; i < 8; i++) {
        int r = wid * 8 + i;
        const float4* xr = (const float4*)(mid + r * 264);
        float4 v0 = xr[lane];
        float4 v1 = xr[lane + 32];
        float s = v0.x + v0.y + v0.z + v0.w + v1.x + v1.y + v1.z + v1.w;
#pragma unroll
        for (int o = 16; o; o >>= 1) s += __shfl_xor_sync(0xffffffffu, s, o);
        float mean = s * (1.f / 256.f);
        float d0 = v0.x - mean, d1 = v0.y - mean, d2 = v0.z - mean, d3 = v0.w - mean;
        float d4 = v1.x - mean, d5 = v1.y - mean, d6 = v1.z - mean, d7 = v1.w - mean;
        float vv = d0*d0 + d1*d1 + d2*d2 + d3*d3 + d4*d4 + d5*d5 + d6*d6 + d7*d7;
#pragma unroll
        for (int o = 16; o; o >>= 1) vv += __shfl_xor_sync(0xffffffffu, vv, o);
        float inv = rsqrtf(vv * (1.f / 256.f) + 1e-5f);
        float4 g0 = *(const float4*)(lng + lane * 4);
        float4 g1 = *(const float4*)(lng + 128 + lane * 4);
        float4 b0 = *(const float4*)(lnb + lane * 4);
        float4 b1 = *(const float4*)(lnb + 128 + lane * 4);
        float o0 = d0 * inv * g0.x + b0.x, o1 = d1 * inv * g0.y + b0.y;
        float o2 = d2 * inv * g0.z + b0.z, o3 = d3 * inv * g0.w + b0.w;
        float o4 = d4 * inv * g1.x + b1.x, o5 = d5 * inv * g1.y + b1.y;
        float o6 = d6 * inv * g1.z + b1.z, o7 = d7 * inv * g1.w + b1.w;
        uint32_t hw0, lw0, hw1, lw1;
        __nv_bfloat16* yt = zln + (size_t)(bm + r) * 512;
        pack_split(o0, o1, hw0, lw0); pack_split(o2, o3, hw1, lw1);
        *(uint2*)(yt + lane * 4) = make_uint2(hw0, hw1);
        *(uint2*)(yt + 256 + lane * 4) = make_uint2(lw0, lw1);
        pack_split(o4, o5, hw0, lw0); pack_split(o6, o7, hw1, lw1);
        *(uint2*)(yt + 128 + lane * 4) = make_uint2(hw0, hw1);
        *(uint2*)(yt + 256 + 128 + lane * 4) = make_uint2(lw0, lw1);
    }
}

// ===========================================================================
// Fused MLP (R12-validated, unchanged)
// ===========================================================================
#define MLP_STG 36864
#define MLP_P1STG (18432 + 36864)
#define MLP_H1 133120
#define MLP_SMEM (MLP_H1 + 2 * MLP_STG)

__global__ __launch_bounds__(512, 1) void gemm_mlp(
    const __nv_bfloat16* __restrict__ Ap, const __nv_bfloat16* __restrict__ W1p,
    const __nv_bfloat16* __restrict__ W2p,
    const float* __restrict__ b1, const float* __restrict__ b2,
    float* __restrict__ out)
{
    extern __shared__ char dsm[];
    uint32_t sbase = smem_u32(dsm);
    uint32_t h1b = sbase;
    uint32_t w2b = sbase + MLP_H1;
    int tid = threadIdx.x, wid = tid >> 5, lane = tid & 31;
    int bm = blockIdx.x * 128;
    int wm = (wid & 1) * 64, wn = (wid >> 1) * 32;

    int ldr = tid >> 3;
    int ldc = (tid & 7) * 8;
    int lg8 = ((lane >> 4) << 3) + (lane & 7);
    int koff = ((lane >> 3) & 1) * 8;
    int cg = (lane & 3) * 2;
    int rg = lane >> 2;

    {
        float acc[4][4][4];
#pragma unroll
        for (int mi = 0; mi < 4; mi++)
#pragma unroll
            for (int ni = 0; ni < 4; ni++)
#pragma unroll
                for (int e = 0; e < 4; e++) acc[mi][ni][e] = 0.f;

        auto issue1 = [&](int c) {
            int seg = c >> 2;
            int kg = (c & 3) * 64;
            int aoff = (seg == 2) ? 256 + kg : kg;
            int boff = (seg == 1) ? 256 + kg : kg;
            uint32_t st = sbase + (c & 1) * MLP_P1STG;
#pragma unroll
            for (int i = 0; i < 2; i++) {
                int r = ldr + i * 64;
                CP_ASYNC16(st + r * 144 + ldc * 2,
                           Ap + (size_t)(bm + r) * 512 + aoff + ldc);
            }
            uint32_t stB = st + 128 * 144;
#pragma unroll
            for (int i = 0; i < 4; i++) {
                int r = ldr + i * 64;
                CP_ASYNC16(stB + r * 144 + ldc * 2,
                           W1p + (size_t)r * 512 + boff + ldc);
            }
            CP_COMMIT();
        };

        issue1(0);
        for (int c = 0; c < 12; c++) {
            if (c + 1 < 12) { issue1(c + 1); CP_WAIT(1); } else { CP_WAIT(0); }
            __syncthreads();
            uint32_t stA = sbase + (c & 1) * MLP_P1STG;
            uint32_t stB = stA + 128 * 144;
#pragma unroll
            for (int kk = 0; kk < 4; kk++) {
                uint32_t a[4][4], b[2][4];
#pragma unroll
                for (int mi = 0; mi < 4; mi++) {
                    uint32_t ad = stA + (wm + mi * 16 + (lane & 15)) * 144
                                + (kk * 16 + (lane >> 4) * 8) * 2;
                    LDSM_X4(a[mi][0], a[mi][1], a[mi][2], a[mi][3], ad);
                }
#pragma unroll
                for (int nb = 0; nb < 2; nb++) {
                    int nrow = wn + nb * 16 + lg8;
                    uint32_t bd = stB + nrow * 144 + (kk * 16 + koff) * 2;
                    LDSM_X4(b[nb][0], b[nb][1], b[nb][2], b[nb][3], bd);
                }
#pragma unroll
                for (int mi = 0; mi < 4; mi++) {
#pragma unroll
                    for (int nb = 0; nb < 2; nb++) {
                        MMA16816(acc[mi][nb * 2 + 0], a[mi][0], a[mi][1], a[mi][2], a[mi][3],
                                 b[nb][0], b[nb][1]);
                        MMA16816(acc[mi][nb * 2 + 1], a[mi][0], a[mi][1], a[mi][2], a[mi][3],
                                 b[nb][2], b[nb][3]);
                    }
                }
            }
            __syncthreads();
        }

        {
            uint32_t st = w2b;
#pragma unroll
            for (int i = 0; i < 4; i++) {
                int r = ldr + i * 64;
                CP_ASYNC16(st + r * 144 + ldc * 2,
                           W2p + (size_t)r * 512 + ldc);
            }
            CP_COMMIT();
        }

#pragma unroll
        for (int ni = 0; ni < 4; ni++) {
            int c0 = wn + ni * 8 + cg;
            float2 bb = *(const float2*)(b1 + c0);
#pragma unroll
            for (int mi = 0; mi < 4; mi++) {
#pragma unroll
                for (int h = 0; h < 2; h++) {
                    int r = wm + mi * 16 + rg + h * 8;
                    float v0 = acc[mi][ni][h * 2 + 0] + bb.x;
                    float v1 = acc[mi][ni][h * 2 + 1] + bb.y;
                    v0 = 0.5f * v0 * (1.f + erff(v0 * 0.7071067811865476f));
                    v1 = 0.5f * v1 * (1.f + erff(v1 * 0.7071067811865476f));
                    uint32_t hw, lw;
                    pack_split(v0, v1, hw, lw);
                    *(uint32_t*)(dsm + r * 1040 + c0 * 2) = hw;
                    *(uint32_t*)(dsm + r * 1040 + (256 + c0) * 2) = lw;
                }
            }
        }
    }
    __syncthreads();

    float acc[4][4][4];
#pragma unroll
    for (int mi = 0; mi < 4; mi++)
#pragma unroll
        for (int ni = 0; ni < 4; ni++)
#pragma unroll
            for (int e = 0; e < 4; e++) acc[mi][ni][e] = 0.f;

    auto issue2 = [&](int c) {
        int seg = c >> 2;
        int kg = (c & 3) * 64;
        int boff = (seg == 1) ? 256 + kg : kg;
        uint32_t st = w2b + (c & 1) * MLP_STG;
#pragma unroll
        for (int i = 0; i < 4; i++) {
            int r = ldr + i * 64;
            CP_ASYNC16(st + r * 144 + ldc * 2,
                       W2p + (size_t)r * 512 + boff + ldc);
        }
        CP_COMMIT();
    };

    for (int c = 0; c < 12; c++) {
        if (c + 1 < 12) { issue2(c + 1); CP_WAIT(1); } else { CP_WAIT(0); }
        __syncthreads();

        int seg = c >> 2;
        int kg = (c & 3) * 64;
        int aoff = (seg == 2) ? 256 + kg : kg;
        uint32_t stB = w2b + (c & 1) * MLP_STG;
#pragma unroll
        for (int kk = 0; kk < 4; kk++) {
            uint32_t a[4][4], b[2][4];
#pragma unroll
            for (int mi = 0; mi < 4; mi++) {
                uint32_t ad = h1b + (wm + mi * 16 + (lane & 15)) * 1040
                            + (aoff + kk * 16 + (lane >> 4) * 8) * 2;
                LDSM_X4(a[mi][0], a[mi][1], a[mi][2], a[mi][3], ad);
            }
#pragma unroll
            for (int nb = 0; nb < 2; nb++) {
                int nrow = wn + nb * 16 + lg8;
                uint32_t bd = stB + nrow * 144 + (kk * 16 + koff) * 2;
                LDSM_X4(b[nb][0], b[nb][1], b[nb][2], b[nb][3], bd);
            }
#pragma unroll
            for (int mi = 0; mi < 4; mi++) {
#pragma unroll
                for (int nb = 0; nb < 2; nb++) {
                    MMA16816(acc[mi][nb * 2 + 0], a[mi][0], a[mi][1], a[mi][2], a[mi][3],
                             b[nb][0], b[nb][1]);
                    MMA16816(acc[mi][nb * 2 + 1], a[mi][0], a[mi][1], a[mi][2], a[mi][3],
                             b[nb][2], b[nb][3]);
                }
            }
        }
        __syncthreads();
    }

#pragma unroll
    for (int ni = 0; ni < 4; ni++) {
        int c0 = wn + ni * 8 + cg;
        float2 bb = *(const float2*)(b2 + c0);
#pragma unroll
        for (int mi = 0; mi < 4; mi++) {
#pragma unroll
            for (int h = 0; h < 2; h++) {
                int r = bm + wm + mi * 16 + rg + h * 8;
                float v0 = acc[mi][ni][h * 2 + 0] + bb.x;
                float v1 = acc[mi][ni][h * 2 + 1] + bb.y;
                float2 rr = *(const float2*)(out + (size_t)r * 256 + c0);
                *(float2*)(out + (size_t)r * 256 + c0) =
                    make_float2(v0 + rr.x, v1 + rr.y);
            }
        }
    }
}

// ---------------------------------------------------------------------------
// Attention v3: grid 1024 = (bh, q-half). 256 q rows/CTA, 8 warps x 32 rows.
// Q-fragments hoisted out of kv loop (loop-invariant). Max-free base-2 softmax.
// ---------------------------------------------------------------------------
#define ATT3_SMEM (36864 + 73728 + 73728)   // Q-half + K + V = 184320

__global__ __launch_bounds__(256) void attn_mma(
    const __nv_bfloat16* __restrict__ Qs, const __nv_bfloat16* __restrict__ Ks,
    const __nv_bfloat16* __restrict__ Vs, __nv_bfloat16* __restrict__ Op)
{
    extern __shared__ char sm[];
    uint32_t sQ = smem_u32(sm);
    uint32_t sK = sQ + 36864;
    uint32_t sV = sQ + 110592;
    int bh = blockIdx.x >> 1;
    int qh = (blockIdx.x & 1) * 256;
    int tid = threadIdx.x, wid = tid >> 5, lane = tid & 31;

    const __nv_bfloat16* qg = Qs + ((size_t)bh * 512 + qh) * 64;
    const __nv_bfloat16* kg = Ks + (size_t)bh * 512 * 64;
    const __nv_bfloat16* vg = Vs + (size_t)bh * 512 * 64;
    for (int idx = tid; idx < 4096; idx += 256) {
        int r = idx >> 3, c = idx & 7;
        CP_ASYNC16(sK + r * 144 + c * 16, kg + r * 64 + c * 8);
        CP_ASYNC16(sV + r * 144 + c * 16, vg + r * 64 + c * 8);
        if (idx < 2048)
            CP_ASYNC16(sQ + r * 144 + c * 16, qg + r * 64 + c * 8);
    }
    CP_COMMIT(); CP_WAIT(0);
    __syncthreads();

    int wm = wid * 32;
    // hoisted Q fragments: [mi][kq][4]
    uint32_t aQ[2][4][4];
#pragma unroll
    for (int mi = 0; mi < 2; mi++)
#pragma unroll
        for (int kq = 0; kq < 4; kq++) {
            uint32_t ad = sQ + (wm + mi * 16 + (lane & 15)) * 144
                        + kq * 32 + (lane >> 4) * 16;
            LDSM_X4(aQ[mi][kq][0], aQ[mi][kq][1], aQ[mi][kq][2], aQ[mi][kq][3], ad);
        }

    float acc[2][4][4];
    float lst[2][2];
#pragma unroll
    for (int mi = 0; mi < 2; mi++) {
        lst[mi][0] = 0.f; lst[mi][1] = 0.f;
#pragma unroll
        for (int jv = 0; jv < 4; jv++)
#pragma unroll
            for (int e = 0; e < 4; e++) acc[mi][jv][e] = 0.f;
    }

    int lg8 = ((lane >> 4) << 3) + (lane & 7);
    int lk8 = ((lane >> 3) & 1) * 16;
    int vrow = ((lane >> 3) & 1) * 8 + (lane & 7);
    int vcb = (lane >> 4) * 16;

    for (int kt = 0; kt < 16; kt++) {
        int kvb = kt * 32;

        uint32_t bK[4][4][2];
#pragma unroll
        for (int g16 = 0; g16 < 2; g16++)
#pragma unroll
            for (int kq = 0; kq < 4; kq++) {
                uint32_t ad = sK + (kvb + g16 * 16 + lg8) * 144 + kq * 32 + lk8;
                uint32_t r0, r1, r2, r3;
                LDSM_X4(r0, r1, r2, r3, ad);
                bK[g16 * 2][kq][0] = r0;     bK[g16 * 2][kq][1] = r1;
                bK[g16 * 2 + 1][kq][0] = r2; bK[g16 * 2 + 1][kq][1] = r3;
            }
        uint32_t bVh[4][2][2], bVl[4][2][2];
#pragma unroll
        for (int ks = 0; ks < 2; ks++) {
            uint32_t ad = sV + (kvb + ks * 16 + vrow) * 144 + vcb;
            uint32_t r0, r1, r2, r3;
            LDSM_X4_T(r0, r1, r2, r3, ad);
            bVh[0][ks][0] = r0; bVh[0][ks][1] = r1;
            bVh[1][ks][0] = r2; bVh[1][ks][1] = r3;
            LDSM_X4_T(r0, r1, r2, r3, ad + 32);
            bVh[2][ks][0] = r0; bVh[2][ks][1] = r1;
            bVh[3][ks][0] = r2; bVh[3][ks][1] = r3;
            LDSM_X4_T(r0, r1, r2, r3, ad + 64);
            bVl[0][ks][0] = r0; bVl[0][ks][1] = r1;
            bVl[1][ks][0] = r2; bVl[1][ks][1] = r3;
            LDSM_X4_T(r0, r1, r2, r3, ad + 96);
            bVl[2][ks][0] = r0; bVl[2][ks][1] = r1;
            bVl[3][ks][0] = r2; bVl[3][ks][1] = r3;
        }

#pragma unroll
        for (int mi = 0; mi < 2; mi++) {
            float s[4][4];
#pragma unroll
            for (int j = 0; j < 4; j++) {
#pragma unroll
                for (int e = 0; e < 4; e++) s[j][e] = 0.f;
                MMA16816(s[j], aQ[mi][0][0], aQ[mi][0][1], aQ[mi][0][2], aQ[mi][0][3],
                         bK[j][0][0], bK[j][0][1]);
                MMA16816(s[j], aQ[mi][1][0], aQ[mi][1][1], aQ[mi][1][2], aQ[mi][1][3],
                         bK[j][1][0], bK[j][1][1]);
                MMA16816(s[j], aQ[mi][0][0], aQ[mi][0][1], aQ[mi][0][2], aQ[mi][0][3],
                         bK[j][2][0], bK[j][2][1]);
                MMA16816(s[j], aQ[mi][1][0], aQ[mi][1][1], aQ[mi][1][2], aQ[mi][1][3],
                         bK[j][3][0], bK[j][3][1]);
                MMA16816(s[j], aQ[mi][2][0], aQ[mi][2][1], aQ[mi][2][2], aQ[mi][2][3],
                         bK[j][0][0], bK[j][0][1]);
                MMA16816(s[j], aQ[mi][3][0], aQ[mi][3][1], aQ[mi][3][2], aQ[mi][3][3],
                         bK[j][1][0], bK[j][1][1]);
            }
            float sm0 = 0.f, sm1 = 0.f;
#pragma unroll
            for (int j = 0; j < 4; j++) {
                s[j][0] = exp2f(s[j][0]); sm0 += s[j][0];
                s[j][1] = exp2f(s[j][1]); sm0 += s[j][1];
                s[j][2] = exp2f(s[j][2]); sm1 += s[j][2];
                s[j][3] = exp2f(s[j][3]); sm1 += s[j][3];
            }
            lst[mi][0] += sm0;
            lst[mi][1] += sm1;
            uint32_t aPh[2][4], aPl[2][4];
#pragma unroll
            for (int ks = 0; ks < 2; ks++) {
                int j0 = 2 * ks, j1 = 2 * ks + 1;
                aPh[ks][0] = packbf(s[j0][0], s[j0][1]);
                aPh[ks][1] = packbf(s[j0][2], s[j0][3]);
                aPh[ks][2] = packbf(s[j1][0], s[j1][1]);
                aPh[ks][3] = packbf(s[j1][2], s[j1][3]);
                __nv_bfloat162 h0 = *(__nv_bfloat162*)&aPh[ks][0];
                __nv_bfloat162 h1 = *(__nv_bfloat162*)&aPh[ks][1];
                __nv_bfloat162 h2 = *(__nv_bfloat162*)&aPh[ks][2];
                __nv_bfloat162 h3 = *(__nv_bfloat162*)&aPh[ks][3];
                aPl[ks][0] = packbf(s[j0][0] - __bfloat162float(h0.x),
                                    s[j0][1] - __bfloat162float(h0.y));
                aPl[ks][1] = packbf(s[j0][2] - __bfloat162float(h1.x),
                                    s[j0][3] - __bfloat162float(h1.y));
                aPl[ks][2] = packbf(s[j1][0] - __bfloat162float(h2.x),
                                    s[j1][1] - __bfloat162float(h2.y));
                aPl[ks][3] = packbf(s[j1][2] - __bfloat162float(h3.x),
                                    s[j1][3] - __bfloat162float(h3.y));
            }
#pragma unroll
            for (int jv = 0; jv < 4; jv++) {
                MMA16816(acc[mi][jv], aPh[0][0], aPh[0][1], aPh[0][2], aPh[0][3],
                         bVh[jv][0][0], bVh[jv][0][1]);
                MMA16816(acc[mi][jv], aPh[1][0], aPh[1][1], aPh[1][2], aPh[1][3],
                         bVh[jv][1][0], bVh[jv][1][1]);
                MMA16816(acc[mi][jv], aPh[0][0], aPh[0][1], aPh[0][2], aPh[0][3],
                         bVl[jv][0][0], bVl[jv][0][1]);
                MMA16816(acc[mi][jv], aPh[1][0], aPh[1][1], aPh[1][2], aPh[1][3],
                         bVl[jv][1][0], bVl[jv][1][1]);
                MMA16816(acc[mi][jv], aPl[0][0], aPl[0][1], aPl[0][2], aPl[0][3],
                         bVh[jv][0][0], bVh[jv][0][1]);
                MMA16816(acc[mi][jv], aPl[1][0], aPl[1][1], aPl[1][2], aPl[1][3],
                         bVh[jv][1][0], bVh[jv][1][1]);
            }
        }
    }

#pragma unroll
    for (int mi = 0; mi < 2; mi++) {
        lst[mi][0] += __shfl_xor_sync(0xffffffffu, lst[mi][0], 1);
        lst[mi][0] += __shfl_xor_sync(0xffffffffu, lst[mi][0], 2);
        lst[mi][1] += __shfl_xor_sync(0xffffffffu, lst[mi][1], 1);
        lst[mi][1] += __shfl_xor_sync(0xffffffffu, lst[mi][1], 2);
    }

    int tb = (bh >> 3) * 512 + qh;
    int cb = (bh & 7) * 32;
#pragma unroll
    for (int mi = 0; mi < 2; mi++) {
        float i0 = 1.f / lst[mi][0];
        float i1 = 1.f / lst[mi][1];
        int r0 = wm + mi * 16 + (lane >> 2);
#pragma unroll
        for (int jv = 0; jv < 4; jv++) {
            int col = cb + jv * 8 + 2 * (lane & 3);
            uint32_t hw, lw;
            pack_split(acc[mi][jv][0] * i0, acc[mi][jv][1] * i0, hw, lw);
            size_t ob = (size_t)(tb + r0) * 512 + col;
            *(uint32_t*)(Op + ob) = hw;
            *(uint32_t*)(Op + ob + 256) = lw;
            pack_split(acc[mi][jv][2] * i1, acc[mi][jv][3] * i1, hw, lw);
            ob = (size_t)(tb + r0 + 8) * 512 + col;
            *(uint32_t*)(Op + ob) = hw;
            *(uint32_t*)(Op + ob + 256) = lw;
        }
    }
}

// ---------------------------------------------------------------------------
extern "C" void kernel_launch(void* const* d_in, const int* in_sizes, int n_in,
                              void* d_out, int out_size) {
    const float* z      = (const float*)d_in[0];
    const float* ln1_g  = (const float*)d_in[1];
    const float* ln1_b  = (const float*)d_in[2];
    const float* proj_v = (const float*)d_in[3];
    const float* proj_g = (const float*)d_in[4];
    const float* proj_b = (const float*)d_in[5];
    const float* ff_v   = (const float*)d_in[6];
    const float* ff_g   = (const float*)d_in[7];
    const float* ff_b   = (const float*)d_in[8];
    const float* ln2_g  = (const float*)d_in[9];
    const float* ln2_b  = (const float*)d_in[10];
    const float* w1_v   = (const float*)d_in[11];
    const float* w1_g   = (const float*)d_in[12];
    const float* w1_b   = (const float*)d_in[13];
    const float* w2_v   = (const float*)d_in[14];
    const float* w2_g   = (const float*)d_in[15];
    const float* w2_b   = (const float*)d_in[16];
    float* out = (float*)d_out;

    void *pWqkv, *pWo, *pW1, *pW2, *pzln, *pqs, *pks, *pvs, *patt, *ptbl;
    cudaGetSymbolAddress(&pWqkv, g_Wqkv);
    cudaGetSymbolAddress(&pWo, g_Wo);
    cudaGetSymbolAddress(&pW1, g_W1);
    cudaGetSymbolAddress(&pW2, g_W2);
    cudaGetSymbolAddress(&pzln, g_zln);
    cudaGetSymbolAddress(&pqs, g_qs);
    cudaGetSymbolAddress(&pks, g_ks);
    cudaGetSymbolAddress(&pvs, g_vs);
    cudaGetSymbolAddress(&patt, g_att);
    cudaGetSymbolAddress(&ptbl, g_rtbl);

    cudaFuncSetAttribute(gemm_mma, cudaFuncAttributeMaxDynamicSharedMemorySize, GEMM_SMEM);
    cudaFuncSetAttribute(gemm_wo_ln, cudaFuncAttributeMaxDynamicSharedMemorySize, WOLN_SMEM);
    cudaFuncSetAttribute(gemm_mlp, cudaFuncAttributeMaxDynamicSharedMemorySize, MLP_SMEM);
    cudaFuncSetAttribute(attn_mma, cudaFuncAttributeMaxDynamicSharedMemorySize, ATT3_SMEM);

    // 0) rope table
    rope_tbl_kernel<<<32, 256>>>((float2*)ptbl);

    // 1) all weight norms
    wnorm_all<<<1536, 256>>>(proj_v, proj_g, ff_v, ff_g, w1_v, w1_g, w2_v, w2_g,
                             (__nv_bfloat16*)pWqkv, (__nv_bfloat16*)pWo,
                             (__nv_bfloat16*)pW1, (__nv_bfloat16*)pW2);

    // 2) LN1 -> packed bf16 (warp-per-token)
    ln_kernel<<<4096, 256>>>(z, ln1_g, ln1_b, (__nv_bfloat16*)pzln);

    // 3) QKV projection with fused bias+RoPE+split scatter (Q scaled by log2e/sqrt(32))
    gemm_mma<<<dim3(6, 256), 256, GEMM_SMEM>>>(
        (const __nv_bfloat16*)pzln, (const __nv_bfloat16*)pWqkv,
        proj_b, nullptr, nullptr,
        (const float2*)ptbl, (__nv_bfloat16*)pqs, (__nv_bfloat16*)pks,
        (__nv_bfloat16*)pvs, 768, 3);

    // 4) attention v3 (2 CTAs per bh, hoisted Q frags) -> packed bf16
    attn_mma<<<1024, 256, ATT3_SMEM>>>(
        (const __nv_bfloat16*)pqs, (const __nv_bfloat16*)pks,
        (const __nv_bfloat16*)pvs, (__nv_bfloat16*)patt);

    // 5) fused Wo + residual z + LN2 -> out (fp32) and zln (packed bf16)
    gemm_wo_ln<<<256, 512, WOLN_SMEM>>>(
        (const __nv_bfloat16*)patt, (const __nv_bfloat16*)pWo,
        ff_b, z, out, ln2_g, ln2_b, (__nv_bfloat16*)pzln);

    // 6) fused MLP: out += gelu(zln@W1^T+b1)@W2^T + b2
    gemm_mlp<<<256, 512, MLP_SMEM>>>(
        (const __nv_bfloat16*)pzln, (const __nv_bfloat16*)pW1,
        (const __nv_bfloat16*)pW2, w1_b, w2_b, out);
}

// round 17
// speedup vs baseline: 1.4763x; 1.1597x over previous
#include <cuda_runtime.h>
#include <cuda_bf16.h>
#include <cuda_fp16.h>
#include <math.h>
#include <stdint.h>

// ---------------------------------------------------------------------------
// ResidualRoPETransformer: B=2,U=32,A=512,E=256,NH=8,HD=32, T=32768 tokens
// Round 17: linear GEMMs switch to fp16 A-split-2 x fp16-B (8 K-chunks vs 12).
// Attention stays bf16 split-3 (P range would overflow fp16).
// ---------------------------------------------------------------------------

#define T_TOK 32768
#define SEQ 512
#define HDIM 32

// ---- scratch (static device globals; no runtime allocation) ----
__device__ __half g_Wqkv[768 * 512];          // fp16, only hi(256) used per row
__device__ __half g_Wo[256 * 512];
__device__ __half g_W1[256 * 512];
__device__ __half g_W2[256 * 512];
__device__ __half g_zln[(size_t)T_TOK * 512];   // fp16 packed [hi|lo]
__device__ __half g_att[(size_t)T_TOK * 512];
__device__ __nv_bfloat16 g_qs[(size_t)512 * 512 * 64];  // bf16 [bh][a][qh|ql] (scaled)
__device__ __nv_bfloat16 g_ks[(size_t)512 * 512 * 64];
__device__ __nv_bfloat16 g_vs[(size_t)512 * 512 * 64];
__device__ float2 g_rtbl[512 * 16];

// ===========================================================================
// PTX helpers
// ===========================================================================
__device__ __forceinline__ uint32_t smem_u32(const void* p) {
    uint32_t a;
    asm("{ .reg .u64 t; cvta.to.shared.u64 t, %1; cvt.u32.u64 %0, t; }"
        : "=r"(a) : "l"(p));
    return a;
}
#define CP_ASYNC16(dst, src) \
    asm volatile("cp.async.cg.shared.global [%0], [%1], 16;" :: "r"(dst), "l"(src))
#define CP_COMMIT() asm volatile("cp.async.commit_group;" ::: "memory")
#define CP_WAIT(n)  asm volatile("cp.async.wait_group %0;" :: "n"(n) : "memory")

#define LDSM_X4(r0, r1, r2, r3, addr) \
    asm volatile("ldmatrix.sync.aligned.m8n8.x4.shared.b16 {%0,%1,%2,%3},[%4];" \
                 : "=r"(r0), "=r"(r1), "=r"(r2), "=r"(r3) : "r"(addr))
#define LDSM_X4_T(r0, r1, r2, r3, addr) \
    asm volatile("ldmatrix.sync.aligned.m8n8.x4.trans.shared.b16 {%0,%1,%2,%3},[%4];" \
                 : "=r"(r0), "=r"(r1), "=r"(r2), "=r"(r3) : "r"(addr))

// bf16 mma (attention)
#define MMA16816(d, a0, a1, a2, a3, b0, b1) \
    asm volatile("mma.sync.aligned.m16n8k16.row.col.f32.bf16.bf16.f32 " \
                 "{%0,%1,%2,%3},{%4,%5,%6,%7},{%8,%9},{%0,%1,%2,%3};" \
                 : "+f"((d)[0]), "+f"((d)[1]), "+f"((d)[2]), "+f"((d)[3]) \
                 : "r"(a0), "r"(a1), "r"(a2), "r"(a3), "r"(b0), "r"(b1))
// fp16 mma (linear layers)
#define MMA16816H(d, a0, a1, a2, a3, b0, b1) \
    asm volatile("mma.sync.aligned.m16n8k16.row.col.f32.f16.f16.f32 " \
                 "{%0,%1,%2,%3},{%4,%5,%6,%7},{%8,%9},{%0,%1,%2,%3};" \
                 : "+f"((d)[0]), "+f"((d)[1]), "+f"((d)[2]), "+f"((d)[3]) \
                 : "r"(a0), "r"(a1), "r"(a2), "r"(a3), "r"(b0), "r"(b1))

__device__ __forceinline__ void split_bf16(float x, __nv_bfloat16& h, __nv_bfloat16& l) {
    h = __float2bfloat16(x);
    l = __float2bfloat16(x - __bfloat162float(h));
}
__device__ __forceinline__ uint32_t packbf(float a, float b) {
    __nv_bfloat162 t = __floats2bfloat162_rn(a, b);
    return *(uint32_t*)&t;
}
__device__ __forceinline__ void pack_split(float v0, float v1, uint32_t& hw, uint32_t& lw) {
    __nv_bfloat16 h0, l0, h1, l1;
    split_bf16(v0, h0, l0); split_bf16(v1, h1, l1);
    hw = packbf(__bfloat162float(h0), __bfloat162float(h1));
    lw = packbf(__bfloat162float(l0), __bfloat162float(l1));
}
// fp16 split-2 pack: hi word + residual-lo word
__device__ __forceinline__ void pack_splith(float v0, float v1, uint32_t& hw, uint32_t& lw) {
    __half h0 = __float2half_rn(v0);
    __half h1 = __float2half_rn(v1);
    __half l0 = __float2half_rn(v0 - __half2float(h0));
    __half l1 = __float2half_rn(v1 - __half2float(h1));
    __half2 H = __halves2half2(h0, h1);
    __half2 L = __halves2half2(l0, l1);
    hw = *(uint32_t*)&H;
    lw = *(uint32_t*)&L;
}

// ===========================================================================
__device__ __forceinline__ float blockReduceSum256(float v, float* red) {
    int lane = threadIdx.x & 31, w = threadIdx.x >> 5;
#pragma unroll
    for (int o = 16; o; o >>= 1) v += __shfl_xor_sync(0xffffffffu, v, o);
    __syncthreads();
    if (lane == 0) red[w] = v;
    __syncthreads();
    float s = 0.f;
#pragma unroll
    for (int i = 0; i < 8; i++) s += red[i];
    return s;
}

// ---- rope table ----
__global__ void rope_tbl_kernel(float2* tbl) {
    int idx = blockIdx.x * 256 + threadIdx.x;
    int a = idx >> 4, i = idx & 15;
    float freq = exp2f(-(float)i * 0.8304820237218406f);
    float s, c;
    sincosf((float)a * freq, &s, &c);
    tbl[idx] = make_float2(c, s);
}

// ---- all weight norms -> fp16 (hi used; lo stored for layout symmetry) ----
__global__ void wnorm_all(const float* __restrict__ pv, const float* __restrict__ pg,
                          const float* __restrict__ fv, const float* __restrict__ fg,
                          const float* __restrict__ w1v, const float* __restrict__ w1g,
                          const float* __restrict__ w2v, const float* __restrict__ w2g,
                          __half* __restrict__ Wqkv, __half* __restrict__ Wo,
                          __half* __restrict__ W1, __half* __restrict__ W2) {
    __shared__ float red[8];
    int b = blockIdx.x;
    const float *v, *g; __half* W; int row;
    if (b < 768)       { v = pv;  g = pg;  W = Wqkv; row = b; }
    else if (b < 1024) { v = fv;  g = fg;  W = Wo;   row = b - 768; }
    else if (b < 1280) { v = w1v; g = w1g; W = W1;   row = b - 1024; }
    else               { v = w2v; g = w2g; W = W2;   row = b - 1280; }
    size_t base = (size_t)row * 256;
    float x = v[base + threadIdx.x];
    float ss = blockReduceSum256(x * x, red);
    float w = x * g[row] * rsqrtf(ss);
    __half h = __float2half_rn(w);
    size_t ob = (size_t)row * 512 + threadIdx.x;
    W[ob] = h;
    W[ob + 256] = __float2half_rn(w - __half2float(h));
}

// ---- layernorm, warp-per-token -> packed fp16 hi/lo ----
__global__ __launch_bounds__(256) void ln_kernel(
    const float* __restrict__ x, const float* __restrict__ g,
    const float* __restrict__ b, __half* __restrict__ y) {
    int wid = threadIdx.x >> 5, lane = threadIdx.x & 31;
    int t = blockIdx.x * 8 + wid;
    const float4* xr = (const float4*)(x + (size_t)t * 256);
    float4 v0 = xr[lane];
    float4 v1 = xr[lane + 32];
    float s = v0.x + v0.y + v0.z + v0.w + v1.x + v1.y + v1.z + v1.w;
#pragma unroll
    for (int o = 16; o; o >>= 1) s += __shfl_xor_sync(0xffffffffu, s, o);
    float mean = s * (1.f / 256.f);
    float d0 = v0.x - mean, d1 = v0.y - mean, d2 = v0.z - mean, d3 = v0.w - mean;
    float d4 = v1.x - mean, d5 = v1.y - mean, d6 = v1.z - mean, d7 = v1.w - mean;
    float vv = d0*d0 + d1*d1 + d2*d2 + d3*d3 + d4*d4 + d5*d5 + d6*d6 + d7*d7;
#pragma unroll
    for (int o = 16; o; o >>= 1) vv += __shfl_xor_sync(0xffffffffu, vv, o);
    float inv = rsqrtf(vv * (1.f / 256.f) + 1e-5f);
    float4 g0 = *(const float4*)(g + lane * 4);
    float4 g1 = *(const float4*)(g + 128 + lane * 4);
    float4 b0 = *(const float4*)(b + lane * 4);
    float4 b1 = *(const float4*)(b + 128 + lane * 4);
    float o0 = d0 * inv * g0.x + b0.x, o1 = d1 * inv * g0.y + b0.y;
    float o2 = d2 * inv * g0.z + b0.z, o3 = d3 * inv * g0.w + b0.w;
    float o4 = d4 * inv * g1.x + b1.x, o5 = d5 * inv * g1.y + b1.y;
    float o6 = d6 * inv * g1.z + b1.z, o7 = d7 * inv * g1.w + b1.w;
    uint32_t hw0, lw0, hw1, lw1;
    __half* yt = y + (size_t)t * 512;
    pack_splith(o0, o1, hw0, lw0); pack_splith(o2, o3, hw1, lw1);
    *(uint2*)(yt + lane * 4) = make_uint2(hw0, hw1);
    *(uint2*)(yt + 256 + lane * 4) = make_uint2(lw0, lw1);
    pack_splith(o4, o5, hw0, lw0); pack_splith(o6, o7, hw1, lw1);
    *(uint2*)(yt + 128 + lane * 4) = make_uint2(hw0, hw1);
    *(uint2*)(yt + 256 + 128 + lane * 4) = make_uint2(lw0, lw1);
}

// ===========================================================================
// fp16 GEMM: C = A@B^T, A split-2 (hi cols 0-255, lo 256-511), B hi-only.
// 8 K-chunks. 8 warps, 2(M)x4(N), tile 64x32, 3-stage ring.
// mode: 2 bias+residual fp32, 3 qkv: bias+rope -> split bf16 Q/K/V
// ===========================================================================
#define ROWP 72
#define STG_BYTES (2 * 128 * ROWP * 2)   // 36864
#define GEMM_SMEM (3 * STG_BYTES)
#define SCQE 0.2550348637156874f         // log2(e)/sqrt(32)

__global__ __launch_bounds__(256) void gemm_mma(
    const __half* __restrict__ Ap, const __half* __restrict__ Wp,
    const float* __restrict__ bias, const float* __restrict__ res,
    float* __restrict__ Cf,
    const float2* __restrict__ rtbl,
    __nv_bfloat16* __restrict__ Oq, __nv_bfloat16* __restrict__ Ok,
    __nv_bfloat16* __restrict__ Ov,
    int N, int mode)
{
    extern __shared__ char dsm[];
    int tid = threadIdx.x, wid = tid >> 5, lane = tid & 31;
    int bm = blockIdx.y * 128, bn = blockIdx.x * 128;
    int wm = (wid & 1) * 64, wn = (wid >> 1) * 32;

    uint32_t sbase = smem_u32(dsm);
    int ldr = tid >> 3;
    int ldc = (tid & 7) * 8;

    float acc[4][4][4];
#pragma unroll
    for (int mi = 0; mi < 4; mi++)
#pragma unroll
        for (int ni = 0; ni < 4; ni++)
#pragma unroll
            for (int e = 0; e < 4; e++) acc[mi][ni][e] = 0.f;

    auto issue_loads = [&](int c) {
        int seg = c >> 2;
        int kg = (c & 3) * 64;
        int aoff = seg ? 256 + kg : kg;
        int boff = kg;                   // B: hi only
        uint32_t st = sbase + (c % 3) * STG_BYTES;
#pragma unroll
        for (int i = 0; i < 4; i++) {
            int r = ldr + i * 32;
            CP_ASYNC16(st + r * 144 + ldc * 2,
                       Ap + (size_t)(bm + r) * 512 + aoff + ldc);
        }
        uint32_t stB = st + 128 * 144;
#pragma unroll
        for (int i = 0; i < 4; i++) {
            int r = ldr + i * 32;
            CP_ASYNC16(stB + r * 144 + ldc * 2,
                       Wp + (size_t)(bn + r) * 512 + boff + ldc);
        }
        CP_COMMIT();
    };

    issue_loads(0);
    issue_loads(1);
    CP_WAIT(1);
    __syncthreads();

    for (int c = 0; c < 8; c++) {
        uint32_t stA = sbase + (c % 3) * STG_BYTES;
        uint32_t stB = stA + 128 * 144;
#pragma unroll
        for (int kk = 0; kk < 4; kk++) {
            uint32_t a[4][4], b[2][4];
#pragma unroll
            for (int mi = 0; mi < 4; mi++) {
                uint32_t ad = stA + (wm + mi * 16 + (lane & 15)) * 144
                            + (kk * 16 + (lane >> 4) * 8) * 2;
                LDSM_X4(a[mi][0], a[mi][1], a[mi][2], a[mi][3], ad);
            }
#pragma unroll
            for (int nb = 0; nb < 2; nb++) {
                int nrow = wn + nb * 16 + ((lane >> 4) << 3) + (lane & 7);
                int koff = ((lane >> 3) & 1) * 8;
                uint32_t bd = stB + nrow * 144 + (kk * 16 + koff) * 2;
                LDSM_X4(b[nb][0], b[nb][1], b[nb][2], b[nb][3], bd);
            }
#pragma unroll
            for (int mi = 0; mi < 4; mi++) {
#pragma unroll
                for (int nb = 0; nb < 2; nb++) {
                    MMA16816H(acc[mi][nb * 2 + 0], a[mi][0], a[mi][1], a[mi][2], a[mi][3],
                              b[nb][0], b[nb][1]);
                    MMA16816H(acc[mi][nb * 2 + 1], a[mi][0], a[mi][1], a[mi][2], a[mi][3],
                              b[nb][2], b[nb][3]);
                }
            }
        }
        if (c + 2 < 8) { issue_loads(c + 2); CP_WAIT(1); __syncthreads(); }
        else if (c + 1 < 8) { CP_WAIT(0); __syncthreads(); }
    }

    int cg = (lane & 3) * 2;
    int rg = lane >> 2;
#pragma unroll
    for (int ni = 0; ni < 4; ni++) {
        int c0 = bn + wn + ni * 8 + cg;
        float2 b2 = *(const float2*)(bias + c0);
#pragma unroll
        for (int mi = 0; mi < 4; mi++) {
            int r0 = bm + wm + mi * 16 + rg;
#pragma unroll
            for (int h = 0; h < 2; h++) {
                int r = r0 + h * 8;
                float v0 = acc[mi][ni][h * 2 + 0] + b2.x;
                float v1 = acc[mi][ni][h * 2 + 1] + b2.y;
                if (mode == 2) {
                    float2 rr = *(const float2*)(res + (size_t)r * N + c0);
                    *(float2*)(Cf + (size_t)r * N + c0) =
                        make_float2(v0 + rr.x, v1 + rr.y);
                } else {
                    int hh = c0 / 96;
                    int rem = c0 - hh * 96;
                    int type = rem >> 5;        // 0=q 1=k 2=v
                    int i2 = rem & 31;
                    int a = r & 511;
                    int bh = ((r >> 9) << 3) + hh;
                    size_t ob = ((size_t)bh * 512 + a) * 64 + i2;
                    uint32_t hw, lw;
                    if (type == 2) {
                        pack_split(v0, v1, hw, lw);
                        *(uint32_t*)(Ov + ob) = hw;
                        *(uint32_t*)(Ov + ob + 32) = lw;
                    } else {
                        float2 cs = rtbl[a * 16 + (i2 >> 1)];
                        float q0 = v0 * cs.x - v1 * cs.y;
                        float q1 = v1 * cs.x + v0 * cs.y;
                        if (type == 0) { q0 *= SCQE; q1 *= SCQE; }
                        pack_split(q0, q1, hw, lw);
                        __nv_bfloat16* O = (type == 0) ? Oq : Ok;
                        *(uint32_t*)(O + ob) = hw;
                        *(uint32_t*)(O + ob + 32) = lw;
                    }
                }
            }
        }
    }
}

// ===========================================================================
// Fused Wo + residual + LN2 (fp16 GEMM, 8 chunks)
// ===========================================================================
#define WOLN_STG ((128 + 256) * 144)
#define WOLN_SMEM (3 * WOLN_STG)

__global__ __launch_bounds__(512, 1) void gemm_wo_ln(
    const __half* __restrict__ Ap, const __half* __restrict__ Wp,
    const float* __restrict__ bias, const float* __restrict__ res,
    float* __restrict__ out,
    const float* __restrict__ lng, const float* __restrict__ lnb,
    __half* __restrict__ zln)
{
    extern __shared__ char dsm[];
    uint32_t sbase = smem_u32(dsm);
    float* mid = (float*)dsm;
    int tid = threadIdx.x, wid = tid >> 5, lane = tid & 31;
    int bm = blockIdx.x * 128;
    int wm = (wid & 1) * 64, wn = (wid >> 1) * 32;

    int ldr = tid >> 3;
    int ldc = (tid & 7) * 8;
    int lg8 = ((lane >> 4) << 3) + (lane & 7);
    int koff = ((lane >> 3) & 1) * 8;
    int cg = (lane & 3) * 2;
    int rg = lane >> 2;

    float acc[4][4][4];
#pragma unroll
    for (int mi = 0; mi < 4; mi++)
#pragma unroll
        for (int ni = 0; ni < 4; ni++)
#pragma unroll
            for (int e = 0; e < 4; e++) acc[mi][ni][e] = 0.f;

    auto issue_loads = [&](int c) {
        int seg = c >> 2;
        int kg = (c & 3) * 64;
        int aoff = seg ? 256 + kg : kg;
        int boff = kg;
        uint32_t st = sbase + (c % 3) * WOLN_STG;
#pragma unroll
        for (int i = 0; i < 2; i++) {
            int r = ldr + i * 64;
            CP_ASYNC16(st + r * 144 + ldc * 2,
                       Ap + (size_t)(bm + r) * 512 + aoff + ldc);
        }
        uint32_t stB = st + 128 * 144;
#pragma unroll
        for (int i = 0; i < 4; i++) {
            int r = ldr + i * 64;
            CP_ASYNC16(stB + r * 144 + ldc * 2,
                       Wp + (size_t)r * 512 + boff + ldc);
        }
        CP_COMMIT();
    };

    issue_loads(0);
    issue_loads(1);
    CP_WAIT(1);
    __syncthreads();

    for (int c = 0; c < 8; c++) {
        uint32_t stA = sbase + (c % 3) * WOLN_STG;
        uint32_t stB = stA + 128 * 144;
#pragma unroll
        for (int kk = 0; kk < 4; kk++) {
            uint32_t a[4][4], b[2][4];
#pragma unroll
            for (int mi = 0; mi < 4; mi++) {
                uint32_t ad = stA + (wm + mi * 16 + (lane & 15)) * 144
                            + (kk * 16 + (lane >> 4) * 8) * 2;
                LDSM_X4(a[mi][0], a[mi][1], a[mi][2], a[mi][3], ad);
            }
#pragma unroll
            for (int nb = 0; nb < 2; nb++) {
                int nrow = wn + nb * 16 + lg8;
                uint32_t bd = stB + nrow * 144 + (kk * 16 + koff) * 2;
                LDSM_X4(b[nb][0], b[nb][1], b[nb][2], b[nb][3], bd);
            }
#pragma unroll
            for (int mi = 0; mi < 4; mi++) {
#pragma unroll
                for (int nb = 0; nb < 2; nb++) {
                    MMA16816H(acc[mi][nb * 2 + 0], a[mi][0], a[mi][1], a[mi][2], a[mi][3],
                              b[nb][0], b[nb][1]);
                    MMA16816H(acc[mi][nb * 2 + 1], a[mi][0], a[mi][1], a[mi][2], a[mi][3],
                              b[nb][2], b[nb][3]);
                }
            }
        }
        if (c + 2 < 8) { issue_loads(c + 2); CP_WAIT(1); __syncthreads(); }
        else if (c + 1 < 8) { CP_WAIT(0); __syncthreads(); }
    }
    __syncthreads();

#pragma unroll
    for (int ni = 0; ni < 4; ni++) {
        int c0 = wn + ni * 8 + cg;
        float2 bb = *(const float2*)(bias + c0);
#pragma unroll
        for (int mi = 0; mi < 4; mi++) {
#pragma unroll
            for (int h = 0; h < 2; h++) {
                int r = wm + mi * 16 + rg + h * 8;
                int gr = bm + r;
                float2 rr = *(const float2*)(res + (size_t)gr * 256 + c0);
                float v0 = acc[mi][ni][h * 2 + 0] + bb.x + rr.x;
                float v1 = acc[mi][ni][h * 2 + 1] + bb.y + rr.y;
                *(float2*)(out + (size_t)gr * 256 + c0) = make_float2(v0, v1);
                *(float2*)(mid + r * 264 + c0) = make_float2(v0, v1);
            }
        }
    }
    __syncthreads();

#pragma unroll
    for (int i = 0; i < 8; i++) {
        int r = wid * 8 + i;
        const float4* xr = (const float4*)(mid + r * 264);
        float4 v0 = xr[lane];
        float4 v1 = xr[lane + 32];
        float s = v0.x + v0.y + v0.z + v0.w + v1.x + v1.y + v1.z + v1.w;
#pragma unroll
        for (int o = 16; o; o >>= 1) s += __shfl_xor_sync(0xffffffffu, s, o);
        float mean = s * (1.f / 256.f);
        float d0 = v0.x - mean, d1 = v0.y - mean, d2 = v0.z - mean, d3 = v0.w - mean;
        float d4 = v1.x - mean, d5 = v1.y - mean, d6 = v1.z - mean, d7 = v1.w - mean;
        float vv = d0*d0 + d1*d1 + d2*d2 + d3*d3 + d4*d4 + d5*d5 + d6*d6 + d7*d7;
#pragma unroll
        for (int o = 16; o; o >>= 1) vv += __shfl_xor_sync(0xffffffffu, vv, o);
        float inv = rsqrtf(vv * (1.f / 256.f) + 1e-5f);
        float4 g0 = *(const float4*)(lng + lane * 4);
        float4 g1 = *(const float4*)(lng + 128 + lane * 4);
        float4 b0 = *(const float4*)(lnb + lane * 4);
        float4 b1 = *(const float4*)(lnb + 128 + lane * 4);
        float o0 = d0 * inv * g0.x + b0.x, o1 = d1 * inv * g0.y + b0.y;
        float o2 = d2 * inv * g0.z + b0.z, o3 = d3 * inv * g0.w + b0.w;
        float o4 = d4 * inv * g1.x + b1.x, o5 = d5 * inv * g1.y + b1.y;
        float o6 = d6 * inv * g1.z + b1.z, o7 = d7 * inv * g1.w + b1.w;
        uint32_t hw0, lw0, hw1, lw1;
        __half* yt = zln + (size_t)(bm + r) * 512;
        pack_splith(o0, o1, hw0, lw0); pack_splith(o2, o3, hw1, lw1);
        *(uint2*)(yt + lane * 4) = make_uint2(hw0, hw1);
        *(uint2*)(yt + 256 + lane * 4) = make_uint2(lw0, lw1);
        pack_splith(o4, o5, hw0, lw0); pack_splith(o6, o7, hw1, lw1);
        *(uint2*)(yt + 128 + lane * 4) = make_uint2(hw0, hw1);
        *(uint2*)(yt + 256 + 128 + lane * 4) = make_uint2(lw0, lw1);
    }
}

// ===========================================================================
// Fused MLP (fp16 GEMMs, 8 chunks each phase)
// ===========================================================================
#define MLP_STG 36864
#define MLP_P1STG (18432 + 36864)
#define MLP_H1 133120
#define MLP_SMEM (MLP_H1 + 2 * MLP_STG)

__global__ __launch_bounds__(512, 1) void gemm_mlp(
    const __half* __restrict__ Ap, const __half* __restrict__ W1p,
    const __half* __restrict__ W2p,
    const float* __restrict__ b1, const float* __restrict__ b2,
    float* __restrict__ out)
{
    extern __shared__ char dsm[];
    uint32_t sbase = smem_u32(dsm);
    uint32_t h1b = sbase;
    uint32_t w2b = sbase + MLP_H1;
    int tid = threadIdx.x, wid = tid >> 5, lane = tid & 31;
    int bm = blockIdx.x * 128;
    int wm = (wid & 1) * 64, wn = (wid >> 1) * 32;

    int ldr = tid >> 3;
    int ldc = (tid & 7) * 8;
    int lg8 = ((lane >> 4) << 3) + (lane & 7);
    int koff = ((lane >> 3) & 1) * 8;
    int cg = (lane & 3) * 2;
    int rg = lane >> 2;

    // ---------------- phase 1 ----------------
    {
        float acc[4][4][4];
#pragma unroll
        for (int mi = 0; mi < 4; mi++)
#pragma unroll
            for (int ni = 0; ni < 4; ni++)
#pragma unroll
                for (int e = 0; e < 4; e++) acc[mi][ni][e] = 0.f;

        auto issue1 = [&](int c) {
            int seg = c >> 2;
            int kg = (c & 3) * 64;
            int aoff = seg ? 256 + kg : kg;
            int boff = kg;
            uint32_t st = sbase + (c & 1) * MLP_P1STG;
#pragma unroll
            for (int i = 0; i < 2; i++) {
                int r = ldr + i * 64;
                CP_ASYNC16(st + r * 144 + ldc * 2,
                           Ap + (size_t)(bm + r) * 512 + aoff + ldc);
            }
            uint32_t stB = st + 128 * 144;
#pragma unroll
            for (int i = 0; i < 4; i++) {
                int r = ldr + i * 64;
                CP_ASYNC16(stB + r * 144 + ldc * 2,
                           W1p + (size_t)r * 512 + boff + ldc);
            }
            CP_COMMIT();
        };

        issue1(0);
        for (int c = 0; c < 8; c++) {
            if (c + 1 < 8) { issue1(c + 1); CP_WAIT(1); } else { CP_WAIT(0); }
            __syncthreads();
            uint32_t stA = sbase + (c & 1) * MLP_P1STG;
            uint32_t stB = stA + 128 * 144;
#pragma unroll
            for (int kk = 0; kk < 4; kk++) {
                uint32_t a[4][4], b[2][4];
#pragma unroll
                for (int mi = 0; mi < 4; mi++) {
                    uint32_t ad = stA + (wm + mi * 16 + (lane & 15)) * 144
                                + (kk * 16 + (lane >> 4) * 8) * 2;
                    LDSM_X4(a[mi][0], a[mi][1], a[mi][2], a[mi][3], ad);
                }
#pragma unroll
                for (int nb = 0; nb < 2; nb++) {
                    int nrow = wn + nb * 16 + lg8;
                    uint32_t bd = stB + nrow * 144 + (kk * 16 + koff) * 2;
                    LDSM_X4(b[nb][0], b[nb][1], b[nb][2], b[nb][3], bd);
                }
#pragma unroll
                for (int mi = 0; mi < 4; mi++) {
#pragma unroll
                    for (int nb = 0; nb < 2; nb++) {
                        MMA16816H(acc[mi][nb * 2 + 0], a[mi][0], a[mi][1], a[mi][2], a[mi][3],
                                  b[nb][0], b[nb][1]);
                        MMA16816H(acc[mi][nb * 2 + 1], a[mi][0], a[mi][1], a[mi][2], a[mi][3],
                                  b[nb][2], b[nb][3]);
                    }
                }
            }
            __syncthreads();
        }

        // prefetch W2 chunk 0 during gelu epilogue
        {
            uint32_t st = w2b;
#pragma unroll
            for (int i = 0; i < 4; i++) {
                int r = ldr + i * 64;
                CP_ASYNC16(st + r * 144 + ldc * 2,
                           W2p + (size_t)r * 512 + ldc);
            }
            CP_COMMIT();
        }

#pragma unroll
        for (int ni = 0; ni < 4; ni++) {
            int c0 = wn + ni * 8 + cg;
            float2 bb = *(const float2*)(b1 + c0);
#pragma unroll
            for (int mi = 0; mi < 4; mi++) {
#pragma unroll
                for (int h = 0; h < 2; h++) {
                    int r = wm + mi * 16 + rg + h * 8;
                    float v0 = acc[mi][ni][h * 2 + 0] + bb.x;
                    float v1 = acc[mi][ni][h * 2 + 1] + bb.y;
                    v0 = 0.5f * v0 * (1.f + erff(v0 * 0.7071067811865476f));
                    v1 = 0.5f * v1 * (1.f + erff(v1 * 0.7071067811865476f));
                    uint32_t hw, lw;
                    pack_splith(v0, v1, hw, lw);
                    *(uint32_t*)(dsm + r * 1040 + c0 * 2) = hw;
                    *(uint32_t*)(dsm + r * 1040 + (256 + c0) * 2) = lw;
                }
            }
        }
    }
    __syncthreads();

    // ---------------- phase 2 ----------------
    float acc[4][4][4];
#pragma unroll
    for (int mi = 0; mi < 4; mi++)
#pragma unroll
        for (int ni = 0; ni < 4; ni++)
#pragma unroll
            for (int e = 0; e < 4; e++) acc[mi][ni][e] = 0.f;

    auto issue2 = [&](int c) {
        int kg = (c & 3) * 64;
        int boff = kg;
        uint32_t st = w2b + (c & 1) * MLP_STG;
#pragma unroll
        for (int i = 0; i < 4; i++) {
            int r = ldr + i * 64;
            CP_ASYNC16(st + r * 144 + ldc * 2,
                       W2p + (size_t)r * 512 + boff + ldc);
        }
        CP_COMMIT();
    };

    for (int c = 0; c < 8; c++) {
        if (c + 1 < 8) { issue2(c + 1); CP_WAIT(1); } else { CP_WAIT(0); }
        __syncthreads();

        int seg = c >> 2;
        int kg = (c & 3) * 64;
        int aoff = seg ? 256 + kg : kg;
        uint32_t stB = w2b + (c & 1) * MLP_STG;
#pragma unroll
        for (int kk = 0; kk < 4; kk++) {
            uint32_t a[4][4], b[2][4];
#pragma unroll
            for (int mi = 0; mi < 4; mi++) {
                uint32_t ad = h1b + (wm + mi * 16 + (lane & 15)) * 1040
                            + (aoff + kk * 16 + (lane >> 4) * 8) * 2;
                LDSM_X4(a[mi][0], a[mi][1], a[mi][2], a[mi][3], ad);
            }
#pragma unroll
            for (int nb = 0; nb < 2; nb++) {
                int nrow = wn + nb * 16 + lg8;
                uint32_t bd = stB + nrow * 144 + (kk * 16 + koff) * 2;
                LDSM_X4(b[nb][0], b[nb][1], b[nb][2], b[nb][3], bd);
            }
#pragma unroll
            for (int mi = 0; mi < 4; mi++) {
#pragma unroll
                for (int nb = 0; nb < 2; nb++) {
                    MMA16816H(acc[mi][nb * 2 + 0], a[mi][0], a[mi][1], a[mi][2], a[mi][3],
                              b[nb][0], b[nb][1]);
                    MMA16816H(acc[mi][nb * 2 + 1], a[mi][0], a[mi][1], a[mi][2], a[mi][3],
                              b[nb][2], b[nb][3]);
                }
            }
        }
        __syncthreads();
    }

#pragma unroll
    for (int ni = 0; ni < 4; ni++) {
        int c0 = wn + ni * 8 + cg;
        float2 bb = *(const float2*)(b2 + c0);
#pragma unroll
        for (int mi = 0; mi < 4; mi++) {
#pragma unroll
            for (int h = 0; h < 2; h++) {
                int r = bm + wm + mi * 16 + rg + h * 8;
                float v0 = acc[mi][ni][h * 2 + 0] + bb.x;
                float v1 = acc[mi][ni][h * 2 + 1] + bb.y;
                float2 rr = *(const float2*)(out + (size_t)r * 256 + c0);
                *(float2*)(out + (size_t)r * 256 + c0) =
                    make_float2(v0 + rr.x, v1 + rr.y);
            }
        }
    }
}

// ---------------------------------------------------------------------------
// Attention v3 (bf16 split-3, R16-validated). Epilogue now emits fp16 hi/lo.
// ---------------------------------------------------------------------------
#define ATT3_SMEM (36864 + 73728 + 73728)

__global__ __launch_bounds__(256) void attn_mma(
    const __nv_bfloat16* __restrict__ Qs, const __nv_bfloat16* __restrict__ Ks,
    const __nv_bfloat16* __restrict__ Vs, __half* __restrict__ Op)
{
    extern __shared__ char sm[];
    uint32_t sQ = smem_u32(sm);
    uint32_t sK = sQ + 36864;
    uint32_t sV = sQ + 110592;
    int bh = blockIdx.x >> 1;
    int qh = (blockIdx.x & 1) * 256;
    int tid = threadIdx.x, wid = tid >> 5, lane = tid & 31;

    const __nv_bfloat16* qg = Qs + ((size_t)bh * 512 + qh) * 64;
    const __nv_bfloat16* kg = Ks + (size_t)bh * 512 * 64;
    const __nv_bfloat16* vg = Vs + (size_t)bh * 512 * 64;
    for (int idx = tid; idx < 4096; idx += 256) {
        int r = idx >> 3, c = idx & 7;
        CP_ASYNC16(sK + r * 144 + c * 16, kg + r * 64 + c * 8);
        CP_ASYNC16(sV + r * 144 + c * 16, vg + r * 64 + c * 8);
        if (idx < 2048)
            CP_ASYNC16(sQ + r * 144 + c * 16, qg + r * 64 + c * 8);
    }
    CP_COMMIT(); CP_WAIT(0);
    __syncthreads();

    int wm = wid * 32;
    uint32_t aQ[2][4][4];
#pragma unroll
    for (int mi = 0; mi < 2; mi++)
#pragma unroll
        for (int kq = 0; kq < 4; kq++) {
            uint32_t ad = sQ + (wm + mi * 16 + (lane & 15)) * 144
                        + kq * 32 + (lane >> 4) * 16;
            LDSM_X4(aQ[mi][kq][0], aQ[mi][kq][1], aQ[mi][kq][2], aQ[mi][kq][3], ad);
        }

    float acc[2][4][4];
    float lst[2][2];
#pragma unroll
    for (int mi = 0; mi < 2; mi++) {
        lst[mi][0] = 0.f; lst[mi][1] = 0.f;
#pragma unroll
        for (int jv = 0; jv < 4; jv++)
#pragma unroll
            for (int e = 0; e < 4; e++) acc[mi][jv][e] = 0.f;
    }

    int lg8 = ((lane >> 4) << 3) + (lane & 7);
    int lk8 = ((lane >> 3) & 1) * 16;
    int vrow = ((lane >> 3) & 1) * 8 + (lane & 7);
    int vcb = (lane >> 4) * 16;

    for (int kt = 0; kt < 16; kt++) {
        int kvb = kt * 32;

        uint32_t bK[4][4][2];
#pragma unroll
        for (int g16 = 0; g16 < 2; g16++)
#pragma unroll
            for (int kq = 0; kq < 4; kq++) {
                uint32_t ad = sK + (kvb + g16 * 16 + lg8) * 144 + kq * 32 + lk8;
                uint32_t r0, r1, r2, r3;
                LDSM_X4(r0, r1, r2, r3, ad);
                bK[g16 * 2][kq][0] = r0;     bK[g16 * 2][kq][1] = r1;
                bK[g16 * 2 + 1][kq][0] = r2; bK[g16 * 2 + 1][kq][1] = r3;
            }
        uint32_t bVh[4][2][2], bVl[4][2][2];
#pragma unroll
        for (int ks = 0; ks < 2; ks++) {
            uint32_t ad = sV + (kvb + ks * 16 + vrow) * 144 + vcb;
            uint32_t r0, r1, r2, r3;
            LDSM_X4_T(r0, r1, r2, r3, ad);
            bVh[0][ks][0] = r0; bVh[0][ks][1] = r1;
            bVh[1][ks][0] = r2; bVh[1][ks][1] = r3;
            LDSM_X4_T(r0, r1, r2, r3, ad + 32);
            bVh[2][ks][0] = r0; bVh[2][ks][1] = r1;
            bVh[3][ks][0] = r2; bVh[3][ks][1] = r3;
            LDSM_X4_T(r0, r1, r2, r3, ad + 64);
            bVl[0][ks][0] = r0; bVl[0][ks][1] = r1;
            bVl[1][ks][0] = r2; bVl[1][ks][1] = r3;
            LDSM_X4_T(r0, r1, r2, r3, ad + 96);
            bVl[2][ks][0] = r0; bVl[2][ks][1] = r1;
            bVl[3][ks][0] = r2; bVl[3][ks][1] = r3;
        }

#pragma unroll
        for (int mi = 0; mi < 2; mi++) {
            float s[4][4];
#pragma unroll
            for (int j = 0; j < 4; j++) {
#pragma unroll
                for (int e = 0; e < 4; e++) s[j][e] = 0.f;
                MMA16816(s[j], aQ[mi][0][0], aQ[mi][0][1], aQ[mi][0][2], aQ[mi][0][3],
                         bK[j][0][0], bK[j][0][1]);
                MMA16816(s[j], aQ[mi][1][0], aQ[mi][1][1], aQ[mi][1][2], aQ[mi][1][3],
                         bK[j][1][0], bK[j][1][1]);
                MMA16816(s[j], aQ[mi][0][0], aQ[mi][0][1], aQ[mi][0][2], aQ[mi][0][3],
                         bK[j][2][0], bK[j][2][1]);
                MMA16816(s[j], aQ[mi][1][0], aQ[mi][1][1], aQ[mi][1][2], aQ[mi][1][3],
                         bK[j][3][0], bK[j][3][1]);
                MMA16816(s[j], aQ[mi][2][0], aQ[mi][2][1], aQ[mi][2][2], aQ[mi][2][3],
                         bK[j][0][0], bK[j][0][1]);
                MMA16816(s[j], aQ[mi][3][0], aQ[mi][3][1], aQ[mi][3][2], aQ[mi][3][3],
                         bK[j][1][0], bK[j][1][1]);
            }
            float sm0 = 0.f, sm1 = 0.f;
#pragma unroll
            for (int j = 0; j < 4; j++) {
                s[j][0] = exp2f(s[j][0]); sm0 += s[j][0];
                s[j][1] = exp2f(s[j][1]); sm0 += s[j][1];
                s[j][2] = exp2f(s[j][2]); sm1 += s[j][2];
                s[j][3] = exp2f(s[j][3]); sm1 += s[j][3];
            }
            lst[mi][0] += sm0;
            lst[mi][1] += sm1;
            uint32_t aPh[2][4], aPl[2][4];
#pragma unroll
            for (int ks = 0; ks < 2; ks++) {
                int j0 = 2 * ks, j1 = 2 * ks + 1;
                aPh[ks][0] = packbf(s[j0][0], s[j0][1]);
                aPh[ks][1] = packbf(s[j0][2], s[j0][3]);
                aPh[ks][2] = packbf(s[j1][0], s[j1][1]);
                aPh[ks][3] = packbf(s[j1][2], s[j1][3]);
                __nv_bfloat162 h0 = *(__nv_bfloat162*)&aPh[ks][0];
                __nv_bfloat162 h1 = *(__nv_bfloat162*)&aPh[ks][1];
                __nv_bfloat162 h2 = *(__nv_bfloat162*)&aPh[ks][2];
                __nv_bfloat162 h3 = *(__nv_bfloat162*)&aPh[ks][3];
                aPl[ks][0] = packbf(s[j0][0] - __bfloat162float(h0.x),
                                    s[j0][1] - __bfloat162float(h0.y));
                aPl[ks][1] = packbf(s[j0][2] - __bfloat162float(h1.x),
                                    s[j0][3] - __bfloat162float(h1.y));
                aPl[ks][2] = packbf(s[j1][0] - __bfloat162float(h2.x),
                                    s[j1][1] - __bfloat162float(h2.y));
                aPl[ks][3] = packbf(s[j1][2] - __bfloat162float(h3.x),
                                    s[j1][3] - __bfloat162float(h3.y));
            }
#pragma unroll
            for (int jv = 0; jv < 4; jv++) {
                MMA16816(acc[mi][jv], aPh[0][0], aPh[0][1], aPh[0][2], aPh[0][3],
                         bVh[jv][0][0], bVh[jv][0][1]);
                MMA16816(acc[mi][jv], aPh[1][0], aPh[1][1], aPh[1][2], aPh[1][3],
                         bVh[jv][1][0], bVh[jv][1][1]);
                MMA16816(acc[mi][jv], aPh[0][0], aPh[0][1], aPh[0][2], aPh[0][3],
                         bVl[jv][0][0], bVl[jv][0][1]);
                MMA16816(acc[mi][jv], aPh[1][0], aPh[1][1], aPh[1][2], aPh[1][3],
                         bVl[jv][1][0], bVl[jv][1][1]);
                MMA16816(acc[mi][jv], aPl[0][0], aPl[0][1], aPl[0][2], aPl[0][3],
                         bVh[jv][0][0], bVh[jv][0][1]);
                MMA16816(acc[mi][jv], aPl[1][0], aPl[1][1], aPl[1][2], aPl[1][3],
                         bVh[jv][1][0], bVh[jv][1][1]);
            }
        }
    }

#pragma unroll
    for (int mi = 0; mi < 2; mi++) {
        lst[mi][0] += __shfl_xor_sync(0xffffffffu, lst[mi][0], 1);
        lst[mi][0] += __shfl_xor_sync(0xffffffffu, lst[mi][0], 2);
        lst[mi][1] += __shfl_xor_sync(0xffffffffu, lst[mi][1], 1);
        lst[mi][1] += __shfl_xor_sync(0xffffffffu, lst[mi][1], 2);
    }

    int tb = (bh >> 3) * 512 + qh;
    int cb = (bh & 7) * 32;
#pragma unroll
    for (int mi = 0; mi < 2; mi++) {
        float i0 = 1.f / lst[mi][0];
        float i1 = 1.f / lst[mi][1];
        int r0 = wm + mi * 16 + (lane >> 2);
#pragma unroll
        for (int jv = 0; jv < 4; jv++) {
            int col = cb + jv * 8 + 2 * (lane & 3);
            uint32_t hw, lw;
            pack_splith(acc[mi][jv][0] * i0, acc[mi][jv][1] * i0, hw, lw);
            size_t ob = (size_t)(tb + r0) * 512 + col;
            *(uint32_t*)(Op + ob) = hw;
            *(uint32_t*)(Op + ob + 256) = lw;
            pack_splith(acc[mi][jv][2] * i1, acc[mi][jv][3] * i1, hw, lw);
            ob = (size_t)(tb + r0 + 8) * 512 + col;
            *(uint32_t*)(Op + ob) = hw;
            *(uint32_t*)(Op + ob + 256) = lw;
        }
    }
}

// ---------------------------------------------------------------------------
extern "C" void kernel_launch(void* const* d_in, const int* in_sizes, int n_in,
                              void* d_out, int out_size) {
    const float* z      = (const float*)d_in[0];
    const float* ln1_g  = (const float*)d_in[1];
    const float* ln1_b  = (const float*)d_in[2];
    const float* proj_v = (const float*)d_in[3];
    const float* proj_g = (const float*)d_in[4];
    const float* proj_b = (const float*)d_in[5];
    const float* ff_v   = (const float*)d_in[6];
    const float* ff_g   = (const float*)d_in[7];
    const float* ff_b   = (const float*)d_in[8];
    const float* ln2_g  = (const float*)d_in[9];
    const float* ln2_b  = (const float*)d_in[10];
    const float* w1_v   = (const float*)d_in[11];
    const float* w1_g   = (const float*)d_in[12];
    const float* w1_b   = (const float*)d_in[13];
    const float* w2_v   = (const float*)d_in[14];
    const float* w2_g   = (const float*)d_in[15];
    const float* w2_b   = (const float*)d_in[16];
    float* out = (float*)d_out;

    void *pWqkv, *pWo, *pW1, *pW2, *pzln, *pqs, *pks, *pvs, *patt, *ptbl;
    cudaGetSymbolAddress(&pWqkv, g_Wqkv);
    cudaGetSymbolAddress(&pWo, g_Wo);
    cudaGetSymbolAddress(&pW1, g_W1);
    cudaGetSymbolAddress(&pW2, g_W2);
    cudaGetSymbolAddress(&pzln, g_zln);
    cudaGetSymbolAddress(&pqs, g_qs);
    cudaGetSymbolAddress(&pks, g_ks);
    cudaGetSymbolAddress(&pvs, g_vs);
    cudaGetSymbolAddress(&patt, g_att);
    cudaGetSymbolAddress(&ptbl, g_rtbl);

    cudaFuncSetAttribute(gemm_mma, cudaFuncAttributeMaxDynamicSharedMemorySize, GEMM_SMEM);
    cudaFuncSetAttribute(gemm_wo_ln, cudaFuncAttributeMaxDynamicSharedMemorySize, WOLN_SMEM);
    cudaFuncSetAttribute(gemm_mlp, cudaFuncAttributeMaxDynamicSharedMemorySize, MLP_SMEM);
    cudaFuncSetAttribute(attn_mma, cudaFuncAttributeMaxDynamicSharedMemorySize, ATT3_SMEM);

    // 0) rope table
    rope_tbl_kernel<<<32, 256>>>((float2*)ptbl);

    // 1) all weight norms -> fp16
    wnorm_all<<<1536, 256>>>(proj_v, proj_g, ff_v, ff_g, w1_v, w1_g, w2_v, w2_g,
                             (__half*)pWqkv, (__half*)pWo,
                             (__half*)pW1, (__half*)pW2);

    // 2) LN1 -> packed fp16
    ln_kernel<<<4096, 256>>>(z, ln1_g, ln1_b, (__half*)pzln);

    // 3) QKV projection (fp16 split-2) + fused bias+RoPE -> split bf16 Q/K/V
    gemm_mma<<<dim3(6, 256), 256, GEMM_SMEM>>>(
        (const __half*)pzln, (const __half*)pWqkv,
        proj_b, nullptr, nullptr,
        (const float2*)ptbl, (__nv_bfloat16*)pqs, (__nv_bfloat16*)pks,
        (__nv_bfloat16*)pvs, 768, 3);

    // 4) attention (bf16 split-3) -> packed fp16
    attn_mma<<<1024, 256, ATT3_SMEM>>>(
        (const __nv_bfloat16*)pqs, (const __nv_bfloat16*)pks,
        (const __nv_bfloat16*)pvs, (__half*)patt);

    // 5) fused Wo + residual z + LN2 -> out (fp32) and zln (packed fp16)
    gemm_wo_ln<<<256, 512, WOLN_SMEM>>>(
        (const __half*)patt, (const __half*)pWo,
        ff_b, z, out, ln2_g, ln2_b, (__half*)pzln);

    // 6) fused MLP: out += gelu(zln@W1^T+b1)@W2^T + b2
    gemm_mlp<<<256, 512, MLP_SMEM>>>(
        (const __half*)pzln, (const __half*)pW1,
        (const __half*)pW2, w1_b, w2_b, out);
}